// round 1
// baseline (speedup 1.0000x reference)
#include <cuda_runtime.h>
#include <math.h>

#define NN 10000
#define NE 160000
#define W_ 256
#define H_ 512
#define EW_ 128

// Scratch (static device memory — no allocation allowed)
__device__ float g_xx[NN * W_];   // LN(pre(x))
__device__ float g_qn[NN * H_];   // xx@Wq + bq
__device__ float g_kn[NN * H_];   // xx@Wk + bk
__device__ float g_vn[NN * H_];   // xx@Wv + bv (pre-gelu)
__device__ float g_m0[NN * H_];   // gelu(xx@Wm + bm)
__device__ float g_agg[NN * H_];  // scatter-add target

__device__ __forceinline__ float gelu_erf(float h) {
    return 0.5f * h * (1.0f + erff(h * 0.70710678118654752f));
}

__global__ void __launch_bounds__(256) k_zero() {
    int i = blockIdx.x * 256 + threadIdx.x;
    if (i < NN * H_) g_agg[i] = 0.f;
}

// xx = LayerNorm(x @ W_pre + b_pre), 8 nodes per block, 256 threads (1 col each)
__global__ void __launch_bounds__(256) k_pre(const float* __restrict__ x,
                                             const float* __restrict__ Wp,
                                             const float* __restrict__ bp) {
    const int NT = 8;
    __shared__ float xs[NT * W_];
    __shared__ float ys[NT * W_];
    __shared__ float s_mean[NT], s_rstd[NT];
    int tid = threadIdx.x;
    int n0 = blockIdx.x * NT;
    for (int idx = tid; idx < NT * W_; idx += 256) xs[idx] = x[n0 * W_ + idx];
    __syncthreads();
    float acc[NT];
#pragma unroll
    for (int i = 0; i < NT; i++) acc[i] = 0.f;
    int j = tid;
    for (int k = 0; k < W_; k++) {
        float w = Wp[k * W_ + j];
#pragma unroll
        for (int i = 0; i < NT; i++) acc[i] += xs[i * W_ + k] * w;
    }
    float bj = bp[j];
#pragma unroll
    for (int i = 0; i < NT; i++) ys[i * W_ + j] = acc[i] + bj;
    __syncthreads();
    int wid = tid >> 5, lane = tid & 31;  // 8 warps == NT nodes
    {
        float s = 0.f;
#pragma unroll
        for (int m = 0; m < W_ / 32; m++) s += ys[wid * W_ + lane + 32 * m];
#pragma unroll
        for (int off = 16; off > 0; off >>= 1) s += __shfl_xor_sync(0xffffffffu, s, off);
        float mean = s * (1.0f / W_);
        float v = 0.f;
#pragma unroll
        for (int m = 0; m < W_ / 32; m++) {
            float d = ys[wid * W_ + lane + 32 * m] - mean;
            v += d * d;
        }
#pragma unroll
        for (int off = 16; off > 0; off >>= 1) v += __shfl_xor_sync(0xffffffffu, v, off);
        if (lane == 0) {
            s_mean[wid] = mean;
            s_rstd[wid] = rsqrtf(v * (1.0f / W_) + 1e-5f);
        }
    }
    __syncthreads();
#pragma unroll
    for (int i = 0; i < NT; i++)
        g_xx[(n0 + i) * W_ + j] = (ys[i * W_ + j] - s_mean[i]) * s_rstd[i];
}

// Node-level projections: qn, kn, vn (linear), m0 = gelu(linear).
// 16 nodes per block, 512 threads (1 output col each), 4 matrices fused.
__global__ void __launch_bounds__(512) k_proj(const float* __restrict__ Wq, const float* __restrict__ bq,
                                              const float* __restrict__ Wk, const float* __restrict__ bk,
                                              const float* __restrict__ Wv, const float* __restrict__ bv,
                                              const float* __restrict__ Wm, const float* __restrict__ bm) {
    const int NT = 16;
    __shared__ float xs[NT * W_];
    int tid = threadIdx.x;
    int n0 = blockIdx.x * NT;
    for (int idx = tid; idx < NT * W_; idx += 512) xs[idx] = g_xx[n0 * W_ + idx];
    __syncthreads();
    float aq[NT], ak[NT], av[NT], am[NT];
#pragma unroll
    for (int i = 0; i < NT; i++) { aq[i] = 0.f; ak[i] = 0.f; av[i] = 0.f; am[i] = 0.f; }
    int j = tid;
    for (int k = 0; k < W_; k++) {
        float wqv = Wq[k * H_ + j];
        float wkv = Wk[k * H_ + j];
        float wvv = Wv[k * H_ + j];
        float wmv = Wm[k * H_ + j];
#pragma unroll
        for (int i = 0; i < NT; i++) {
            float a = xs[i * W_ + k];
            aq[i] += a * wqv;
            ak[i] += a * wkv;
            av[i] += a * wvv;
            am[i] += a * wmv;
        }
    }
    float bqj = bq[j], bkj = bk[j], bvj = bv[j], bmj = bm[j];
#pragma unroll
    for (int i = 0; i < NT; i++) {
        int idx = (n0 + i) * H_ + j;
        g_qn[idx] = aq[i] + bqj;
        g_kn[idx] = ak[i] + bkj;
        g_vn[idx] = av[i] + bvj;
        g_m0[idx] = gelu_erf(am[i] + bmj);
    }
}

// Fused edge kernel: embedding mix -> ee@Wr{0,1,2} -> combine with gathered node
// projections -> per-head attention -> gelu(v)*att -> atomic scatter-add.
// 32 edges per block, 256 threads. Each warp owns 4 edges across a 128-col chunk
// (= exactly 2 heads), so attention reductions are warp-local shfl ops.
__global__ void __launch_bounds__(256) k_edge(const int* __restrict__ edge_index,
                                              const int* __restrict__ edge_attr,
                                              const float* __restrict__ edge_embed,
                                              const float* __restrict__ emb0,
                                              const float* __restrict__ emb1,
                                              const float* __restrict__ emb2,
                                              const float* __restrict__ emb3,
                                              const float* __restrict__ init0_e,
                                              const float* __restrict__ init0,
                                              const float* __restrict__ Wr0, const float* __restrict__ br0,
                                              const float* __restrict__ Wr1, const float* __restrict__ br1,
                                              const float* __restrict__ Wr2, const float* __restrict__ br2) {
    const int TE = 32;
    __shared__ float ee[TE * EW_];
    __shared__ int s_src[TE], s_dst[TE];
    __shared__ int s_attr[TE * 4];
    int tid = threadIdx.x;
    int e0 = blockIdx.x * TE;
    if (tid < TE) {
        s_src[tid] = edge_index[e0 + tid];
        s_dst[tid] = edge_index[NE + e0 + tid];
    }
    if (tid < TE * 4) s_attr[tid] = edge_attr[e0 * 4 + tid];

    // scalar constants (cheap per-thread recompute; cached loads)
    float ew0 = expf(init0_e[0]), ew1 = expf(init0_e[1]);
    float ew2 = expf(init0_e[2]), ew3 = expf(init0_e[3]);
    float rs = rsqrtf(ew0 + ew1 + ew2 + ew3);
    ew0 *= rs; ew1 *= rs; ew2 *= rs; ew3 *= rs;
    float s_e = expf(init0[2]);
    float s_v = expf(init0[3]);
    float c0 = init0[0] * 0.125f;  // 1/sqrt(HEAD_DIM)=1/8 folded in
    float c1 = init0[1];
    __syncthreads();

    // ee = 0.5*(weighted embedding sum + edge_embed)
    for (int idx = tid; idx < TE * EW_; idx += 256) {
        int e = idx >> 7;
        int c = idx & (EW_ - 1);
        int a0 = s_attr[e * 4 + 0], a1 = s_attr[e * 4 + 1];
        int a2 = s_attr[e * 4 + 2], a3 = s_attr[e * 4 + 3];
        float v = emb0[a0 * EW_ + c] * ew0 + emb1[a1 * EW_ + c] * ew1 +
                  emb2[a2 * EW_ + c] * ew2 + emb3[a3 * EW_ + c] * ew3;
        ee[idx] = 0.5f * (v + edge_embed[(e0 + e) * EW_ + c]);
    }
    __syncthreads();

    int lane = tid & 31;
    int eg = tid >> 5;       // warp id = edge group (4 edges)
    int cbase = lane * 4;    // 4 consecutive cols within 128-col chunk

#pragma unroll 1
    for (int chunk = 0; chunk < 4; chunk++) {
        float aq[16], ak[16], av[16];  // [edge j][col cc]
#pragma unroll
        for (int i = 0; i < 16; i++) { aq[i] = 0.f; ak[i] = 0.f; av[i] = 0.f; }
        int co = chunk * 128 + cbase;
        const float4* wq = (const float4*)(Wr0 + co);
        const float4* wk = (const float4*)(Wr1 + co);
        const float4* wv = (const float4*)(Wr2 + co);
        for (int k = 0; k < EW_; k++) {
            float4 q4 = wq[k * (H_ / 4)];
            float4 k4 = wk[k * (H_ / 4)];
            float4 v4 = wv[k * (H_ / 4)];
#pragma unroll
            for (int j = 0; j < 4; j++) {
                float a = ee[(eg * 4 + j) * EW_ + k];  // warp-uniform broadcast
                aq[j * 4 + 0] += a * q4.x; aq[j * 4 + 1] += a * q4.y;
                aq[j * 4 + 2] += a * q4.z; aq[j * 4 + 3] += a * q4.w;
                ak[j * 4 + 0] += a * k4.x; ak[j * 4 + 1] += a * k4.y;
                ak[j * 4 + 2] += a * k4.z; ak[j * 4 + 3] += a * k4.w;
                av[j * 4 + 0] += a * v4.x; av[j * 4 + 1] += a * v4.y;
                av[j * 4 + 2] += a * v4.z; av[j * 4 + 3] += a * v4.w;
            }
        }
        float4 bq4 = *(const float4*)(br0 + co);
        float4 bk4 = *(const float4*)(br1 + co);
        float4 bv4 = *(const float4*)(br2 + co);

        float p[4];
#pragma unroll
        for (int j = 0; j < 4; j++) {
            int e = eg * 4 + j;
            float4 qg = *(const float4*)(g_qn + s_dst[e] * H_ + co);
            float4 kg = *(const float4*)(g_kn + s_src[e] * H_ + co);
            float xq0 = qg.x + (aq[j * 4 + 0] + bq4.x) * s_e;
            float xq1 = qg.y + (aq[j * 4 + 1] + bq4.y) * s_e;
            float xq2 = qg.z + (aq[j * 4 + 2] + bq4.z) * s_e;
            float xq3 = qg.w + (aq[j * 4 + 3] + bq4.w) * s_e;
            float xk0 = kg.x + (ak[j * 4 + 0] + bk4.x) * s_e;
            float xk1 = kg.y + (ak[j * 4 + 1] + bk4.y) * s_e;
            float xk2 = kg.z + (ak[j * 4 + 2] + bk4.z) * s_e;
            float xk3 = kg.w + (ak[j * 4 + 3] + bk4.w) * s_e;
            p[j] = xq0 * xk0 + xq1 * xk1 + xq2 * xk2 + xq3 * xk3;
        }
        // per-head reduce: lanes 0-15 = head 2*chunk, lanes 16-31 = head 2*chunk+1
#pragma unroll
        for (int off = 8; off > 0; off >>= 1) {
#pragma unroll
            for (int j = 0; j < 4; j++) p[j] += __shfl_xor_sync(0xffffffffu, p[j], off);
        }
#pragma unroll
        for (int j = 0; j < 4; j++) {
            int e = eg * 4 + j;
            float att = expf(p[j] * c0 + c1);
            float4 vg = *(const float4*)(g_vn + s_src[e] * H_ + co);
            float xv0 = gelu_erf(vg.x + (av[j * 4 + 0] + bv4.x) * s_v);
            float xv1 = gelu_erf(vg.y + (av[j * 4 + 1] + bv4.y) * s_v);
            float xv2 = gelu_erf(vg.z + (av[j * 4 + 2] + bv4.z) * s_v);
            float xv3 = gelu_erf(vg.w + (av[j * 4 + 3] + bv4.w) * s_v);
            float* dp = g_agg + s_dst[e] * H_ + co;
            atomicAdd(dp + 0, xv0 * att);
            atomicAdd(dp + 1, xv1 * att);
            atomicAdd(dp + 2, xv2 * att);
            atomicAdd(dp + 3, xv3 * att);
        }
    }
}

// out = x + (m0 + agg) @ W_post + b_post
__global__ void __launch_bounds__(256) k_post(const float* __restrict__ x,
                                              const float* __restrict__ Wp,
                                              const float* __restrict__ bp,
                                              float* __restrict__ out) {
    const int NT = 16;
    __shared__ float hs[NT * H_];  // 32KB
    int tid = threadIdx.x;
    int n0 = blockIdx.x * NT;
    for (int idx = tid; idx < NT * H_; idx += 256)
        hs[idx] = g_m0[n0 * H_ + idx] + g_agg[n0 * H_ + idx];
    __syncthreads();
    float acc[NT];
#pragma unroll
    for (int i = 0; i < NT; i++) acc[i] = 0.f;
    int j = tid;
    for (int k = 0; k < H_; k++) {
        float w = Wp[k * W_ + j];
#pragma unroll
        for (int i = 0; i < NT; i++) acc[i] += hs[i * H_ + k] * w;
    }
    float bj = bp[j];
#pragma unroll
    for (int i = 0; i < NT; i++)
        out[(n0 + i) * W_ + j] = x[(n0 + i) * W_ + j] + acc[i] + bj;
}

extern "C" void kernel_launch(void* const* d_in, const int* in_sizes, int n_in,
                              void* d_out, int out_size) {
    const float* x          = (const float*)d_in[0];
    const int*   edge_index = (const int*)d_in[1];
    const int*   edge_attr  = (const int*)d_in[2];
    const float* edge_embed = (const float*)d_in[3];
    const float* emb0       = (const float*)d_in[4];
    const float* emb1       = (const float*)d_in[5];
    const float* emb2       = (const float*)d_in[6];
    const float* emb3       = (const float*)d_in[7];
    const float* init0_e    = (const float*)d_in[8];
    const float* init0      = (const float*)d_in[9];
    const float* W_pre      = (const float*)d_in[10];
    const float* b_pre      = (const float*)d_in[11];
    const float* W_msg0     = (const float*)d_in[12];
    const float* b_msg0     = (const float*)d_in[13];
    const float* W_q        = (const float*)d_in[14];
    const float* b_q        = (const float*)d_in[15];
    const float* W_k        = (const float*)d_in[16];
    const float* b_k        = (const float*)d_in[17];
    const float* W_v        = (const float*)d_in[18];
    const float* b_v        = (const float*)d_in[19];
    const float* W_r0       = (const float*)d_in[20];
    const float* b_r0       = (const float*)d_in[21];
    const float* W_r1       = (const float*)d_in[22];
    const float* b_r1       = (const float*)d_in[23];
    const float* W_r2       = (const float*)d_in[24];
    const float* b_r2       = (const float*)d_in[25];
    const float* W_post     = (const float*)d_in[26];
    const float* b_post     = (const float*)d_in[27];
    float* out = (float*)d_out;

    k_zero<<<(NN * H_ + 255) / 256, 256>>>();
    k_pre<<<NN / 8, 256>>>(x, W_pre, b_pre);
    k_proj<<<NN / 16, 512>>>(W_q, b_q, W_k, b_k, W_v, b_v, W_msg0, b_msg0);
    k_edge<<<NE / 32, 256>>>(edge_index, edge_attr, edge_embed,
                             emb0, emb1, emb2, emb3, init0_e, init0,
                             W_r0, b_r0, W_r1, b_r1, W_r2, b_r2);
    k_post<<<NN / 16, 256>>>(x, W_post, b_post, out);
}

// round 2
// speedup vs baseline: 1.0779x; 1.0779x over previous
#include <cuda_runtime.h>
#include <math.h>

#define NN 10000
#define NE 160000
#define W_ 256
#define H_ 512
#define EW_ 128

// Scratch (static device memory — no allocation allowed)
__device__ float g_xx[NN * W_];   // LN(pre(x))
__device__ float g_qn[NN * H_];   // xx@Wq + bq + br0*s_e
__device__ float g_kn[NN * H_];   // xx@Wk + bk + br1*s_e
__device__ float g_vn[NN * H_];   // xx@Wv + bv + br2*s_v (pre-gelu)
__device__ float g_m0[NN * H_];   // gelu(xx@Wm + bm)
__device__ float g_agg[NN * H_];  // scatter-add target
__device__ uint4 g_eef4[NE * 32];     // ee in tf32, A-fragment order (82MB)
__device__ uint2 g_wf2[3 * 64 * 16 * 32];  // Wr0..2 in tf32, B-fragment order

__device__ __forceinline__ float gelu_erf(float h) {
    return 0.5f * h * (1.0f + erff(h * 0.70710678118654752f));
}

__device__ __forceinline__ unsigned f2tf(float x) {
    unsigned u;
    asm("cvt.rna.tf32.f32 %0, %1;" : "=r"(u) : "f"(x));
    return u;
}

__device__ __forceinline__ void mma8(float* d, const uint4& a, const uint2& b) {
    asm volatile(
        "mma.sync.aligned.m16n8k8.row.col.f32.tf32.tf32.f32 "
        "{%0,%1,%2,%3},{%4,%5,%6,%7},{%8,%9},{%0,%1,%2,%3};"
        : "+f"(d[0]), "+f"(d[1]), "+f"(d[2]), "+f"(d[3])
        : "r"(a.x), "r"(a.y), "r"(a.z), "r"(a.w), "r"(b.x), "r"(b.y));
}

__device__ __forceinline__ void red2(float* p, float x, float y) {
    asm volatile("red.global.add.v2.f32 [%0], {%1,%2};" :: "l"(p), "f"(x), "f"(y) : "memory");
}

__global__ void __launch_bounds__(256) k_zero() {
    int i = blockIdx.x * 256 + threadIdx.x;
    if (i < NN * H_) g_agg[i] = 0.f;
}

// Weight fragment pre-pass: g_wf2[((m*64+nt)*16+kt)*32+lane] = {b0,b1} tf32
__global__ void __launch_bounds__(256) k_wf(const float* __restrict__ W0,
                                            const float* __restrict__ W1,
                                            const float* __restrict__ W2) {
    int idx = blockIdx.x * 256 + threadIdx.x;  // 0..98303
    int lane = idx & 31;
    int kt = (idx >> 5) & 15;
    int nt = (idx >> 9) & 63;
    int m = idx >> 15;
    const float* W = (m == 0) ? W0 : ((m == 1) ? W1 : W2);
    int tg = lane & 3, gid = lane >> 2;
    float b0 = W[(kt * 8 + tg) * H_ + nt * 8 + gid];
    float b1 = W[(kt * 8 + tg + 4) * H_ + nt * 8 + gid];
    unsigned* out = (unsigned*)g_wf2;
    out[idx * 2 + 0] = f2tf(b0);
    out[idx * 2 + 1] = f2tf(b1);
}

// ee pre-pass: embedding mix -> tf32 A-fragment order. 32 edges/block.
__global__ void __launch_bounds__(256) k_eef(const int* __restrict__ edge_attr,
                                             const float* __restrict__ edge_embed,
                                             const float* __restrict__ emb0,
                                             const float* __restrict__ emb1,
                                             const float* __restrict__ emb2,
                                             const float* __restrict__ emb3,
                                             const float* __restrict__ init0_e) {
    __shared__ float ee_s[32 * EW_];
    __shared__ int s_attr[128];
    int tid = threadIdx.x;
    int e0 = blockIdx.x * 32;
    if (tid < 128) s_attr[tid] = edge_attr[e0 * 4 + tid];
    float ew0 = expf(init0_e[0]), ew1 = expf(init0_e[1]);
    float ew2 = expf(init0_e[2]), ew3 = expf(init0_e[3]);
    float rs = rsqrtf(ew0 + ew1 + ew2 + ew3);
    ew0 *= rs; ew1 *= rs; ew2 *= rs; ew3 *= rs;
    __syncthreads();
    for (int idx = tid; idx < 32 * EW_; idx += 256) {
        int e = idx >> 7;
        int c = idx & (EW_ - 1);
        int a0 = s_attr[e * 4 + 0], a1 = s_attr[e * 4 + 1];
        int a2 = s_attr[e * 4 + 2], a3 = s_attr[e * 4 + 3];
        float v = emb0[a0 * EW_ + c] * ew0 + emb1[a1 * EW_ + c] * ew1 +
                  emb2[a2 * EW_ + c] * ew2 + emb3[a3 * EW_ + c] * ew3;
        ee_s[idx] = 0.5f * (v + edge_embed[(e0 + e) * EW_ + c]);
    }
    __syncthreads();
    unsigned* out = (unsigned*)g_eef4 + (size_t)blockIdx.x * 4096;
    for (int idx = tid; idx < 4096; idx += 256) {
        int fb = idx >> 7;       // frag block: local_et*16 + kt
        int w = idx & 127;
        int t = w >> 2;          // lane
        int i = w & 3;           // frag element
        int let = fb >> 4;
        int kt = fb & 15;
        int er = (t >> 2) + ((i & 1) << 3);        // row within 16-edge tile
        int col = kt * 8 + (t & 3) + ((i & 2) << 1);
        out[idx] = f2tf(ee_s[(let * 16 + er) * EW_ + col]);
    }
}

// xx = LayerNorm(x @ W_pre + b_pre), 8 nodes per block, 256 threads
__global__ void __launch_bounds__(256) k_pre(const float* __restrict__ x,
                                             const float* __restrict__ Wp,
                                             const float* __restrict__ bp) {
    const int NT = 8;
    __shared__ float xs[NT * W_];
    __shared__ float ys[NT * W_];
    __shared__ float s_mean[NT], s_rstd[NT];
    int tid = threadIdx.x;
    int n0 = blockIdx.x * NT;
    for (int idx = tid; idx < NT * W_; idx += 256) xs[idx] = x[n0 * W_ + idx];
    __syncthreads();
    float acc[NT];
#pragma unroll
    for (int i = 0; i < NT; i++) acc[i] = 0.f;
    int j = tid;
    for (int k = 0; k < W_; k++) {
        float w = Wp[k * W_ + j];
#pragma unroll
        for (int i = 0; i < NT; i++) acc[i] += xs[i * W_ + k] * w;
    }
    float bj = bp[j];
#pragma unroll
    for (int i = 0; i < NT; i++) ys[i * W_ + j] = acc[i] + bj;
    __syncthreads();
    int wid = tid >> 5, lane = tid & 31;
    {
        float s = 0.f;
#pragma unroll
        for (int m = 0; m < W_ / 32; m++) s += ys[wid * W_ + lane + 32 * m];
#pragma unroll
        for (int off = 16; off > 0; off >>= 1) s += __shfl_xor_sync(0xffffffffu, s, off);
        float mean = s * (1.0f / W_);
        float v = 0.f;
#pragma unroll
        for (int m = 0; m < W_ / 32; m++) {
            float d = ys[wid * W_ + lane + 32 * m] - mean;
            v += d * d;
        }
#pragma unroll
        for (int off = 16; off > 0; off >>= 1) v += __shfl_xor_sync(0xffffffffu, v, off);
        if (lane == 0) {
            s_mean[wid] = mean;
            s_rstd[wid] = rsqrtf(v * (1.0f / W_) + 1e-5f);
        }
    }
    __syncthreads();
#pragma unroll
    for (int i = 0; i < NT; i++)
        g_xx[(n0 + i) * W_ + j] = (ys[i * W_ + j] - s_mean[i]) * s_rstd[i];
}

// Node projections with edge-bias folding:
// qn = xx@Wq + bq + br0*s_e ; kn = ... + br1*s_e ; vn = ... + br2*s_v ; m0 = gelu(...)
__global__ void __launch_bounds__(512) k_proj(const float* __restrict__ Wq, const float* __restrict__ bq,
                                              const float* __restrict__ Wk, const float* __restrict__ bk,
                                              const float* __restrict__ Wv, const float* __restrict__ bv,
                                              const float* __restrict__ Wm, const float* __restrict__ bm,
                                              const float* __restrict__ br0,
                                              const float* __restrict__ br1,
                                              const float* __restrict__ br2,
                                              const float* __restrict__ init0) {
    const int NT = 16;
    __shared__ float xs[NT * W_];
    int tid = threadIdx.x;
    int n0 = blockIdx.x * NT;
    float s_e = expf(init0[2]);
    float s_v = expf(init0[3]);
    for (int idx = tid; idx < NT * W_; idx += 512) xs[idx] = g_xx[n0 * W_ + idx];
    __syncthreads();
    float aq[NT], ak[NT], av[NT], am[NT];
#pragma unroll
    for (int i = 0; i < NT; i++) { aq[i] = 0.f; ak[i] = 0.f; av[i] = 0.f; am[i] = 0.f; }
    int j = tid;
    for (int k = 0; k < W_; k++) {
        float wqv = Wq[k * H_ + j];
        float wkv = Wk[k * H_ + j];
        float wvv = Wv[k * H_ + j];
        float wmv = Wm[k * H_ + j];
#pragma unroll
        for (int i = 0; i < NT; i++) {
            float a = xs[i * W_ + k];
            aq[i] += a * wqv;
            ak[i] += a * wkv;
            av[i] += a * wvv;
            am[i] += a * wmv;
        }
    }
    float bqj = bq[j] + br0[j] * s_e;
    float bkj = bk[j] + br1[j] * s_e;
    float bvj = bv[j] + br2[j] * s_v;
    float bmj = bm[j];
#pragma unroll
    for (int i = 0; i < NT; i++) {
        int idx = (n0 + i) * H_ + j;
        g_qn[idx] = aq[i] + bqj;
        g_kn[idx] = ak[i] + bkj;
        g_vn[idx] = av[i] + bvj;
        g_m0[idx] = gelu_erf(am[i] + bmj);
    }
}

// Tensor-core edge kernel: 128 edges/block, 8 warps = 4 m-groups x 2 n-groups.
// Per chunk (= 1 head = 64 cols): tf32 mma for R_q,R_k,R_v, then attention +
// gelu + vector scatter-add.
__global__ void __launch_bounds__(256, 1) k_edge(const int* __restrict__ edge_index,
                                                 const float* __restrict__ init0) {
    __shared__ int s_src[128], s_dst[128];
    __shared__ float p_buf[2][128];
    int tid = threadIdx.x;
    int lane = tid & 31, wid = tid >> 5;
    int mg = wid & 3;        // m-group 0..3 (32 edges each)
    int ng = wid >> 2;       // n-group 0..1 (32 cols each)
    int gid = lane >> 2, tg = lane & 3;
    int e0 = blockIdx.x * 128;
    if (tid < 128) {
        s_src[tid] = edge_index[e0 + tid];
        s_dst[tid] = edge_index[NE + e0 + tid];
    }
    float s_e = expf(init0[2]);
    float s_v = expf(init0[3]);
    float c0 = init0[0] * 0.125f;
    float c1 = init0[1];
    __syncthreads();

    const uint4* A0 = g_eef4 + (size_t)(blockIdx.x * 8 + mg * 2) * 512 + lane;

#pragma unroll 1
    for (int chunk = 0; chunk < 8; chunk++) {
        float acc[3][2][4][4];  // [matrix q/k/v][mtile][ntile][c] = 96 regs
#pragma unroll
        for (int m = 0; m < 3; m++)
#pragma unroll
            for (int mt = 0; mt < 2; mt++)
#pragma unroll
                for (int nt = 0; nt < 4; nt++)
#pragma unroll
                    for (int c = 0; c < 4; c++) acc[m][mt][nt][c] = 0.f;

        int ntg0 = chunk * 8 + ng * 4;
#pragma unroll 4
        for (int kt = 0; kt < 16; kt++) {
            uint4 a0v = A0[kt * 32];
            uint4 a1v = A0[512 + kt * 32];
#pragma unroll
            for (int m = 0; m < 3; m++) {
#pragma unroll
                for (int nt = 0; nt < 4; nt++) {
                    uint2 b = g_wf2[((m * 64 + ntg0 + nt) * 16 + kt) * 32 + lane];
                    mma8(acc[m][0][nt], a0v, b);
                    mma8(acc[m][1][nt], a1v, b);
                }
            }
        }

        // attention partial dots (fp32 gathers + tf32 GEMM results)
        float p[2][2];
        p[0][0] = p[0][1] = p[1][0] = p[1][1] = 0.f;
#pragma unroll
        for (int mt = 0; mt < 2; mt++) {
            int el = mg * 32 + mt * 16 + gid;
            int d0 = s_dst[el], d1 = s_dst[el + 8];
            int s0 = s_src[el], s1 = s_src[el + 8];
#pragma unroll
            for (int nt = 0; nt < 4; nt++) {
                int colg = chunk * 64 + ng * 32 + nt * 8 + tg * 2;
                float2 q0 = *(const float2*)(g_qn + (size_t)d0 * H_ + colg);
                float2 k0 = *(const float2*)(g_kn + (size_t)s0 * H_ + colg);
                p[mt][0] += (q0.x + acc[0][mt][nt][0] * s_e) * (k0.x + acc[1][mt][nt][0] * s_e)
                          + (q0.y + acc[0][mt][nt][1] * s_e) * (k0.y + acc[1][mt][nt][1] * s_e);
                float2 q1 = *(const float2*)(g_qn + (size_t)d1 * H_ + colg);
                float2 k1 = *(const float2*)(g_kn + (size_t)s1 * H_ + colg);
                p[mt][1] += (q1.x + acc[0][mt][nt][2] * s_e) * (k1.x + acc[1][mt][nt][2] * s_e)
                          + (q1.y + acc[0][mt][nt][3] * s_e) * (k1.y + acc[1][mt][nt][3] * s_e);
            }
        }
        // quad reduce (cols within this n-group)
#pragma unroll
        for (int off = 1; off <= 2; off <<= 1) {
            p[0][0] += __shfl_xor_sync(0xffffffffu, p[0][0], off);
            p[0][1] += __shfl_xor_sync(0xffffffffu, p[0][1], off);
            p[1][0] += __shfl_xor_sync(0xffffffffu, p[1][0], off);
            p[1][1] += __shfl_xor_sync(0xffffffffu, p[1][1], off);
        }
        __syncthreads();  // previous chunk's readers done
        if (tg == 0) {
            p_buf[ng][mg * 32 + gid] = p[0][0];
            p_buf[ng][mg * 32 + gid + 8] = p[0][1];
            p_buf[ng][mg * 32 + 16 + gid] = p[1][0];
            p_buf[ng][mg * 32 + 24 + gid] = p[1][1];
        }
        __syncthreads();

        // V epilogue: gelu + att scale + vector scatter-add
#pragma unroll
        for (int mt = 0; mt < 2; mt++) {
            int el = mg * 32 + mt * 16 + gid;
            float att0 = expf((p_buf[0][el] + p_buf[1][el]) * c0 + c1);
            float att1 = expf((p_buf[0][el + 8] + p_buf[1][el + 8]) * c0 + c1);
            int d0 = s_dst[el], d1 = s_dst[el + 8];
            int s0 = s_src[el], s1 = s_src[el + 8];
#pragma unroll
            for (int nt = 0; nt < 4; nt++) {
                int colg = chunk * 64 + ng * 32 + nt * 8 + tg * 2;
                float2 v0 = *(const float2*)(g_vn + (size_t)s0 * H_ + colg);
                float xv0 = gelu_erf(v0.x + acc[2][mt][nt][0] * s_v) * att0;
                float xv1 = gelu_erf(v0.y + acc[2][mt][nt][1] * s_v) * att0;
                red2(g_agg + (size_t)d0 * H_ + colg, xv0, xv1);
                float2 v1 = *(const float2*)(g_vn + (size_t)s1 * H_ + colg);
                float xv2 = gelu_erf(v1.x + acc[2][mt][nt][2] * s_v) * att1;
                float xv3 = gelu_erf(v1.y + acc[2][mt][nt][3] * s_v) * att1;
                red2(g_agg + (size_t)d1 * H_ + colg, xv2, xv3);
            }
        }
    }
}

// out = x + (m0 + agg) @ W_post + b_post
__global__ void __launch_bounds__(256) k_post(const float* __restrict__ x,
                                              const float* __restrict__ Wp,
                                              const float* __restrict__ bp,
                                              float* __restrict__ out) {
    const int NT = 16;
    __shared__ float hs[NT * H_];
    int tid = threadIdx.x;
    int n0 = blockIdx.x * NT;
    for (int idx = tid; idx < NT * H_; idx += 256)
        hs[idx] = g_m0[n0 * H_ + idx] + g_agg[n0 * H_ + idx];
    __syncthreads();
    float acc[NT];
#pragma unroll
    for (int i = 0; i < NT; i++) acc[i] = 0.f;
    int j = tid;
    for (int k = 0; k < H_; k++) {
        float w = Wp[k * W_ + j];
#pragma unroll
        for (int i = 0; i < NT; i++) acc[i] += hs[i * H_ + k] * w;
    }
    float bj = bp[j];
#pragma unroll
    for (int i = 0; i < NT; i++)
        out[(n0 + i) * W_ + j] = x[(n0 + i) * W_ + j] + acc[i] + bj;
}

extern "C" void kernel_launch(void* const* d_in, const int* in_sizes, int n_in,
                              void* d_out, int out_size) {
    const float* x          = (const float*)d_in[0];
    const int*   edge_index = (const int*)d_in[1];
    const int*   edge_attr  = (const int*)d_in[2];
    const float* edge_embed = (const float*)d_in[3];
    const float* emb0       = (const float*)d_in[4];
    const float* emb1       = (const float*)d_in[5];
    const float* emb2       = (const float*)d_in[6];
    const float* emb3       = (const float*)d_in[7];
    const float* init0_e    = (const float*)d_in[8];
    const float* init0      = (const float*)d_in[9];
    const float* W_pre      = (const float*)d_in[10];
    const float* b_pre      = (const float*)d_in[11];
    const float* W_msg0     = (const float*)d_in[12];
    const float* b_msg0     = (const float*)d_in[13];
    const float* W_q        = (const float*)d_in[14];
    const float* b_q        = (const float*)d_in[15];
    const float* W_k        = (const float*)d_in[16];
    const float* b_k        = (const float*)d_in[17];
    const float* W_v        = (const float*)d_in[18];
    const float* b_v        = (const float*)d_in[19];
    const float* W_r0       = (const float*)d_in[20];
    const float* b_r0       = (const float*)d_in[21];
    const float* W_r1       = (const float*)d_in[22];
    const float* b_r1       = (const float*)d_in[23];
    const float* W_r2       = (const float*)d_in[24];
    const float* b_r2       = (const float*)d_in[25];
    const float* W_post     = (const float*)d_in[26];
    const float* b_post     = (const float*)d_in[27];
    float* out = (float*)d_out;

    k_zero<<<(NN * H_ + 255) / 256, 256>>>();
    k_wf<<<384, 256>>>(W_r0, W_r1, W_r2);
    k_pre<<<NN / 8, 256>>>(x, W_pre, b_pre);
    k_eef<<<NE / 32, 256>>>(edge_attr, edge_embed, emb0, emb1, emb2, emb3, init0_e);
    k_proj<<<NN / 16, 512>>>(W_q, b_q, W_k, b_k, W_v, b_v, W_msg0, b_msg0,
                             b_r0, b_r1, b_r2, init0);
    k_edge<<<NE / 128, 256>>>(edge_index, init0);
    k_post<<<NN / 16, 256>>>(x, W_post, b_post, out);
}

// round 3
// speedup vs baseline: 1.5307x; 1.4201x over previous
#include <cuda_runtime.h>
#include <math.h>

#define NN 10000
#define NE 160000
#define W_ 256
#define H_ 512
#define EW_ 128

// Scratch (static device memory — no allocation allowed)
__device__ float g_xx[NN * W_];   // LN(pre(x))
__device__ float g_qn[NN * H_];   // xx@Wq + bq + br0*s_e
__device__ float g_kn[NN * H_];   // xx@Wk + bk + br1*s_e
__device__ float g_vn[NN * H_];   // xx@Wv + bv + br2*s_v (pre-gelu)
__device__ float g_m0[NN * H_];   // gelu(xx@Wm + bm)
__device__ float g_agg[NN * H_];  // scatter-add target
__device__ uint4 g_eef4[NE * 32];          // ee tf32, A-fragment order
__device__ uint2 g_wf2[3 * 64 * 16 * 32];  // Wr0..2 tf32, B-fragment order

__device__ __forceinline__ float gelu_erf(float h) {
    return 0.5f * h * (1.0f + erff(h * 0.70710678118654752f));
}

__device__ __forceinline__ unsigned f2tf(float x) {
    unsigned u;
    asm("cvt.rna.tf32.f32 %0, %1;" : "=r"(u) : "f"(x));
    return u;
}

__device__ __forceinline__ void mma8(float* d, const uint4& a, const uint2& b) {
    asm volatile(
        "mma.sync.aligned.m16n8k8.row.col.f32.tf32.tf32.f32 "
        "{%0,%1,%2,%3},{%4,%5,%6,%7},{%8,%9},{%0,%1,%2,%3};"
        : "+f"(d[0]), "+f"(d[1]), "+f"(d[2]), "+f"(d[3])
        : "r"(a.x), "r"(a.y), "r"(a.z), "r"(a.w), "r"(b.x), "r"(b.y));
}

__device__ __forceinline__ void red2(float* p, float x, float y) {
    asm volatile("red.global.add.v2.f32 [%0], {%1,%2};" :: "l"(p), "f"(x), "f"(y) : "memory");
}

__device__ __forceinline__ void cpa16(void* smem, const void* g) {
    unsigned s = (unsigned)__cvta_generic_to_shared(smem);
    asm volatile("cp.async.cg.shared.global [%0], [%1], 16;" :: "r"(s), "l"(g));
}
#define CP_COMMIT() asm volatile("cp.async.commit_group;" ::: "memory")
#define CP_WAIT1()  asm volatile("cp.async.wait_group 1;" ::: "memory")

__global__ void __launch_bounds__(256) k_zero() {
    int i = blockIdx.x * 256 + threadIdx.x;
    if (i < NN * H_) g_agg[i] = 0.f;
}

// Weight fragment pre-pass: g_wf2[((m*64+nt)*16+kt)*32+lane] = {b0,b1} tf32
__global__ void __launch_bounds__(256) k_wf(const float* __restrict__ W0,
                                            const float* __restrict__ W1,
                                            const float* __restrict__ W2) {
    int idx = blockIdx.x * 256 + threadIdx.x;  // 0..98303
    int lane = idx & 31;
    int kt = (idx >> 5) & 15;
    int nt = (idx >> 9) & 63;
    int m = idx >> 15;
    const float* W = (m == 0) ? W0 : ((m == 1) ? W1 : W2);
    int tg = lane & 3, gid = lane >> 2;
    float b0 = W[(kt * 8 + tg) * H_ + nt * 8 + gid];
    float b1 = W[(kt * 8 + tg + 4) * H_ + nt * 8 + gid];
    unsigned* out = (unsigned*)g_wf2;
    out[idx * 2 + 0] = f2tf(b0);
    out[idx * 2 + 1] = f2tf(b1);
}

// ee pre-pass: embedding mix -> tf32 A-fragment order. 32 edges/block.
__global__ void __launch_bounds__(256) k_eef(const int* __restrict__ edge_attr,
                                             const float* __restrict__ edge_embed,
                                             const float* __restrict__ emb0,
                                             const float* __restrict__ emb1,
                                             const float* __restrict__ emb2,
                                             const float* __restrict__ emb3,
                                             const float* __restrict__ init0_e) {
    __shared__ float ee_s[32 * EW_];
    __shared__ int s_attr[128];
    int tid = threadIdx.x;
    int e0 = blockIdx.x * 32;
    if (tid < 128) s_attr[tid] = edge_attr[e0 * 4 + tid];
    float ew0 = expf(init0_e[0]), ew1 = expf(init0_e[1]);
    float ew2 = expf(init0_e[2]), ew3 = expf(init0_e[3]);
    float rs = rsqrtf(ew0 + ew1 + ew2 + ew3);
    ew0 *= rs; ew1 *= rs; ew2 *= rs; ew3 *= rs;
    __syncthreads();
    for (int idx = tid; idx < 32 * EW_; idx += 256) {
        int e = idx >> 7;
        int c = idx & (EW_ - 1);
        int a0 = s_attr[e * 4 + 0], a1 = s_attr[e * 4 + 1];
        int a2 = s_attr[e * 4 + 2], a3 = s_attr[e * 4 + 3];
        float v = emb0[a0 * EW_ + c] * ew0 + emb1[a1 * EW_ + c] * ew1 +
                  emb2[a2 * EW_ + c] * ew2 + emb3[a3 * EW_ + c] * ew3;
        ee_s[idx] = 0.5f * (v + edge_embed[(e0 + e) * EW_ + c]);
    }
    __syncthreads();
    unsigned* out = (unsigned*)g_eef4 + (size_t)blockIdx.x * 4096;
    for (int idx = tid; idx < 4096; idx += 256) {
        int fb = idx >> 7;       // frag block: local_et*16 + kt
        int w = idx & 127;
        int t = w >> 2;          // lane
        int i = w & 3;           // frag element
        int let = fb >> 4;
        int kt = fb & 15;
        int er = (t >> 2) + ((i & 1) << 3);
        int col = kt * 8 + (t & 3) + ((i & 2) << 1);
        out[idx] = f2tf(ee_s[(let * 16 + er) * EW_ + col]);
    }
}

// xx = LayerNorm(x @ W_pre + b_pre), 8 nodes per block, 256 threads
__global__ void __launch_bounds__(256) k_pre(const float* __restrict__ x,
                                             const float* __restrict__ Wp,
                                             const float* __restrict__ bp) {
    const int NT = 8;
    __shared__ float xs[NT * W_];
    __shared__ float ys[NT * W_];
    __shared__ float s_mean[NT], s_rstd[NT];
    int tid = threadIdx.x;
    int n0 = blockIdx.x * NT;
    for (int idx = tid; idx < NT * W_; idx += 256) xs[idx] = x[n0 * W_ + idx];
    __syncthreads();
    float acc[NT];
#pragma unroll
    for (int i = 0; i < NT; i++) acc[i] = 0.f;
    int j = tid;
    for (int k = 0; k < W_; k++) {
        float w = Wp[k * W_ + j];
#pragma unroll
        for (int i = 0; i < NT; i++) acc[i] += xs[i * W_ + k] * w;
    }
    float bj = bp[j];
#pragma unroll
    for (int i = 0; i < NT; i++) ys[i * W_ + j] = acc[i] + bj;
    __syncthreads();
    int wid = tid >> 5, lane = tid & 31;
    {
        float s = 0.f;
#pragma unroll
        for (int m = 0; m < W_ / 32; m++) s += ys[wid * W_ + lane + 32 * m];
#pragma unroll
        for (int off = 16; off > 0; off >>= 1) s += __shfl_xor_sync(0xffffffffu, s, off);
        float mean = s * (1.0f / W_);
        float v = 0.f;
#pragma unroll
        for (int m = 0; m < W_ / 32; m++) {
            float d = ys[wid * W_ + lane + 32 * m] - mean;
            v += d * d;
        }
#pragma unroll
        for (int off = 16; off > 0; off >>= 1) v += __shfl_xor_sync(0xffffffffu, v, off);
        if (lane == 0) {
            s_mean[wid] = mean;
            s_rstd[wid] = rsqrtf(v * (1.0f / W_) + 1e-5f);
        }
    }
    __syncthreads();
#pragma unroll
    for (int i = 0; i < NT; i++)
        g_xx[(n0 + i) * W_ + j] = (ys[i * W_ + j] - s_mean[i]) * s_rstd[i];
}

// Node projections with edge-bias folding
__global__ void __launch_bounds__(512) k_proj(const float* __restrict__ Wq, const float* __restrict__ bq,
                                              const float* __restrict__ Wk, const float* __restrict__ bk,
                                              const float* __restrict__ Wv, const float* __restrict__ bv,
                                              const float* __restrict__ Wm, const float* __restrict__ bm,
                                              const float* __restrict__ br0,
                                              const float* __restrict__ br1,
                                              const float* __restrict__ br2,
                                              const float* __restrict__ init0) {
    const int NT = 16;
    __shared__ float xs[NT * W_];
    int tid = threadIdx.x;
    int n0 = blockIdx.x * NT;
    float s_e = expf(init0[2]);
    float s_v = expf(init0[3]);
    for (int idx = tid; idx < NT * W_; idx += 512) xs[idx] = g_xx[n0 * W_ + idx];
    __syncthreads();
    float aq[NT], ak[NT], av[NT], am[NT];
#pragma unroll
    for (int i = 0; i < NT; i++) { aq[i] = 0.f; ak[i] = 0.f; av[i] = 0.f; am[i] = 0.f; }
    int j = tid;
    for (int k = 0; k < W_; k++) {
        float wqv = Wq[k * H_ + j];
        float wkv = Wk[k * H_ + j];
        float wvv = Wv[k * H_ + j];
        float wmv = Wm[k * H_ + j];
#pragma unroll
        for (int i = 0; i < NT; i++) {
            float a = xs[i * W_ + k];
            aq[i] += a * wqv;
            ak[i] += a * wkv;
            av[i] += a * wvv;
            am[i] += a * wmv;
        }
    }
    float bqj = bq[j] + br0[j] * s_e;
    float bkj = bk[j] + br1[j] * s_e;
    float bvj = bv[j] + br2[j] * s_v;
    float bmj = bm[j];
#pragma unroll
    for (int i = 0; i < NT; i++) {
        int idx = (n0 + i) * H_ + j;
        g_qn[idx] = aq[i] + bqj;
        g_kn[idx] = ak[i] + bkj;
        g_vn[idx] = av[i] + bvj;
        g_m0[idx] = gelu_erf(am[i] + bmj);
    }
}

// ---------------------------------------------------------------------------
// Pipelined tensor-core edge kernel.
// 128 edges/block, 8 warps = 2 mg (64 edges) x 4 ng (16 cols).
// A (ee fragments, 64KB) loaded once into smem; B fragments streamed through a
// 2-stage 48KB smem ring with cp.async prefetch. 16 stages = 8 chunks x 2.
// ---------------------------------------------------------------------------
__device__ __forceinline__ void issue_b_stage(uint2* b_sm, int tid, int s) {
    int chunk = s >> 1, h = s & 1, buf = s & 1;
#pragma unroll
    for (int r = 0; r < 12; r++) {
        int i = r * 256 + tid;            // 0..3071 (16B units)
        int cid = i >> 7;                 // 0..23 = m*8 + nt8
        int off = i & 127;
        int m = cid >> 3, nt8 = cid & 7;
        cpa16(b_sm + buf * 6144 + cid * 256 + off * 2,
              g_wf2 + (((m * 64 + chunk * 8 + nt8) * 16 + h * 8) * 32) + off * 2);
    }
}

__global__ void __launch_bounds__(256, 1) k_edge(const int* __restrict__ edge_index,
                                                 const float* __restrict__ init0) {
    extern __shared__ char dsm[];
    uint4* a_sm = (uint4*)dsm;              // [8 mtile][16 kt][32 lane] = 64KB
    uint2* b_sm = (uint2*)(dsm + 65536);    // [2 buf][3 m][8 nt][8 ktl][32 lane] = 96KB
    __shared__ int s_src[128], s_dst[128];
    __shared__ float p_buf[4][128];

    int tid = threadIdx.x;
    int lane = tid & 31, wid = tid >> 5;
    int mg = wid >> 2;        // 0..1  (64 edges)
    int ng = wid & 3;         // 0..3  (16 cols)
    int gid = lane >> 2, tg = lane & 3;
    int e0 = blockIdx.x * 128;

    if (tid < 128) {
        s_src[tid] = edge_index[e0 + tid];
        s_dst[tid] = edge_index[NE + e0 + tid];
    }
    float s_e = expf(init0[2]);
    float s_v = expf(init0[3]);
    float c0 = init0[0] * 0.125f;
    float c1 = init0[1];

    // Prologue: A copy + B stage 0 (group 0), B stage 1 (group 1)
    {
        const uint4* srcA = g_eef4 + (size_t)blockIdx.x * 4096;
#pragma unroll
        for (int r = 0; r < 16; r++) {
            int i = r * 256 + tid;
            cpa16(a_sm + i, srcA + i);
        }
        issue_b_stage(b_sm, tid, 0);
        CP_COMMIT();
        issue_b_stage(b_sm, tid, 1);
        CP_COMMIT();
    }

    const uint4* aw = a_sm + mg * 4 * 512 + lane;
    const uint2* bw = b_sm + ng * 512 + lane;

#pragma unroll 1
    for (int chunk = 0; chunk < 8; chunk++) {
        float acc[3][4][2][4];
#pragma unroll
        for (int m = 0; m < 3; m++)
#pragma unroll
            for (int mt = 0; mt < 4; mt++)
#pragma unroll
                for (int nt = 0; nt < 2; nt++)
#pragma unroll
                    for (int c = 0; c < 4; c++) acc[m][mt][nt][c] = 0.f;

        // ---- stage even: kt 0..7, buf 0 ----
        CP_WAIT1();
        __syncthreads();
#pragma unroll 2
        for (int ktl = 0; ktl < 8; ktl++) {
            uint4 av4[4];
#pragma unroll
            for (int mt = 0; mt < 4; mt++) av4[mt] = aw[mt * 512 + ktl * 32];
            uint2 bv[3][2];
#pragma unroll
            for (int m = 0; m < 3; m++)
#pragma unroll
                for (int nt = 0; nt < 2; nt++)
                    bv[m][nt] = bw[m * 2048 + nt * 256 + ktl * 32];
#pragma unroll
            for (int m = 0; m < 3; m++)
#pragma unroll
                for (int mt = 0; mt < 4; mt++)
#pragma unroll
                    for (int nt = 0; nt < 2; nt++)
                        mma8(acc[m][mt][nt], av4[mt], bv[m][nt]);
        }
        __syncthreads();
        if (chunk * 2 + 2 < 16) issue_b_stage(b_sm, tid, chunk * 2 + 2);
        CP_COMMIT();

        // ---- stage odd: kt 8..15, buf 1 ----
        CP_WAIT1();
        __syncthreads();
#pragma unroll 2
        for (int ktl = 0; ktl < 8; ktl++) {
            uint4 av4[4];
#pragma unroll
            for (int mt = 0; mt < 4; mt++) av4[mt] = aw[mt * 512 + (8 + ktl) * 32];
            uint2 bv[3][2];
#pragma unroll
            for (int m = 0; m < 3; m++)
#pragma unroll
                for (int nt = 0; nt < 2; nt++)
                    bv[m][nt] = bw[6144 + m * 2048 + nt * 256 + ktl * 32];
#pragma unroll
            for (int m = 0; m < 3; m++)
#pragma unroll
                for (int mt = 0; mt < 4; mt++)
#pragma unroll
                    for (int nt = 0; nt < 2; nt++)
                        mma8(acc[m][mt][nt], av4[mt], bv[m][nt]);
        }

        // ---- attention partial dots ----
        float p[4][2];
#pragma unroll
        for (int mt = 0; mt < 4; mt++) { p[mt][0] = 0.f; p[mt][1] = 0.f; }
#pragma unroll
        for (int mt = 0; mt < 4; mt++) {
            int el = mg * 64 + mt * 16 + gid;
            int d0 = s_dst[el], d1 = s_dst[el + 8];
            int s0 = s_src[el], s1 = s_src[el + 8];
#pragma unroll
            for (int nt = 0; nt < 2; nt++) {
                int colg = chunk * 64 + ng * 16 + nt * 8 + tg * 2;
                float2 q0 = *(const float2*)(g_qn + (size_t)d0 * H_ + colg);
                float2 k0 = *(const float2*)(g_kn + (size_t)s0 * H_ + colg);
                p[mt][0] += (q0.x + acc[0][mt][nt][0] * s_e) * (k0.x + acc[1][mt][nt][0] * s_e)
                          + (q0.y + acc[0][mt][nt][1] * s_e) * (k0.y + acc[1][mt][nt][1] * s_e);
                float2 q1 = *(const float2*)(g_qn + (size_t)d1 * H_ + colg);
                float2 k1 = *(const float2*)(g_kn + (size_t)s1 * H_ + colg);
                p[mt][1] += (q1.x + acc[0][mt][nt][2] * s_e) * (k1.x + acc[1][mt][nt][2] * s_e)
                          + (q1.y + acc[0][mt][nt][3] * s_e) * (k1.y + acc[1][mt][nt][3] * s_e);
            }
        }
#pragma unroll
        for (int off = 1; off <= 2; off <<= 1)
#pragma unroll
            for (int mt = 0; mt < 4; mt++) {
                p[mt][0] += __shfl_xor_sync(0xffffffffu, p[mt][0], off);
                p[mt][1] += __shfl_xor_sync(0xffffffffu, p[mt][1], off);
            }
        __syncthreads();   // (also: all warps done reading b_sm buf1)
        if (tg == 0) {
#pragma unroll
            for (int mt = 0; mt < 4; mt++) {
                int el = mg * 64 + mt * 16 + gid;
                p_buf[ng][el] = p[mt][0];
                p_buf[ng][el + 8] = p[mt][1];
            }
        }
        __syncthreads();

        // prefetch next odd stage while epilogue runs
        if (chunk * 2 + 3 < 16) issue_b_stage(b_sm, tid, chunk * 2 + 3);
        CP_COMMIT();

        // ---- V epilogue: gelu + att scale + vector scatter-add ----
#pragma unroll
        for (int mt = 0; mt < 4; mt++) {
            int el = mg * 64 + mt * 16 + gid;
            float sum0 = p_buf[0][el] + p_buf[1][el] + p_buf[2][el] + p_buf[3][el];
            float sum1 = p_buf[0][el + 8] + p_buf[1][el + 8] + p_buf[2][el + 8] + p_buf[3][el + 8];
            float att0 = expf(sum0 * c0 + c1);
            float att1 = expf(sum1 * c0 + c1);
            int d0 = s_dst[el], d1 = s_dst[el + 8];
            int s0 = s_src[el], s1 = s_src[el + 8];
#pragma unroll
            for (int nt = 0; nt < 2; nt++) {
                int colg = chunk * 64 + ng * 16 + nt * 8 + tg * 2;
                float2 v0 = *(const float2*)(g_vn + (size_t)s0 * H_ + colg);
                float xv0 = gelu_erf(v0.x + acc[2][mt][nt][0] * s_v) * att0;
                float xv1 = gelu_erf(v0.y + acc[2][mt][nt][1] * s_v) * att0;
                red2(g_agg + (size_t)d0 * H_ + colg, xv0, xv1);
                float2 v1 = *(const float2*)(g_vn + (size_t)s1 * H_ + colg);
                float xv2 = gelu_erf(v1.x + acc[2][mt][nt][2] * s_v) * att1;
                float xv3 = gelu_erf(v1.y + acc[2][mt][nt][3] * s_v) * att1;
                red2(g_agg + (size_t)d1 * H_ + colg, xv2, xv3);
            }
        }
    }
}

// out = x + (m0 + agg) @ W_post + b_post
__global__ void __launch_bounds__(256) k_post(const float* __restrict__ x,
                                              const float* __restrict__ Wp,
                                              const float* __restrict__ bp,
                                              float* __restrict__ out) {
    const int NT = 16;
    __shared__ float hs[NT * H_];
    int tid = threadIdx.x;
    int n0 = blockIdx.x * NT;
    for (int idx = tid; idx < NT * H_; idx += 256)
        hs[idx] = g_m0[n0 * H_ + idx] + g_agg[n0 * H_ + idx];
    __syncthreads();
    float acc[NT];
#pragma unroll
    for (int i = 0; i < NT; i++) acc[i] = 0.f;
    int j = tid;
    for (int k = 0; k < H_; k++) {
        float w = Wp[k * W_ + j];
#pragma unroll
        for (int i = 0; i < NT; i++) acc[i] += hs[i * H_ + k] * w;
    }
    float bj = bp[j];
#pragma unroll
    for (int i = 0; i < NT; i++)
        out[(n0 + i) * W_ + j] = x[(n0 + i) * W_ + j] + acc[i] + bj;
}

extern "C" void kernel_launch(void* const* d_in, const int* in_sizes, int n_in,
                              void* d_out, int out_size) {
    const float* x          = (const float*)d_in[0];
    const int*   edge_index = (const int*)d_in[1];
    const int*   edge_attr  = (const int*)d_in[2];
    const float* edge_embed = (const float*)d_in[3];
    const float* emb0       = (const float*)d_in[4];
    const float* emb1       = (const float*)d_in[5];
    const float* emb2       = (const float*)d_in[6];
    const float* emb3       = (const float*)d_in[7];
    const float* init0_e    = (const float*)d_in[8];
    const float* init0      = (const float*)d_in[9];
    const float* W_pre      = (const float*)d_in[10];
    const float* b_pre      = (const float*)d_in[11];
    const float* W_msg0     = (const float*)d_in[12];
    const float* b_msg0     = (const float*)d_in[13];
    const float* W_q        = (const float*)d_in[14];
    const float* b_q        = (const float*)d_in[15];
    const float* W_k        = (const float*)d_in[16];
    const float* b_k        = (const float*)d_in[17];
    const float* W_v        = (const float*)d_in[18];
    const float* b_v        = (const float*)d_in[19];
    const float* W_r0       = (const float*)d_in[20];
    const float* b_r0       = (const float*)d_in[21];
    const float* W_r1       = (const float*)d_in[22];
    const float* b_r1       = (const float*)d_in[23];
    const float* W_r2       = (const float*)d_in[24];
    const float* b_r2       = (const float*)d_in[25];
    const float* W_post     = (const float*)d_in[26];
    const float* b_post     = (const float*)d_in[27];
    float* out = (float*)d_out;

    cudaFuncSetAttribute(k_edge, cudaFuncAttributeMaxDynamicSharedMemorySize, 163840);

    k_zero<<<(NN * H_ + 255) / 256, 256>>>();
    k_wf<<<384, 256>>>(W_r0, W_r1, W_r2);
    k_pre<<<NN / 8, 256>>>(x, W_pre, b_pre);
    k_eef<<<NE / 32, 256>>>(edge_attr, edge_embed, emb0, emb1, emb2, emb3, init0_e);
    k_proj<<<NN / 16, 512>>>(W_q, b_q, W_k, b_k, W_v, b_v, W_msg0, b_msg0,
                             b_r0, b_r1, b_r2, init0);
    k_edge<<<NE / 128, 256, 163840>>>(edge_index, init0);
    k_post<<<NN / 16, 256>>>(x, W_post, b_post, out);
}

// round 4
// speedup vs baseline: 1.5731x; 1.0277x over previous
#include <cuda_runtime.h>
#include <math.h>

#define NN 10000
#define NE 160000
#define W_ 256
#define H_ 512
#define EW_ 128

// Scratch (static device memory — no allocation allowed)
__device__ float g_xx[NN * W_];   // LN(pre(x))
__device__ float g_qn[NN * H_];   // xx@Wq + bq + br0*s_e
__device__ float g_kn[NN * H_];   // xx@Wk + bk + br1*s_e
__device__ float g_vn[NN * H_];   // xx@Wv + bv + br2*s_v (pre-gelu)
__device__ float g_m0[NN * H_];   // gelu(xx@Wm + bm)
__device__ float g_agg[NN * H_];  // scatter-add target
__device__ uint4 g_eef4[NE * 32];          // ee tf32, A-fragment order
__device__ uint2 g_wf2[16 * 3 * 8 * 8 * 32];  // Wr0..2 tf32, STAGE-contiguous B-frag order

__device__ __forceinline__ float gelu_erf(float h) {
    return 0.5f * h * (1.0f + erff(h * 0.70710678118654752f));
}

__device__ __forceinline__ unsigned f2tf(float x) {
    unsigned u;
    asm("cvt.rna.tf32.f32 %0, %1;" : "=r"(u) : "f"(x));
    return u;
}

__device__ __forceinline__ void mma8(float* d, const uint4& a, const uint2& b) {
    asm volatile(
        "mma.sync.aligned.m16n8k8.row.col.f32.tf32.tf32.f32 "
        "{%0,%1,%2,%3},{%4,%5,%6,%7},{%8,%9},{%0,%1,%2,%3};"
        : "+f"(d[0]), "+f"(d[1]), "+f"(d[2]), "+f"(d[3])
        : "r"(a.x), "r"(a.y), "r"(a.z), "r"(a.w), "r"(b.x), "r"(b.y));
}

__device__ __forceinline__ void red2(float* p, float x, float y) {
    asm volatile("red.global.add.v2.f32 [%0], {%1,%2};" :: "l"(p), "f"(x), "f"(y) : "memory");
}

// ---- mbarrier + bulk-copy helpers ----
__device__ __forceinline__ unsigned s2u(const void* p) {
    return (unsigned)__cvta_generic_to_shared(p);
}
__device__ __forceinline__ void mbar_init(unsigned mbar, unsigned cnt) {
    asm volatile("mbarrier.init.shared.b64 [%0], %1;" :: "r"(mbar), "r"(cnt) : "memory");
}
__device__ __forceinline__ void mbar_expect(unsigned mbar, unsigned bytes) {
    asm volatile("mbarrier.arrive.expect_tx.shared.b64 _, [%0], %1;"
                 :: "r"(mbar), "r"(bytes) : "memory");
}
__device__ __forceinline__ void bulk_g2s(unsigned dst, const void* src, unsigned bytes,
                                         unsigned mbar) {
    asm volatile("cp.async.bulk.shared::cta.global.mbarrier::complete_tx::bytes "
                 "[%0], [%1], %2, [%3];"
                 :: "r"(dst), "l"(src), "r"(bytes), "r"(mbar) : "memory");
}
__device__ __forceinline__ void mbar_wait(unsigned mbar, int phase) {
    asm volatile(
        "{\n\t.reg .pred P;\n\t"
        "W_%=:\n\t"
        "mbarrier.try_wait.parity.acquire.cta.shared::cta.b64 P, [%0], %1, 0x989680;\n\t"
        "@P bra.uni D_%=;\n\t"
        "bra.uni W_%=;\n\t"
        "D_%=:\n\t}"
        :: "r"(mbar), "r"(phase) : "memory");
}

__global__ void __launch_bounds__(256) k_zero() {
    int i = blockIdx.x * 256 + threadIdx.x;
    if (i < NN * H_) g_agg[i] = 0.f;
}

// Weight fragment pre-pass, stage-contiguous layout:
// stage = (nt>>3)*2 + (kt>>3); uidx = (((stage*3+m)*8 + (nt&7))*8 + (kt&7))*32 + lane
__global__ void __launch_bounds__(256) k_wf(const float* __restrict__ W0,
                                            const float* __restrict__ W1,
                                            const float* __restrict__ W2) {
    int idx = blockIdx.x * 256 + threadIdx.x;  // 0..98303
    int lane = idx & 31;
    int kt = (idx >> 5) & 15;
    int nt = (idx >> 9) & 63;
    int m = idx >> 15;
    const float* W = (m == 0) ? W0 : ((m == 1) ? W1 : W2);
    int tg = lane & 3, gid = lane >> 2;
    float b0 = W[(kt * 8 + tg) * H_ + nt * 8 + gid];
    float b1 = W[(kt * 8 + tg + 4) * H_ + nt * 8 + gid];
    int stage = ((nt >> 3) << 1) + (kt >> 3);
    int uidx = (((stage * 3 + m) * 8 + (nt & 7)) * 8 + (kt & 7)) * 32 + lane;
    unsigned* out = (unsigned*)g_wf2;
    out[uidx * 2 + 0] = f2tf(b0);
    out[uidx * 2 + 1] = f2tf(b1);
}

// ee pre-pass: embedding mix -> tf32 A-fragment order. 32 edges/block.
__global__ void __launch_bounds__(256) k_eef(const int* __restrict__ edge_attr,
                                             const float* __restrict__ edge_embed,
                                             const float* __restrict__ emb0,
                                             const float* __restrict__ emb1,
                                             const float* __restrict__ emb2,
                                             const float* __restrict__ emb3,
                                             const float* __restrict__ init0_e) {
    __shared__ float ee_s[32 * EW_];
    __shared__ int s_attr[128];
    int tid = threadIdx.x;
    int e0 = blockIdx.x * 32;
    if (tid < 128) s_attr[tid] = edge_attr[e0 * 4 + tid];
    float ew0 = expf(init0_e[0]), ew1 = expf(init0_e[1]);
    float ew2 = expf(init0_e[2]), ew3 = expf(init0_e[3]);
    float rs = rsqrtf(ew0 + ew1 + ew2 + ew3);
    ew0 *= rs; ew1 *= rs; ew2 *= rs; ew3 *= rs;
    __syncthreads();
    for (int idx = tid; idx < 32 * EW_; idx += 256) {
        int e = idx >> 7;
        int c = idx & (EW_ - 1);
        int a0 = s_attr[e * 4 + 0], a1 = s_attr[e * 4 + 1];
        int a2 = s_attr[e * 4 + 2], a3 = s_attr[e * 4 + 3];
        float v = emb0[a0 * EW_ + c] * ew0 + emb1[a1 * EW_ + c] * ew1 +
                  emb2[a2 * EW_ + c] * ew2 + emb3[a3 * EW_ + c] * ew3;
        ee_s[idx] = 0.5f * (v + edge_embed[(e0 + e) * EW_ + c]);
    }
    __syncthreads();
    unsigned* out = (unsigned*)g_eef4 + (size_t)blockIdx.x * 4096;
    for (int idx = tid; idx < 4096; idx += 256) {
        int fb = idx >> 7;       // frag block: local_et*16 + kt
        int w = idx & 127;
        int t = w >> 2;          // lane
        int i = w & 3;           // frag element
        int let = fb >> 4;
        int kt = fb & 15;
        int er = (t >> 2) + ((i & 1) << 3);
        int col = kt * 8 + (t & 3) + ((i & 2) << 1);
        out[idx] = f2tf(ee_s[(let * 16 + er) * EW_ + col]);
    }
}

// xx = LayerNorm(x @ W_pre + b_pre), 8 nodes per block, 256 threads
__global__ void __launch_bounds__(256) k_pre(const float* __restrict__ x,
                                             const float* __restrict__ Wp,
                                             const float* __restrict__ bp) {
    const int NT = 8;
    __shared__ float xs[NT * W_];
    __shared__ float ys[NT * W_];
    __shared__ float s_mean[NT], s_rstd[NT];
    int tid = threadIdx.x;
    int n0 = blockIdx.x * NT;
    for (int idx = tid; idx < NT * W_; idx += 256) xs[idx] = x[n0 * W_ + idx];
    __syncthreads();
    float acc[NT];
#pragma unroll
    for (int i = 0; i < NT; i++) acc[i] = 0.f;
    int j = tid;
    for (int k = 0; k < W_; k++) {
        float w = Wp[k * W_ + j];
#pragma unroll
        for (int i = 0; i < NT; i++) acc[i] += xs[i * W_ + k] * w;
    }
    float bj = bp[j];
#pragma unroll
    for (int i = 0; i < NT; i++) ys[i * W_ + j] = acc[i] + bj;
    __syncthreads();
    int wid = tid >> 5, lane = tid & 31;
    {
        float s = 0.f;
#pragma unroll
        for (int m = 0; m < W_ / 32; m++) s += ys[wid * W_ + lane + 32 * m];
#pragma unroll
        for (int off = 16; off > 0; off >>= 1) s += __shfl_xor_sync(0xffffffffu, s, off);
        float mean = s * (1.0f / W_);
        float v = 0.f;
#pragma unroll
        for (int m = 0; m < W_ / 32; m++) {
            float d = ys[wid * W_ + lane + 32 * m] - mean;
            v += d * d;
        }
#pragma unroll
        for (int off = 16; off > 0; off >>= 1) v += __shfl_xor_sync(0xffffffffu, v, off);
        if (lane == 0) {
            s_mean[wid] = mean;
            s_rstd[wid] = rsqrtf(v * (1.0f / W_) + 1e-5f);
        }
    }
    __syncthreads();
#pragma unroll
    for (int i = 0; i < NT; i++)
        g_xx[(n0 + i) * W_ + j] = (ys[i * W_ + j] - s_mean[i]) * s_rstd[i];
}

// Node projections with edge-bias folding
__global__ void __launch_bounds__(512) k_proj(const float* __restrict__ Wq, const float* __restrict__ bq,
                                              const float* __restrict__ Wk, const float* __restrict__ bk,
                                              const float* __restrict__ Wv, const float* __restrict__ bv,
                                              const float* __restrict__ Wm, const float* __restrict__ bm,
                                              const float* __restrict__ br0,
                                              const float* __restrict__ br1,
                                              const float* __restrict__ br2,
                                              const float* __restrict__ init0) {
    const int NT = 16;
    __shared__ float xs[NT * W_];
    int tid = threadIdx.x;
    int n0 = blockIdx.x * NT;
    float s_e = expf(init0[2]);
    float s_v = expf(init0[3]);
    for (int idx = tid; idx < NT * W_; idx += 512) xs[idx] = g_xx[n0 * W_ + idx];
    __syncthreads();
    float aq[NT], ak[NT], av[NT], am[NT];
#pragma unroll
    for (int i = 0; i < NT; i++) { aq[i] = 0.f; ak[i] = 0.f; av[i] = 0.f; am[i] = 0.f; }
    int j = tid;
    for (int k = 0; k < W_; k++) {
        float wqv = Wq[k * H_ + j];
        float wkv = Wk[k * H_ + j];
        float wvv = Wv[k * H_ + j];
        float wmv = Wm[k * H_ + j];
#pragma unroll
        for (int i = 0; i < NT; i++) {
            float a = xs[i * W_ + k];
            aq[i] += a * wqv;
            ak[i] += a * wkv;
            av[i] += a * wvv;
            am[i] += a * wmv;
        }
    }
    float bqj = bq[j] + br0[j] * s_e;
    float bkj = bk[j] + br1[j] * s_e;
    float bvj = bv[j] + br2[j] * s_v;
    float bmj = bm[j];
#pragma unroll
    for (int i = 0; i < NT; i++) {
        int idx = (n0 + i) * H_ + j;
        g_qn[idx] = aq[i] + bqj;
        g_kn[idx] = ak[i] + bkj;
        g_vn[idx] = av[i] + bvj;
        g_m0[idx] = gelu_erf(am[i] + bmj);
    }
}

// ---------------------------------------------------------------------------
// Pipelined tensor-core edge kernel with cp.async.bulk feeds.
// 128 edges/block, 8 warps = 2 mg (64 edges) x 4 ng (16 cols).
// A (64KB) bulk-copied once; B streamed via 2-stage 48KB ring, each stage a
// SINGLE cp.async.bulk (issue cost ~0) with mbarrier completion.
// ---------------------------------------------------------------------------
__global__ void __launch_bounds__(256, 1) k_edge(const int* __restrict__ edge_index,
                                                 const float* __restrict__ init0) {
    extern __shared__ char dsm[];
    uint4* a_sm = (uint4*)dsm;              // [8 mtile][16 kt][32 lane] = 64KB
    uint2* b_sm = (uint2*)(dsm + 65536);    // [2 buf][3 m][8 nt8][8 ktl][32 lane] = 96KB
    __shared__ int s_src[128], s_dst[128];
    __shared__ float p_buf[4][128];
    __shared__ __align__(8) unsigned long long mbar_s[3];  // A, buf0, buf1

    int tid = threadIdx.x;
    int lane = tid & 31, wid = tid >> 5;
    int mg = wid >> 2;        // 0..1  (64 edges)
    int ng = wid & 3;         // 0..3  (16 cols)
    int gid = lane >> 2, tg = lane & 3;
    int e0 = blockIdx.x * 128;

    unsigned mbA = s2u(&mbar_s[0]);
    unsigned mb0 = s2u(&mbar_s[1]);
    unsigned mb1 = s2u(&mbar_s[2]);

    if (tid < 128) {
        s_src[tid] = edge_index[e0 + tid];
        s_dst[tid] = edge_index[NE + e0 + tid];
    }
    if (tid == 0) {
        mbar_init(mbA, 1);
        mbar_init(mb0, 1);
        mbar_init(mb1, 1);
    }
    float s_e = expf(init0[2]);
    float s_v = expf(init0[3]);
    float c0 = init0[0] * 0.125f;
    float c1 = init0[1];
    __syncthreads();

    // Prologue: A (64KB) + B stage 0 -> buf0, stage 1 -> buf1
    if (tid == 0) {
        mbar_expect(mbA, 65536);
        bulk_g2s(s2u(a_sm), g_eef4 + (size_t)blockIdx.x * 4096, 65536, mbA);
        mbar_expect(mb0, 49152);
        bulk_g2s(s2u(b_sm), g_wf2, 49152, mb0);
        mbar_expect(mb1, 49152);
        bulk_g2s(s2u(b_sm + 6144), g_wf2 + 6144, 49152, mb1);
    }

    const uint4* aw = a_sm + mg * 4 * 512 + lane;
    const uint2* bw = b_sm + ng * 512 + lane;

    mbar_wait(mbA, 0);
    int ph0 = 0, ph1 = 0;

#pragma unroll 1
    for (int chunk = 0; chunk < 8; chunk++) {
        float acc[3][4][2][4];
#pragma unroll
        for (int m = 0; m < 3; m++)
#pragma unroll
            for (int mt = 0; mt < 4; mt++)
#pragma unroll
                for (int nt = 0; nt < 2; nt++)
#pragma unroll
                    for (int c = 0; c < 4; c++) acc[m][mt][nt][c] = 0.f;

        // ---- even half: stage 2*chunk in buf0, kt 0..7 ----
        mbar_wait(mb0, ph0);
        ph0 ^= 1;
#pragma unroll 2
        for (int ktl = 0; ktl < 8; ktl++) {
            uint4 av4[4];
#pragma unroll
            for (int mt = 0; mt < 4; mt++) av4[mt] = aw[mt * 512 + ktl * 32];
            uint2 bv[3][2];
#pragma unroll
            for (int m = 0; m < 3; m++)
#pragma unroll
                for (int nt = 0; nt < 2; nt++)
                    bv[m][nt] = bw[m * 2048 + nt * 256 + ktl * 32];
#pragma unroll
            for (int m = 0; m < 3; m++)
#pragma unroll
                for (int mt = 0; mt < 4; mt++)
#pragma unroll
                    for (int nt = 0; nt < 2; nt++)
                        mma8(acc[m][mt][nt], av4[mt], bv[m][nt]);
        }
        __syncthreads();  // all warps done with buf0
        if (tid == 0 && chunk < 7) {
            mbar_expect(mb0, 49152);
            bulk_g2s(s2u(b_sm), g_wf2 + (size_t)(chunk * 2 + 2) * 6144, 49152, mb0);
        }

        // ---- odd half: stage 2*chunk+1 in buf1, kt 8..15 ----
        mbar_wait(mb1, ph1);
        ph1 ^= 1;
#pragma unroll 2
        for (int ktl = 0; ktl < 8; ktl++) {
            uint4 av4[4];
#pragma unroll
            for (int mt = 0; mt < 4; mt++) av4[mt] = aw[mt * 512 + (8 + ktl) * 32];
            uint2 bv[3][2];
#pragma unroll
            for (int m = 0; m < 3; m++)
#pragma unroll
                for (int nt = 0; nt < 2; nt++)
                    bv[m][nt] = bw[6144 + m * 2048 + nt * 256 + ktl * 32];
#pragma unroll
            for (int m = 0; m < 3; m++)
#pragma unroll
                for (int mt = 0; mt < 4; mt++)
#pragma unroll
                    for (int nt = 0; nt < 2; nt++)
                        mma8(acc[m][mt][nt], av4[mt], bv[m][nt]);
        }

        // ---- attention partial dots ----
        float p[4][2];
#pragma unroll
        for (int mt = 0; mt < 4; mt++) { p[mt][0] = 0.f; p[mt][1] = 0.f; }
#pragma unroll
        for (int mt = 0; mt < 4; mt++) {
            int el = mg * 64 + mt * 16 + gid;
            int d0 = s_dst[el], d1 = s_dst[el + 8];
            int s0 = s_src[el], s1 = s_src[el + 8];
#pragma unroll
            for (int nt = 0; nt < 2; nt++) {
                int colg = chunk * 64 + ng * 16 + nt * 8 + tg * 2;
                float2 q0 = *(const float2*)(g_qn + (size_t)d0 * H_ + colg);
                float2 k0 = *(const float2*)(g_kn + (size_t)s0 * H_ + colg);
                p[mt][0] += (q0.x + acc[0][mt][nt][0] * s_e) * (k0.x + acc[1][mt][nt][0] * s_e)
                          + (q0.y + acc[0][mt][nt][1] * s_e) * (k0.y + acc[1][mt][nt][1] * s_e);
                float2 q1 = *(const float2*)(g_qn + (size_t)d1 * H_ + colg);
                float2 k1 = *(const float2*)(g_kn + (size_t)s1 * H_ + colg);
                p[mt][1] += (q1.x + acc[0][mt][nt][2] * s_e) * (k1.x + acc[1][mt][nt][2] * s_e)
                          + (q1.y + acc[0][mt][nt][3] * s_e) * (k1.y + acc[1][mt][nt][3] * s_e);
            }
        }
#pragma unroll
        for (int off = 1; off <= 2; off <<= 1)
#pragma unroll
            for (int mt = 0; mt < 4; mt++) {
                p[mt][0] += __shfl_xor_sync(0xffffffffu, p[mt][0], off);
                p[mt][1] += __shfl_xor_sync(0xffffffffu, p[mt][1], off);
            }
        __syncthreads();   // all warps done reading buf1 (+ p_buf prev chunk)
        if (tg == 0) {
#pragma unroll
            for (int mt = 0; mt < 4; mt++) {
                int el = mg * 64 + mt * 16 + gid;
                p_buf[ng][el] = p[mt][0];
                p_buf[ng][el + 8] = p[mt][1];
            }
        }
        __syncthreads();
        if (tid == 0 && chunk < 7) {
            mbar_expect(mb1, 49152);
            bulk_g2s(s2u(b_sm + 6144), g_wf2 + (size_t)(chunk * 2 + 3) * 6144, 49152, mb1);
        }

        // ---- V epilogue: gelu + att scale + vector scatter-add ----
#pragma unroll
        for (int mt = 0; mt < 4; mt++) {
            int el = mg * 64 + mt * 16 + gid;
            float sum0 = p_buf[0][el] + p_buf[1][el] + p_buf[2][el] + p_buf[3][el];
            float sum1 = p_buf[0][el + 8] + p_buf[1][el + 8] + p_buf[2][el + 8] + p_buf[3][el + 8];
            float att0 = expf(sum0 * c0 + c1);
            float att1 = expf(sum1 * c0 + c1);
            int d0 = s_dst[el], d1 = s_dst[el + 8];
            int s0 = s_src[el], s1 = s_src[el + 8];
#pragma unroll
            for (int nt = 0; nt < 2; nt++) {
                int colg = chunk * 64 + ng * 16 + nt * 8 + tg * 2;
                float2 v0 = *(const float2*)(g_vn + (size_t)s0 * H_ + colg);
                float xv0 = gelu_erf(v0.x + acc[2][mt][nt][0] * s_v) * att0;
                float xv1 = gelu_erf(v0.y + acc[2][mt][nt][1] * s_v) * att0;
                red2(g_agg + (size_t)d0 * H_ + colg, xv0, xv1);
                float2 v1 = *(const float2*)(g_vn + (size_t)s1 * H_ + colg);
                float xv2 = gelu_erf(v1.x + acc[2][mt][nt][2] * s_v) * att1;
                float xv3 = gelu_erf(v1.y + acc[2][mt][nt][3] * s_v) * att1;
                red2(g_agg + (size_t)d1 * H_ + colg, xv2, xv3);
            }
        }
    }
}

// out = x + (m0 + agg) @ W_post + b_post
__global__ void __launch_bounds__(256) k_post(const float* __restrict__ x,
                                              const float* __restrict__ Wp,
                                              const float* __restrict__ bp,
                                              float* __restrict__ out) {
    const int NT = 16;
    __shared__ float hs[NT * H_];
    int tid = threadIdx.x;
    int n0 = blockIdx.x * NT;
    for (int idx = tid; idx < NT * H_; idx += 256)
        hs[idx] = g_m0[n0 * H_ + idx] + g_agg[n0 * H_ + idx];
    __syncthreads();
    float acc[NT];
#pragma unroll
    for (int i = 0; i < NT; i++) acc[i] = 0.f;
    int j = tid;
    for (int k = 0; k < H_; k++) {
        float w = Wp[k * W_ + j];
#pragma unroll
        for (int i = 0; i < NT; i++) acc[i] += hs[i * H_ + k] * w;
    }
    float bj = bp[j];
#pragma unroll
    for (int i = 0; i < NT; i++)
        out[(n0 + i) * W_ + j] = x[(n0 + i) * W_ + j] + acc[i] + bj;
}

extern "C" void kernel_launch(void* const* d_in, const int* in_sizes, int n_in,
                              void* d_out, int out_size) {
    const float* x          = (const float*)d_in[0];
    const int*   edge_index = (const int*)d_in[1];
    const int*   edge_attr  = (const int*)d_in[2];
    const float* edge_embed = (const float*)d_in[3];
    const float* emb0       = (const float*)d_in[4];
    const float* emb1       = (const float*)d_in[5];
    const float* emb2       = (const float*)d_in[6];
    const float* emb3       = (const float*)d_in[7];
    const float* init0_e    = (const float*)d_in[8];
    const float* init0      = (const float*)d_in[9];
    const float* W_pre      = (const float*)d_in[10];
    const float* b_pre      = (const float*)d_in[11];
    const float* W_msg0     = (const float*)d_in[12];
    const float* b_msg0     = (const float*)d_in[13];
    const float* W_q        = (const float*)d_in[14];
    const float* b_q        = (const float*)d_in[15];
    const float* W_k        = (const float*)d_in[16];
    const float* b_k        = (const float*)d_in[17];
    const float* W_v        = (const float*)d_in[18];
    const float* b_v        = (const float*)d_in[19];
    const float* W_r0       = (const float*)d_in[20];
    const float* b_r0       = (const float*)d_in[21];
    const float* W_r1       = (const float*)d_in[22];
    const float* b_r1       = (const float*)d_in[23];
    const float* W_r2       = (const float*)d_in[24];
    const float* b_r2       = (const float*)d_in[25];
    const float* W_post     = (const float*)d_in[26];
    const float* b_post     = (const float*)d_in[27];
    float* out = (float*)d_out;

    cudaFuncSetAttribute(k_edge, cudaFuncAttributeMaxDynamicSharedMemorySize, 163840);

    k_zero<<<(NN * H_ + 255) / 256, 256>>>();
    k_wf<<<384, 256>>>(W_r0, W_r1, W_r2);
    k_pre<<<NN / 8, 256>>>(x, W_pre, b_pre);
    k_eef<<<NE / 32, 256>>>(edge_attr, edge_embed, emb0, emb1, emb2, emb3, init0_e);
    k_proj<<<NN / 16, 512>>>(W_q, b_q, W_k, b_k, W_v, b_v, W_msg0, b_msg0,
                             b_r0, b_r1, b_r2, init0);
    k_edge<<<NE / 128, 256, 163840>>>(edge_index, init0);
    k_post<<<NN / 16, 256>>>(x, W_post, b_post, out);
}

// round 5
// speedup vs baseline: 2.0087x; 1.2769x over previous
#include <cuda_runtime.h>
#include <math.h>

#define NN 10000
#define NE 160000
#define W_ 256
#define H_ 512
#define EW_ 128

// Scratch (static device memory — no allocation allowed)
__device__ float g_xx[NN * W_];   // LN(pre(x))
__device__ float g_qn[NN * H_];   // xx@Wq + bq + br0*s_e
__device__ float g_kn[NN * H_];   // xx@Wk + bk + br1*s_e
__device__ float g_vn[NN * H_];   // xx@Wv + bv + br2*s_v (pre-gelu)
__device__ float g_m0[NN * H_];   // gelu(xx@Wm + bm)
__device__ float g_agg[NN * H_];  // scatter-add target
__device__ uint4 g_eef4[NE * 32];          // ee tf32, A-fragment order
__device__ uint2 g_wf2[16 * 3 * 8 * 8 * 32];  // Wr0..2 tf32, STAGE-contiguous B-frag order

__device__ __forceinline__ float gelu_erf(float h) {
    return 0.5f * h * (1.0f + erff(h * 0.70710678118654752f));
}

__device__ __forceinline__ unsigned f2tf(float x) {
    unsigned u;
    asm("cvt.rna.tf32.f32 %0, %1;" : "=r"(u) : "f"(x));
    return u;
}

__device__ __forceinline__ void mma8(float* d, const uint4& a, const uint2& b) {
    asm volatile(
        "mma.sync.aligned.m16n8k8.row.col.f32.tf32.tf32.f32 "
        "{%0,%1,%2,%3},{%4,%5,%6,%7},{%8,%9},{%0,%1,%2,%3};"
        : "+f"(d[0]), "+f"(d[1]), "+f"(d[2]), "+f"(d[3])
        : "r"(a.x), "r"(a.y), "r"(a.z), "r"(a.w), "r"(b.x), "r"(b.y));
}

__device__ __forceinline__ void red2(float* p, float x, float y) {
    asm volatile("red.global.add.v2.f32 [%0], {%1,%2};" :: "l"(p), "f"(x), "f"(y) : "memory");
}

// ---- mbarrier + bulk-copy helpers ----
__device__ __forceinline__ unsigned s2u(const void* p) {
    return (unsigned)__cvta_generic_to_shared(p);
}
__device__ __forceinline__ void mbar_init(unsigned mbar, unsigned cnt) {
    asm volatile("mbarrier.init.shared.b64 [%0], %1;" :: "r"(mbar), "r"(cnt) : "memory");
}
__device__ __forceinline__ void mbar_expect(unsigned mbar, unsigned bytes) {
    asm volatile("mbarrier.arrive.expect_tx.shared.b64 _, [%0], %1;"
                 :: "r"(mbar), "r"(bytes) : "memory");
}
__device__ __forceinline__ void bulk_g2s(unsigned dst, const void* src, unsigned bytes,
                                         unsigned mbar) {
    asm volatile("cp.async.bulk.shared::cta.global.mbarrier::complete_tx::bytes "
                 "[%0], [%1], %2, [%3];"
                 :: "r"(dst), "l"(src), "r"(bytes), "r"(mbar) : "memory");
}
__device__ __forceinline__ void mbar_wait(unsigned mbar, int phase) {
    asm volatile(
        "{\n\t.reg .pred P;\n\t"
        "W_%=:\n\t"
        "mbarrier.try_wait.parity.acquire.cta.shared::cta.b64 P, [%0], %1, 0x989680;\n\t"
        "@P bra.uni D_%=;\n\t"
        "bra.uni W_%=;\n\t"
        "D_%=:\n\t}"
        :: "r"(mbar), "r"(phase) : "memory");
}

// Merged: blocks [0,384) = weight-fragment pre-pass; blocks [384,5384) = ee pre-pass.
__global__ void __launch_bounds__(256) k_wfeef(const float* __restrict__ W0,
                                               const float* __restrict__ W1,
                                               const float* __restrict__ W2,
                                               const int* __restrict__ edge_attr,
                                               const float* __restrict__ edge_embed,
                                               const float* __restrict__ emb0,
                                               const float* __restrict__ emb1,
                                               const float* __restrict__ emb2,
                                               const float* __restrict__ emb3,
                                               const float* __restrict__ init0_e) {
    __shared__ float ee_s[32 * EW_];
    __shared__ int s_attr[128];
    int tid = threadIdx.x;
    if (blockIdx.x < 384) {
        // Weight fragments, stage-contiguous layout
        int idx = blockIdx.x * 256 + tid;  // 0..98303
        int lane = idx & 31;
        int kt = (idx >> 5) & 15;
        int nt = (idx >> 9) & 63;
        int m = idx >> 15;
        const float* W = (m == 0) ? W0 : ((m == 1) ? W1 : W2);
        int tg = lane & 3, gid = lane >> 2;
        float b0 = W[(kt * 8 + tg) * H_ + nt * 8 + gid];
        float b1 = W[(kt * 8 + tg + 4) * H_ + nt * 8 + gid];
        int stage = ((nt >> 3) << 1) + (kt >> 3);
        int uidx = (((stage * 3 + m) * 8 + (nt & 7)) * 8 + (kt & 7)) * 32 + lane;
        unsigned* out = (unsigned*)g_wf2;
        out[uidx * 2 + 0] = f2tf(b0);
        out[uidx * 2 + 1] = f2tf(b1);
        return;
    }
    int blk = blockIdx.x - 384;
    int e0 = blk * 32;
    if (tid < 128) s_attr[tid] = edge_attr[e0 * 4 + tid];
    float ew0 = expf(init0_e[0]), ew1 = expf(init0_e[1]);
    float ew2 = expf(init0_e[2]), ew3 = expf(init0_e[3]);
    float rs = rsqrtf(ew0 + ew1 + ew2 + ew3);
    ew0 *= rs; ew1 *= rs; ew2 *= rs; ew3 *= rs;
    __syncthreads();
    for (int idx = tid; idx < 32 * EW_; idx += 256) {
        int e = idx >> 7;
        int c = idx & (EW_ - 1);
        int a0 = s_attr[e * 4 + 0], a1 = s_attr[e * 4 + 1];
        int a2 = s_attr[e * 4 + 2], a3 = s_attr[e * 4 + 3];
        float v = emb0[a0 * EW_ + c] * ew0 + emb1[a1 * EW_ + c] * ew1 +
                  emb2[a2 * EW_ + c] * ew2 + emb3[a3 * EW_ + c] * ew3;
        ee_s[idx] = 0.5f * (v + edge_embed[(e0 + e) * EW_ + c]);
    }
    __syncthreads();
    unsigned* out = (unsigned*)g_eef4 + (size_t)blk * 4096;
    for (int idx = tid; idx < 4096; idx += 256) {
        int fb = idx >> 7;       // frag block: local_et*16 + kt
        int w = idx & 127;
        int t = w >> 2;          // lane
        int i = w & 3;           // frag element
        int let = fb >> 4;
        int kt = fb & 15;
        int er = (t >> 2) + ((i & 1) << 3);
        int col = kt * 8 + (t & 3) + ((i & 2) << 1);
        out[idx] = f2tf(ee_s[(let * 16 + er) * EW_ + col]);
    }
}

// xx = LayerNorm(x @ W_pre + b_pre), 8 nodes per block, 256 threads
__global__ void __launch_bounds__(256) k_pre(const float* __restrict__ x,
                                             const float* __restrict__ Wp,
                                             const float* __restrict__ bp) {
    const int NT = 8;
    __shared__ float xs[NT * W_];
    __shared__ float ys[NT * W_];
    __shared__ float s_mean[NT], s_rstd[NT];
    int tid = threadIdx.x;
    int n0 = blockIdx.x * NT;
    for (int idx = tid; idx < NT * W_; idx += 256) xs[idx] = x[n0 * W_ + idx];
    __syncthreads();
    float acc[NT];
#pragma unroll
    for (int i = 0; i < NT; i++) acc[i] = 0.f;
    int j = tid;
    for (int k = 0; k < W_; k++) {
        float w = Wp[k * W_ + j];
#pragma unroll
        for (int i = 0; i < NT; i++) acc[i] += xs[i * W_ + k] * w;
    }
    float bj = bp[j];
#pragma unroll
    for (int i = 0; i < NT; i++) ys[i * W_ + j] = acc[i] + bj;
    __syncthreads();
    int wid = tid >> 5, lane = tid & 31;
    {
        float s = 0.f;
#pragma unroll
        for (int m = 0; m < W_ / 32; m++) s += ys[wid * W_ + lane + 32 * m];
#pragma unroll
        for (int off = 16; off > 0; off >>= 1) s += __shfl_xor_sync(0xffffffffu, s, off);
        float mean = s * (1.0f / W_);
        float v = 0.f;
#pragma unroll
        for (int m = 0; m < W_ / 32; m++) {
            float d = ys[wid * W_ + lane + 32 * m] - mean;
            v += d * d;
        }
#pragma unroll
        for (int off = 16; off > 0; off >>= 1) v += __shfl_xor_sync(0xffffffffu, v, off);
        if (lane == 0) {
            s_mean[wid] = mean;
            s_rstd[wid] = rsqrtf(v * (1.0f / W_) + 1e-5f);
        }
    }
    __syncthreads();
#pragma unroll
    for (int i = 0; i < NT; i++)
        g_xx[(n0 + i) * W_ + j] = (ys[i * W_ + j] - s_mean[i]) * s_rstd[i];
}

// Node projections with edge-bias folding + g_agg zeroing (same index space)
__global__ void __launch_bounds__(512) k_projz(const float* __restrict__ Wq, const float* __restrict__ bq,
                                               const float* __restrict__ Wk, const float* __restrict__ bk,
                                               const float* __restrict__ Wv, const float* __restrict__ bv,
                                               const float* __restrict__ Wm, const float* __restrict__ bm,
                                               const float* __restrict__ br0,
                                               const float* __restrict__ br1,
                                               const float* __restrict__ br2,
                                               const float* __restrict__ init0) {
    const int NT = 16;
    __shared__ float xs[NT * W_];
    int tid = threadIdx.x;
    int n0 = blockIdx.x * NT;
    float s_e = expf(init0[2]);
    float s_v = expf(init0[3]);
    for (int idx = tid; idx < NT * W_; idx += 512) xs[idx] = g_xx[n0 * W_ + idx];
    __syncthreads();
    float aq[NT], ak[NT], av[NT], am[NT];
#pragma unroll
    for (int i = 0; i < NT; i++) { aq[i] = 0.f; ak[i] = 0.f; av[i] = 0.f; am[i] = 0.f; }
    int j = tid;
    for (int k = 0; k < W_; k++) {
        float wqv = Wq[k * H_ + j];
        float wkv = Wk[k * H_ + j];
        float wvv = Wv[k * H_ + j];
        float wmv = Wm[k * H_ + j];
#pragma unroll
        for (int i = 0; i < NT; i++) {
            float a = xs[i * W_ + k];
            aq[i] += a * wqv;
            ak[i] += a * wkv;
            av[i] += a * wvv;
            am[i] += a * wmv;
        }
    }
    float bqj = bq[j] + br0[j] * s_e;
    float bkj = bk[j] + br1[j] * s_e;
    float bvj = bv[j] + br2[j] * s_v;
    float bmj = bm[j];
#pragma unroll
    for (int i = 0; i < NT; i++) {
        int idx = (n0 + i) * H_ + j;
        g_qn[idx] = aq[i] + bqj;
        g_kn[idx] = ak[i] + bkj;
        g_vn[idx] = av[i] + bvj;
        g_m0[idx] = gelu_erf(am[i] + bmj);
        g_agg[idx] = 0.f;
    }
}

// ---------------------------------------------------------------------------
// Pipelined tensor-core edge kernel with cp.async.bulk feeds and register
// prefetch of the q/k/v gathers so their L2 latency hides under the mma work.
// 128 edges/block, 8 warps = 2 mg (64 edges) x 4 ng (16 cols).
// ---------------------------------------------------------------------------
__global__ void __launch_bounds__(256, 1) k_edge(const int* __restrict__ edge_index,
                                                 const float* __restrict__ init0) {
    extern __shared__ char dsm[];
    uint4* a_sm = (uint4*)dsm;              // [8 mtile][16 kt][32 lane] = 64KB
    uint2* b_sm = (uint2*)(dsm + 65536);    // [2 buf][3 m][8 nt8][8 ktl][32 lane] = 96KB
    __shared__ int s_src[128], s_dst[128];
    __shared__ float p_buf[4][128];
    __shared__ __align__(8) unsigned long long mbar_s[3];  // A, buf0, buf1

    int tid = threadIdx.x;
    int lane = tid & 31, wid = tid >> 5;
    int mg = wid >> 2;        // 0..1  (64 edges)
    int ng = wid & 3;         // 0..3  (16 cols)
    int gid = lane >> 2, tg = lane & 3;
    int e0 = blockIdx.x * 128;

    unsigned mbA = s2u(&mbar_s[0]);
    unsigned mb0 = s2u(&mbar_s[1]);
    unsigned mb1 = s2u(&mbar_s[2]);

    if (tid < 128) {
        s_src[tid] = edge_index[e0 + tid];
        s_dst[tid] = edge_index[NE + e0 + tid];
    }
    if (tid == 0) {
        mbar_init(mbA, 1);
        mbar_init(mb0, 1);
        mbar_init(mb1, 1);
    }
    float s_e = expf(init0[2]);
    float s_v = expf(init0[3]);
    float c0 = init0[0] * 0.125f;
    float c1 = init0[1];
    __syncthreads();

    // Prologue: A (64KB) + B stage 0 -> buf0, stage 1 -> buf1
    if (tid == 0) {
        mbar_expect(mbA, 65536);
        bulk_g2s(s2u(a_sm), g_eef4 + (size_t)blockIdx.x * 4096, 65536, mbA);
        mbar_expect(mb0, 49152);
        bulk_g2s(s2u(b_sm), g_wf2, 49152, mb0);
        mbar_expect(mb1, 49152);
        bulk_g2s(s2u(b_sm + 6144), g_wf2 + 6144, 49152, mb1);
    }

    // chunk-invariant gather rows
    int rd0[4], rd1[4], rs0[4], rs1[4];
#pragma unroll
    for (int mt = 0; mt < 4; mt++) {
        int el = mg * 64 + mt * 16 + gid;
        rd0[mt] = s_dst[el];
        rd1[mt] = s_dst[el + 8];
        rs0[mt] = s_src[el];
        rs1[mt] = s_src[el + 8];
    }

    const uint4* aw = a_sm + mg * 4 * 512 + lane;
    const uint2* bw = b_sm + ng * 512 + lane;

    mbar_wait(mbA, 0);
    int ph0 = 0, ph1 = 0;

#pragma unroll 1
    for (int chunk = 0; chunk < 8; chunk++) {
        float acc[3][4][2][4];
#pragma unroll
        for (int m = 0; m < 3; m++)
#pragma unroll
            for (int mt = 0; mt < 4; mt++)
#pragma unroll
                for (int nt = 0; nt < 2; nt++)
#pragma unroll
                    for (int c = 0; c < 4; c++) acc[m][mt][nt][c] = 0.f;

        int colbase = chunk * 64 + ng * 16 + tg * 2;

        // ---- prefetch q/k gathers: latency hides under both mma halves ----
        float2 qv[4][2][2], kv[4][2][2];
#pragma unroll
        for (int mt = 0; mt < 4; mt++)
#pragma unroll
            for (int nt = 0; nt < 2; nt++) {
                int colg = colbase + nt * 8;
                qv[mt][nt][0] = *(const float2*)(g_qn + (size_t)rd0[mt] * H_ + colg);
                qv[mt][nt][1] = *(const float2*)(g_qn + (size_t)rd1[mt] * H_ + colg);
                kv[mt][nt][0] = *(const float2*)(g_kn + (size_t)rs0[mt] * H_ + colg);
                kv[mt][nt][1] = *(const float2*)(g_kn + (size_t)rs1[mt] * H_ + colg);
            }

        // ---- even half: stage 2*chunk in buf0, kt 0..7 ----
        mbar_wait(mb0, ph0);
        ph0 ^= 1;
#pragma unroll 2
        for (int ktl = 0; ktl < 8; ktl++) {
            uint4 av4[4];
#pragma unroll
            for (int mt = 0; mt < 4; mt++) av4[mt] = aw[mt * 512 + ktl * 32];
            uint2 bv[3][2];
#pragma unroll
            for (int m = 0; m < 3; m++)
#pragma unroll
                for (int nt = 0; nt < 2; nt++)
                    bv[m][nt] = bw[m * 2048 + nt * 256 + ktl * 32];
#pragma unroll
            for (int m = 0; m < 3; m++)
#pragma unroll
                for (int mt = 0; mt < 4; mt++)
#pragma unroll
                    for (int nt = 0; nt < 2; nt++)
                        mma8(acc[m][mt][nt], av4[mt], bv[m][nt]);
        }
        __syncthreads();  // all warps done with buf0
        if (tid == 0 && chunk < 7) {
            mbar_expect(mb0, 49152);
            bulk_g2s(s2u(b_sm), g_wf2 + (size_t)(chunk * 2 + 2) * 6144, 49152, mb0);
        }

        // ---- prefetch v gathers: latency hides under odd mma half ----
        float2 vv[4][2][2];
#pragma unroll
        for (int mt = 0; mt < 4; mt++)
#pragma unroll
            for (int nt = 0; nt < 2; nt++) {
                int colg = colbase + nt * 8;
                vv[mt][nt][0] = *(const float2*)(g_vn + (size_t)rs0[mt] * H_ + colg);
                vv[mt][nt][1] = *(const float2*)(g_vn + (size_t)rs1[mt] * H_ + colg);
            }

        // ---- odd half: stage 2*chunk+1 in buf1, kt 8..15 ----
        mbar_wait(mb1, ph1);
        ph1 ^= 1;
#pragma unroll 2
        for (int ktl = 0; ktl < 8; ktl++) {
            uint4 av4[4];
#pragma unroll
            for (int mt = 0; mt < 4; mt++) av4[mt] = aw[mt * 512 + (8 + ktl) * 32];
            uint2 bv[3][2];
#pragma unroll
            for (int m = 0; m < 3; m++)
#pragma unroll
                for (int nt = 0; nt < 2; nt++)
                    bv[m][nt] = bw[6144 + m * 2048 + nt * 256 + ktl * 32];
#pragma unroll
            for (int m = 0; m < 3; m++)
#pragma unroll
                for (int mt = 0; mt < 4; mt++)
#pragma unroll
                    for (int nt = 0; nt < 2; nt++)
                        mma8(acc[m][mt][nt], av4[mt], bv[m][nt]);
        }

        // ---- attention partial dots (registers only) ----
        float p[4][2];
#pragma unroll
        for (int mt = 0; mt < 4; mt++) { p[mt][0] = 0.f; p[mt][1] = 0.f; }
#pragma unroll
        for (int mt = 0; mt < 4; mt++)
#pragma unroll
            for (int nt = 0; nt < 2; nt++) {
                p[mt][0] += (qv[mt][nt][0].x + acc[0][mt][nt][0] * s_e) * (kv[mt][nt][0].x + acc[1][mt][nt][0] * s_e)
                          + (qv[mt][nt][0].y + acc[0][mt][nt][1] * s_e) * (kv[mt][nt][0].y + acc[1][mt][nt][1] * s_e);
                p[mt][1] += (qv[mt][nt][1].x + acc[0][mt][nt][2] * s_e) * (kv[mt][nt][1].x + acc[1][mt][nt][2] * s_e)
                          + (qv[mt][nt][1].y + acc[0][mt][nt][3] * s_e) * (kv[mt][nt][1].y + acc[1][mt][nt][3] * s_e);
            }
#pragma unroll
        for (int off = 1; off <= 2; off <<= 1)
#pragma unroll
            for (int mt = 0; mt < 4; mt++) {
                p[mt][0] += __shfl_xor_sync(0xffffffffu, p[mt][0], off);
                p[mt][1] += __shfl_xor_sync(0xffffffffu, p[mt][1], off);
            }
        __syncthreads();   // all warps done reading buf1 (+ p_buf prev chunk)
        if (tg == 0) {
#pragma unroll
            for (int mt = 0; mt < 4; mt++) {
                int el = mg * 64 + mt * 16 + gid;
                p_buf[ng][el] = p[mt][0];
                p_buf[ng][el + 8] = p[mt][1];
            }
        }
        __syncthreads();
        if (tid == 0 && chunk < 7) {
            mbar_expect(mb1, 49152);
            bulk_g2s(s2u(b_sm + 6144), g_wf2 + (size_t)(chunk * 2 + 3) * 6144, 49152, mb1);
        }

        // ---- V epilogue: gelu + att scale + vector scatter-add ----
#pragma unroll
        for (int mt = 0; mt < 4; mt++) {
            int el = mg * 64 + mt * 16 + gid;
            float sum0 = p_buf[0][el] + p_buf[1][el] + p_buf[2][el] + p_buf[3][el];
            float sum1 = p_buf[0][el + 8] + p_buf[1][el + 8] + p_buf[2][el + 8] + p_buf[3][el + 8];
            float att0 = expf(sum0 * c0 + c1);
            float att1 = expf(sum1 * c0 + c1);
#pragma unroll
            for (int nt = 0; nt < 2; nt++) {
                int colg = colbase + nt * 8;
                float xv0 = gelu_erf(vv[mt][nt][0].x + acc[2][mt][nt][0] * s_v) * att0;
                float xv1 = gelu_erf(vv[mt][nt][0].y + acc[2][mt][nt][1] * s_v) * att0;
                red2(g_agg + (size_t)rd0[mt] * H_ + colg, xv0, xv1);
                float xv2 = gelu_erf(vv[mt][nt][1].x + acc[2][mt][nt][2] * s_v) * att1;
                float xv3 = gelu_erf(vv[mt][nt][1].y + acc[2][mt][nt][3] * s_v) * att1;
                red2(g_agg + (size_t)rd1[mt] * H_ + colg, xv2, xv3);
            }
        }
    }
}

// out = x + (m0 + agg) @ W_post + b_post
__global__ void __launch_bounds__(256) k_post(const float* __restrict__ x,
                                              const float* __restrict__ Wp,
                                              const float* __restrict__ bp,
                                              float* __restrict__ out) {
    const int NT = 16;
    __shared__ float hs[NT * H_];
    int tid = threadIdx.x;
    int n0 = blockIdx.x * NT;
    for (int idx = tid; idx < NT * H_; idx += 256)
        hs[idx] = g_m0[n0 * H_ + idx] + g_agg[n0 * H_ + idx];
    __syncthreads();
    float acc[NT];
#pragma unroll
    for (int i = 0; i < NT; i++) acc[i] = 0.f;
    int j = tid;
    for (int k = 0; k < H_; k++) {
        float w = Wp[k * W_ + j];
#pragma unroll
        for (int i = 0; i < NT; i++) acc[i] += hs[i * H_ + k] * w;
    }
    float bj = bp[j];
#pragma unroll
    for (int i = 0; i < NT; i++)
        out[(n0 + i) * W_ + j] = x[(n0 + i) * W_ + j] + acc[i] + bj;
}

extern "C" void kernel_launch(void* const* d_in, const int* in_sizes, int n_in,
                              void* d_out, int out_size) {
    const float* x          = (const float*)d_in[0];
    const int*   edge_index = (const int*)d_in[1];
    const int*   edge_attr  = (const int*)d_in[2];
    const float* edge_embed = (const float*)d_in[3];
    const float* emb0       = (const float*)d_in[4];
    const float* emb1       = (const float*)d_in[5];
    const float* emb2       = (const float*)d_in[6];
    const float* emb3       = (const float*)d_in[7];
    const float* init0_e    = (const float*)d_in[8];
    const float* init0      = (const float*)d_in[9];
    const float* W_pre      = (const float*)d_in[10];
    const float* b_pre      = (const float*)d_in[11];
    const float* W_msg0     = (const float*)d_in[12];
    const float* b_msg0     = (const float*)d_in[13];
    const float* W_q        = (const float*)d_in[14];
    const float* b_q        = (const float*)d_in[15];
    const float* W_k        = (const float*)d_in[16];
    const float* b_k        = (const float*)d_in[17];
    const float* W_v        = (const float*)d_in[18];
    const float* b_v        = (const float*)d_in[19];
    const float* W_r0       = (const float*)d_in[20];
    const float* b_r0       = (const float*)d_in[21];
    const float* W_r1       = (const float*)d_in[22];
    const float* b_r1       = (const float*)d_in[23];
    const float* W_r2       = (const float*)d_in[24];
    const float* b_r2       = (const float*)d_in[25];
    const float* W_post     = (const float*)d_in[26];
    const float* b_post     = (const float*)d_in[27];
    float* out = (float*)d_out;

    cudaFuncSetAttribute(k_edge, cudaFuncAttributeMaxDynamicSharedMemorySize, 163840);

    k_pre<<<NN / 8, 256>>>(x, W_pre, b_pre);
    k_wfeef<<<384 + NE / 32, 256>>>(W_r0, W_r1, W_r2, edge_attr, edge_embed,
                                    emb0, emb1, emb2, emb3, init0_e);
    k_projz<<<NN / 16, 512>>>(W_q, b_q, W_k, b_k, W_v, b_v, W_msg0, b_msg0,
                              b_r0, b_r1, b_r2, init0);
    k_edge<<<NE / 128, 256, 163840>>>(edge_index, init0);
    k_post<<<NN / 16, 256>>>(x, W_post, b_post, out);
}

// round 6
// speedup vs baseline: 2.5760x; 1.2824x over previous
#include <cuda_runtime.h>
#include <math.h>

#define NN 10000
#define NP 10048   // padded nodes (157 * 64)
#define NE 160000
#define W_ 256
#define H_ 512
#define EW_ 128

// Scratch (static device memory — no allocation allowed)
__device__ float g_qn[NN * H_];   // xx@Wq + bq + br0*s_e
__device__ float g_kn[NN * H_];   // xx@Wk + bk + br1*s_e
__device__ float g_vn[NN * H_];   // xx@Wv + bv + br2*s_v (pre-gelu)
__device__ float g_m0[NN * H_];   // gelu(xx@Wm + bm)
__device__ float g_agg[NN * H_];  // scatter-add target
__device__ uint4 g_eef4[NE * 32];             // ee tf32, A-fragment order
__device__ uint2 g_wf2[16 * 3 * 8 * 8 * 32];  // Wr0..2 tf32 (scales folded), stage-contiguous
__device__ uint2 g_wfn[32 * 8192];            // Wq/Wk/Wv/Wm tf32, stage-contiguous (2MB)
__device__ uint4 g_xxf[NP * 64];              // LN(pre(x)) tf32 A-fragments

__device__ __forceinline__ float gelu_erf(float h) {
    return 0.5f * h * (1.0f + erff(h * 0.70710678118654752f));
}

__device__ __forceinline__ unsigned f2tf(float x) {
    unsigned u;
    asm("cvt.rna.tf32.f32 %0, %1;" : "=r"(u) : "f"(x));
    return u;
}

__device__ __forceinline__ void mma8(float* d, const uint4& a, const uint2& b) {
    asm volatile(
        "mma.sync.aligned.m16n8k8.row.col.f32.tf32.tf32.f32 "
        "{%0,%1,%2,%3},{%4,%5,%6,%7},{%8,%9},{%0,%1,%2,%3};"
        : "+f"(d[0]), "+f"(d[1]), "+f"(d[2]), "+f"(d[3])
        : "r"(a.x), "r"(a.y), "r"(a.z), "r"(a.w), "r"(b.x), "r"(b.y));
}

__device__ __forceinline__ void red2(float* p, float x, float y) {
    asm volatile("red.global.add.v2.f32 [%0], {%1,%2};" :: "l"(p), "f"(x), "f"(y) : "memory");
}

// ---- mbarrier + bulk-copy helpers ----
__device__ __forceinline__ unsigned s2u(const void* p) {
    return (unsigned)__cvta_generic_to_shared(p);
}
__device__ __forceinline__ void mbar_init(unsigned mbar, unsigned cnt) {
    asm volatile("mbarrier.init.shared.b64 [%0], %1;" :: "r"(mbar), "r"(cnt) : "memory");
}
__device__ __forceinline__ void mbar_expect(unsigned mbar, unsigned bytes) {
    asm volatile("mbarrier.arrive.expect_tx.shared.b64 _, [%0], %1;"
                 :: "r"(mbar), "r"(bytes) : "memory");
}
__device__ __forceinline__ void bulk_g2s(unsigned dst, const void* src, unsigned bytes,
                                         unsigned mbar) {
    asm volatile("cp.async.bulk.shared::cta.global.mbarrier::complete_tx::bytes "
                 "[%0], [%1], %2, [%3];"
                 :: "r"(dst), "l"(src), "r"(bytes), "r"(mbar) : "memory");
}
__device__ __forceinline__ void mbar_wait(unsigned mbar, int phase) {
    asm volatile(
        "{\n\t.reg .pred P;\n\t"
        "W_%=:\n\t"
        "mbarrier.try_wait.parity.acquire.cta.shared::cta.b64 P, [%0], %1, 0x989680;\n\t"
        "@P bra.uni D_%=;\n\t"
        "bra.uni W_%=;\n\t"
        "D_%=:\n\t}"
        :: "r"(mbar), "r"(phase) : "memory");
}

// Merged pre-pass:
//   blocks [0,384):      Wr0..2 -> B-fragments with s_e/s_v folded in (g_wf2)
//   blocks [384,1408):   Wq/Wk/Wv/Wm -> B-fragments (g_wfn)
//   blocks [1408,6408):  ee embedding mix -> A-fragments (g_eef4)
__global__ void __launch_bounds__(256) k_wfeef(const float* __restrict__ W0,
                                               const float* __restrict__ W1,
                                               const float* __restrict__ W2,
                                               const float* __restrict__ Wq,
                                               const float* __restrict__ Wk,
                                               const float* __restrict__ Wv,
                                               const float* __restrict__ Wm,
                                               const int* __restrict__ edge_attr,
                                               const float* __restrict__ edge_embed,
                                               const float* __restrict__ emb0,
                                               const float* __restrict__ emb1,
                                               const float* __restrict__ emb2,
                                               const float* __restrict__ emb3,
                                               const float* __restrict__ init0_e,
                                               const float* __restrict__ init0) {
    __shared__ float ee_s[32 * EW_];
    __shared__ int s_attr[128];
    int tid = threadIdx.x;
    if (blockIdx.x < 384) {
        // Wr fragments, stage-contiguous, scale folded
        int idx = blockIdx.x * 256 + tid;  // 0..98303
        int lane = idx & 31;
        int kt = (idx >> 5) & 15;
        int nt = (idx >> 9) & 63;
        int m = idx >> 15;
        const float* W = (m == 0) ? W0 : ((m == 1) ? W1 : W2);
        float sc = expf((m == 2) ? init0[3] : init0[2]);
        int tg = lane & 3, gid = lane >> 2;
        float b0 = W[(kt * 8 + tg) * H_ + nt * 8 + gid] * sc;
        float b1 = W[(kt * 8 + tg + 4) * H_ + nt * 8 + gid] * sc;
        int stage = ((nt >> 3) << 1) + (kt >> 3);
        int uidx = (((stage * 3 + m) * 8 + (nt & 7)) * 8 + (kt & 7)) * 32 + lane;
        unsigned* out = (unsigned*)g_wf2;
        out[uidx * 2 + 0] = f2tf(b0);
        out[uidx * 2 + 1] = f2tf(b1);
        return;
    }
    if (blockIdx.x < 1408) {
        // Node-projection weight fragments (K=256 -> kt 0..31)
        int idx = (blockIdx.x - 384) * 256 + tid;  // 0..262143
        int lane = idx & 31;
        int kt = (idx >> 5) & 31;
        int nt = (idx >> 10) & 63;
        int m = idx >> 16;  // 0=q,1=k,2=v,3=m0
        const float* W = (m == 0) ? Wq : ((m == 1) ? Wk : ((m == 2) ? Wv : Wm));
        int tg = lane & 3, gid = lane >> 2;
        float b0 = W[(kt * 8 + tg) * H_ + nt * 8 + gid];
        float b1 = W[(kt * 8 + tg + 4) * H_ + nt * 8 + gid];
        int s = m * 8 + (nt >> 3);
        int uidx = ((s * 8 + (nt & 7)) * 32 + kt) * 32 + lane;
        unsigned* out = (unsigned*)g_wfn;
        out[uidx * 2 + 0] = f2tf(b0);
        out[uidx * 2 + 1] = f2tf(b1);
        return;
    }
    int blk = blockIdx.x - 1408;
    int e0 = blk * 32;
    if (tid < 128) s_attr[tid] = edge_attr[e0 * 4 + tid];
    float ew0 = expf(init0_e[0]), ew1 = expf(init0_e[1]);
    float ew2 = expf(init0_e[2]), ew3 = expf(init0_e[3]);
    float rs = rsqrtf(ew0 + ew1 + ew2 + ew3);
    ew0 *= rs; ew1 *= rs; ew2 *= rs; ew3 *= rs;
    __syncthreads();
    for (int idx = tid; idx < 32 * EW_; idx += 256) {
        int e = idx >> 7;
        int c = idx & (EW_ - 1);
        int a0 = s_attr[e * 4 + 0], a1 = s_attr[e * 4 + 1];
        int a2 = s_attr[e * 4 + 2], a3 = s_attr[e * 4 + 3];
        float v = emb0[a0 * EW_ + c] * ew0 + emb1[a1 * EW_ + c] * ew1 +
                  emb2[a2 * EW_ + c] * ew2 + emb3[a3 * EW_ + c] * ew3;
        ee_s[idx] = 0.5f * (v + edge_embed[(e0 + e) * EW_ + c]);
    }
    __syncthreads();
    unsigned* out = (unsigned*)g_eef4 + (size_t)blk * 4096;
    for (int idx = tid; idx < 4096; idx += 256) {
        int fb = idx >> 7;
        int w = idx & 127;
        int t = w >> 2;
        int i = w & 3;
        int let = fb >> 4;
        int kt = fb & 15;
        int er = (t >> 2) + ((i & 1) << 3);
        int col = kt * 8 + (t & 3) + ((i & 2) << 1);
        out[idx] = f2tf(ee_s[(let * 16 + er) * EW_ + col]);
    }
}

// xx = LayerNorm(x @ W_pre + b_pre), 16 nodes per block (= one A-frag tile),
// output written directly in tf32 A-fragment order to g_xxf.
__global__ void __launch_bounds__(256) k_pre(const float* __restrict__ x,
                                             const float* __restrict__ Wp,
                                             const float* __restrict__ bp) {
    const int NT = 16;
    __shared__ float xs[NT * W_];
    __shared__ float ys[NT * W_];
    __shared__ float s_mean[NT], s_rstd[NT];
    int tid = threadIdx.x;
    int n0 = blockIdx.x * NT;
    for (int idx = tid; idx < NT * W_; idx += 256) {
        int row = idx >> 8;
        xs[idx] = (n0 + row < NN) ? x[n0 * W_ + idx] : 0.f;
    }
    __syncthreads();
    float acc[NT];
#pragma unroll
    for (int i = 0; i < NT; i++) acc[i] = 0.f;
    int j = tid;
    for (int k = 0; k < W_; k++) {
        float w = Wp[k * W_ + j];
#pragma unroll
        for (int i = 0; i < NT; i++) acc[i] += xs[i * W_ + k] * w;
    }
    float bj = bp[j];
#pragma unroll
    for (int i = 0; i < NT; i++) ys[i * W_ + j] = acc[i] + bj;
    __syncthreads();
    int wid = tid >> 5, lane = tid & 31;
#pragma unroll
    for (int rr = 0; rr < 2; rr++) {
        int row = wid * 2 + rr;
        float s = 0.f;
#pragma unroll
        for (int m = 0; m < W_ / 32; m++) s += ys[row * W_ + lane + 32 * m];
#pragma unroll
        for (int off = 16; off > 0; off >>= 1) s += __shfl_xor_sync(0xffffffffu, s, off);
        float mean = s * (1.0f / W_);
        float v = 0.f;
#pragma unroll
        for (int m = 0; m < W_ / 32; m++) {
            float d = ys[row * W_ + lane + 32 * m] - mean;
            v += d * d;
        }
#pragma unroll
        for (int off = 16; off > 0; off >>= 1) v += __shfl_xor_sync(0xffffffffu, v, off);
        if (lane == 0) {
            s_mean[row] = mean;
            s_rstd[row] = rsqrtf(v * (1.0f / W_) + 1e-5f);
        }
    }
    __syncthreads();
    unsigned* out = (unsigned*)(g_xxf + (size_t)blockIdx.x * 1024);
    for (int idx = tid; idx < 4096; idx += 256) {
        int kt = idx >> 7;
        int w = idx & 127;
        int t = w >> 2;
        int i = w & 3;
        int er = (t >> 2) + ((i & 1) << 3);
        int col = kt * 8 + (t & 3) + ((i & 2) << 1);
        out[idx] = f2tf((ys[er * W_ + col] - s_mean[er]) * s_rstd[er]);
    }
}

// ---------------------------------------------------------------------------
// Tensor-core node projections: 64 nodes/block, 32 passes (4 matrices x 8
// 64-col chunks), B streamed via 2-buffer 64KB bulk copies. Also zeroes
// this block's g_agg slice (overlapped with prologue copies).
// ---------------------------------------------------------------------------
__global__ void __launch_bounds__(256, 1) k_projz(const float* __restrict__ bq,
                                                  const float* __restrict__ bk,
                                                  const float* __restrict__ bv,
                                                  const float* __restrict__ bm,
                                                  const float* __restrict__ br0,
                                                  const float* __restrict__ br1,
                                                  const float* __restrict__ br2,
                                                  const float* __restrict__ init0) {
    extern __shared__ char dsm[];
    uint4* a_sm = (uint4*)dsm;              // 4 tiles x 1024 uint4 = 64KB
    uint2* b_sm = (uint2*)(dsm + 65536);    // 2 x 8192 uint2 = 128KB
    __shared__ __align__(8) unsigned long long mbar_s[3];

    int tid = threadIdx.x;
    int lane = tid & 31, wid = tid >> 5;
    int mg = wid >> 2;        // 0..1 (32 rows each)
    int ng = wid & 3;         // 0..3 (16 cols of the 64-col chunk)
    int gid = lane >> 2, tg = lane & 3;
    int blk = blockIdx.x;

    unsigned mbA = s2u(&mbar_s[0]);
    unsigned mb0 = s2u(&mbar_s[1]);
    unsigned mb1 = s2u(&mbar_s[2]);
    if (tid == 0) {
        mbar_init(mbA, 1);
        mbar_init(mb0, 1);
        mbar_init(mb1, 1);
    }
    float s_e = expf(init0[2]);
    float s_v = expf(init0[3]);
    __syncthreads();

    if (tid == 0) {
        mbar_expect(mbA, 65536);
        bulk_g2s(s2u(a_sm), g_xxf + (size_t)blk * 4096, 65536, mbA);
        mbar_expect(mb0, 65536);
        bulk_g2s(s2u(b_sm), g_wfn, 65536, mb0);
        mbar_expect(mb1, 65536);
        bulk_g2s(s2u(b_sm + 8192), g_wfn + 8192, 65536, mb1);
    }

    // zero g_agg slice while copies are in flight
    {
        int r0 = blk * 64;
        float4 z = make_float4(0.f, 0.f, 0.f, 0.f);
        for (int i = tid; i < 64 * (H_ / 4); i += 256) {
            int r = r0 + (i >> 7);
            if (r < NN) *(float4*)(g_agg + (size_t)r * H_ + ((i & 127) << 2)) = z;
        }
    }

    const uint4* aw = a_sm + mg * 2048 + lane;
    const uint2* bw = b_sm + ng * 2048 + lane;

    mbar_wait(mbA, 0);
    int ph0 = 0, ph1 = 0;

#pragma unroll 1
    for (int s = 0; s < 32; s++) {
        int buf = s & 1;
        if (buf == 0) { mbar_wait(mb0, ph0); ph0 ^= 1; }
        else          { mbar_wait(mb1, ph1); ph1 ^= 1; }

        float acc[2][2][4];
#pragma unroll
        for (int mt = 0; mt < 2; mt++)
#pragma unroll
            for (int nt = 0; nt < 2; nt++)
#pragma unroll
                for (int c = 0; c < 4; c++) acc[mt][nt][c] = 0.f;

#pragma unroll 4
        for (int kt = 0; kt < 32; kt++) {
            uint4 av0 = aw[kt * 32];
            uint4 av1 = aw[1024 + kt * 32];
            uint2 bv0 = bw[buf * 8192 + kt * 32];
            uint2 bv1 = bw[buf * 8192 + 1024 + kt * 32];
            mma8(acc[0][0], av0, bv0);
            mma8(acc[0][1], av0, bv1);
            mma8(acc[1][0], av1, bv0);
            mma8(acc[1][1], av1, bv1);
        }
        __syncthreads();
        if (tid == 0 && s + 2 < 32) {
            if (buf == 0) { mbar_expect(mb0, 65536); bulk_g2s(s2u(b_sm), g_wfn + (size_t)(s + 2) * 8192, 65536, mb0); }
            else          { mbar_expect(mb1, 65536); bulk_g2s(s2u(b_sm + 8192), g_wfn + (size_t)(s + 2) * 8192, 65536, mb1); }
        }

        // epilogue for pass s = (m, cchunk)
        int m = s >> 3, cc = s & 7;
        const float* bmain = (m == 0) ? bq : ((m == 1) ? bk : ((m == 2) ? bv : bm));
        const float* badd  = (m == 0) ? br0 : ((m == 1) ? br1 : br2);
        float scale = (m < 2) ? s_e : s_v;
        float* dst = (m == 0) ? g_qn : ((m == 1) ? g_kn : ((m == 2) ? g_vn : g_m0));
        float2 bb[2];
#pragma unroll
        for (int nt = 0; nt < 2; nt++) {
            int col = cc * 64 + ng * 16 + nt * 8 + tg * 2;
            float2 b1 = *(const float2*)(bmain + col);
            if (m < 3) {
                float2 b2 = *(const float2*)(badd + col);
                bb[nt] = make_float2(b1.x + b2.x * scale, b1.y + b2.y * scale);
            } else {
                bb[nt] = b1;
            }
        }
#pragma unroll
        for (int mt = 0; mt < 2; mt++) {
            int r0 = blk * 64 + mg * 32 + mt * 16 + gid;
            int r1 = r0 + 8;
#pragma unroll
            for (int nt = 0; nt < 2; nt++) {
                int col = cc * 64 + ng * 16 + nt * 8 + tg * 2;
                float o00 = acc[mt][nt][0] + bb[nt].x;
                float o01 = acc[mt][nt][1] + bb[nt].y;
                float o10 = acc[mt][nt][2] + bb[nt].x;
                float o11 = acc[mt][nt][3] + bb[nt].y;
                if (m == 3) {
                    o00 = gelu_erf(o00); o01 = gelu_erf(o01);
                    o10 = gelu_erf(o10); o11 = gelu_erf(o11);
                }
                if (r0 < NN) *(float2*)(dst + (size_t)r0 * H_ + col) = make_float2(o00, o01);
                if (r1 < NN) *(float2*)(dst + (size_t)r1 * H_ + col) = make_float2(o10, o11);
            }
        }
    }
}

// ---------------------------------------------------------------------------
// Pipelined tensor-core edge kernel (scales pre-folded into weights).
// ---------------------------------------------------------------------------
__global__ void __launch_bounds__(256, 1) k_edge(const int* __restrict__ edge_index,
                                                 const float* __restrict__ init0) {
    extern __shared__ char dsm[];
    uint4* a_sm = (uint4*)dsm;              // 64KB
    uint2* b_sm = (uint2*)(dsm + 65536);    // 96KB
    __shared__ int s_src[128], s_dst[128];
    __shared__ float p_buf[4][128];
    __shared__ __align__(8) unsigned long long mbar_s[3];

    int tid = threadIdx.x;
    int lane = tid & 31, wid = tid >> 5;
    int mg = wid >> 2;
    int ng = wid & 3;
    int gid = lane >> 2, tg = lane & 3;
    int e0 = blockIdx.x * 128;

    unsigned mbA = s2u(&mbar_s[0]);
    unsigned mb0 = s2u(&mbar_s[1]);
    unsigned mb1 = s2u(&mbar_s[2]);

    if (tid < 128) {
        s_src[tid] = edge_index[e0 + tid];
        s_dst[tid] = edge_index[NE + e0 + tid];
    }
    if (tid == 0) {
        mbar_init(mbA, 1);
        mbar_init(mb0, 1);
        mbar_init(mb1, 1);
    }
    float c0 = init0[0] * 0.125f;
    float c1 = init0[1];
    __syncthreads();

    if (tid == 0) {
        mbar_expect(mbA, 65536);
        bulk_g2s(s2u(a_sm), g_eef4 + (size_t)blockIdx.x * 4096, 65536, mbA);
        mbar_expect(mb0, 49152);
        bulk_g2s(s2u(b_sm), g_wf2, 49152, mb0);
        mbar_expect(mb1, 49152);
        bulk_g2s(s2u(b_sm + 6144), g_wf2 + 6144, 49152, mb1);
    }

    int rd0[4], rd1[4], rs0[4], rs1[4];
#pragma unroll
    for (int mt = 0; mt < 4; mt++) {
        int el = mg * 64 + mt * 16 + gid;
        rd0[mt] = s_dst[el];
        rd1[mt] = s_dst[el + 8];
        rs0[mt] = s_src[el];
        rs1[mt] = s_src[el + 8];
    }

    const uint4* aw = a_sm + mg * 4 * 512 + lane;
    const uint2* bw = b_sm + ng * 512 + lane;

    mbar_wait(mbA, 0);
    int ph0 = 0, ph1 = 0;

#pragma unroll 1
    for (int chunk = 0; chunk < 8; chunk++) {
        float acc[3][4][2][4];
#pragma unroll
        for (int m = 0; m < 3; m++)
#pragma unroll
            for (int mt = 0; mt < 4; mt++)
#pragma unroll
                for (int nt = 0; nt < 2; nt++)
#pragma unroll
                    for (int c = 0; c < 4; c++) acc[m][mt][nt][c] = 0.f;

        int colbase = chunk * 64 + ng * 16 + tg * 2;

        float2 qv[4][2][2], kv[4][2][2];
#pragma unroll
        for (int mt = 0; mt < 4; mt++)
#pragma unroll
            for (int nt = 0; nt < 2; nt++) {
                int colg = colbase + nt * 8;
                qv[mt][nt][0] = *(const float2*)(g_qn + (size_t)rd0[mt] * H_ + colg);
                qv[mt][nt][1] = *(const float2*)(g_qn + (size_t)rd1[mt] * H_ + colg);
                kv[mt][nt][0] = *(const float2*)(g_kn + (size_t)rs0[mt] * H_ + colg);
                kv[mt][nt][1] = *(const float2*)(g_kn + (size_t)rs1[mt] * H_ + colg);
            }

        mbar_wait(mb0, ph0);
        ph0 ^= 1;
#pragma unroll 2
        for (int ktl = 0; ktl < 8; ktl++) {
            uint4 av4[4];
#pragma unroll
            for (int mt = 0; mt < 4; mt++) av4[mt] = aw[mt * 512 + ktl * 32];
            uint2 bv[3][2];
#pragma unroll
            for (int m = 0; m < 3; m++)
#pragma unroll
                for (int nt = 0; nt < 2; nt++)
                    bv[m][nt] = bw[m * 2048 + nt * 256 + ktl * 32];
#pragma unroll
            for (int m = 0; m < 3; m++)
#pragma unroll
                for (int mt = 0; mt < 4; mt++)
#pragma unroll
                    for (int nt = 0; nt < 2; nt++)
                        mma8(acc[m][mt][nt], av4[mt], bv[m][nt]);
        }
        __syncthreads();
        if (tid == 0 && chunk < 7) {
            mbar_expect(mb0, 49152);
            bulk_g2s(s2u(b_sm), g_wf2 + (size_t)(chunk * 2 + 2) * 6144, 49152, mb0);
        }

        float2 vv[4][2][2];
#pragma unroll
        for (int mt = 0; mt < 4; mt++)
#pragma unroll
            for (int nt = 0; nt < 2; nt++) {
                int colg = colbase + nt * 8;
                vv[mt][nt][0] = *(const float2*)(g_vn + (size_t)rs0[mt] * H_ + colg);
                vv[mt][nt][1] = *(const float2*)(g_vn + (size_t)rs1[mt] * H_ + colg);
            }

        mbar_wait(mb1, ph1);
        ph1 ^= 1;
#pragma unroll 2
        for (int ktl = 0; ktl < 8; ktl++) {
            uint4 av4[4];
#pragma unroll
            for (int mt = 0; mt < 4; mt++) av4[mt] = aw[mt * 512 + (8 + ktl) * 32];
            uint2 bv[3][2];
#pragma unroll
            for (int m = 0; m < 3; m++)
#pragma unroll
                for (int nt = 0; nt < 2; nt++)
                    bv[m][nt] = bw[6144 + m * 2048 + nt * 256 + ktl * 32];
#pragma unroll
            for (int m = 0; m < 3; m++)
#pragma unroll
                for (int mt = 0; mt < 4; mt++)
#pragma unroll
                    for (int nt = 0; nt < 2; nt++)
                        mma8(acc[m][mt][nt], av4[mt], bv[m][nt]);
        }

        float p[4][2];
#pragma unroll
        for (int mt = 0; mt < 4; mt++) { p[mt][0] = 0.f; p[mt][1] = 0.f; }
#pragma unroll
        for (int mt = 0; mt < 4; mt++)
#pragma unroll
            for (int nt = 0; nt < 2; nt++) {
                p[mt][0] += (qv[mt][nt][0].x + acc[0][mt][nt][0]) * (kv[mt][nt][0].x + acc[1][mt][nt][0])
                          + (qv[mt][nt][0].y + acc[0][mt][nt][1]) * (kv[mt][nt][0].y + acc[1][mt][nt][1]);
                p[mt][1] += (qv[mt][nt][1].x + acc[0][mt][nt][2]) * (kv[mt][nt][1].x + acc[1][mt][nt][2])
                          + (qv[mt][nt][1].y + acc[0][mt][nt][3]) * (kv[mt][nt][1].y + acc[1][mt][nt][3]);
            }
#pragma unroll
        for (int off = 1; off <= 2; off <<= 1)
#pragma unroll
            for (int mt = 0; mt < 4; mt++) {
                p[mt][0] += __shfl_xor_sync(0xffffffffu, p[mt][0], off);
                p[mt][1] += __shfl_xor_sync(0xffffffffu, p[mt][1], off);
            }
        __syncthreads();
        if (tg == 0) {
#pragma unroll
            for (int mt = 0; mt < 4; mt++) {
                int el = mg * 64 + mt * 16 + gid;
                p_buf[ng][el] = p[mt][0];
                p_buf[ng][el + 8] = p[mt][1];
            }
        }
        __syncthreads();
        if (tid == 0 && chunk < 7) {
            mbar_expect(mb1, 49152);
            bulk_g2s(s2u(b_sm + 6144), g_wf2 + (size_t)(chunk * 2 + 3) * 6144, 49152, mb1);
        }

#pragma unroll
        for (int mt = 0; mt < 4; mt++) {
            int el = mg * 64 + mt * 16 + gid;
            float sum0 = p_buf[0][el] + p_buf[1][el] + p_buf[2][el] + p_buf[3][el];
            float sum1 = p_buf[0][el + 8] + p_buf[1][el + 8] + p_buf[2][el + 8] + p_buf[3][el + 8];
            float att0 = expf(sum0 * c0 + c1);
            float att1 = expf(sum1 * c0 + c1);
#pragma unroll
            for (int nt = 0; nt < 2; nt++) {
                int colg = colbase + nt * 8;
                float xv0 = gelu_erf(vv[mt][nt][0].x + acc[2][mt][nt][0]) * att0;
                float xv1 = gelu_erf(vv[mt][nt][0].y + acc[2][mt][nt][1]) * att0;
                red2(g_agg + (size_t)rd0[mt] * H_ + colg, xv0, xv1);
                float xv2 = gelu_erf(vv[mt][nt][1].x + acc[2][mt][nt][2]) * att1;
                float xv3 = gelu_erf(vv[mt][nt][1].y + acc[2][mt][nt][3]) * att1;
                red2(g_agg + (size_t)rd1[mt] * H_ + colg, xv2, xv3);
            }
        }
    }
}

// out = x + (m0 + agg) @ W_post + b_post
__global__ void __launch_bounds__(256) k_post(const float* __restrict__ x,
                                              const float* __restrict__ Wp,
                                              const float* __restrict__ bp,
                                              float* __restrict__ out) {
    const int NT = 16;
    __shared__ float hs[NT * H_];
    int tid = threadIdx.x;
    int n0 = blockIdx.x * NT;
    for (int idx = tid; idx < NT * H_; idx += 256)
        hs[idx] = g_m0[n0 * H_ + idx] + g_agg[n0 * H_ + idx];
    __syncthreads();
    float acc[NT];
#pragma unroll
    for (int i = 0; i < NT; i++) acc[i] = 0.f;
    int j = tid;
    for (int k = 0; k < H_; k++) {
        float w = Wp[k * W_ + j];
#pragma unroll
        for (int i = 0; i < NT; i++) acc[i] += hs[i * H_ + k] * w;
    }
    float bj = bp[j];
#pragma unroll
    for (int i = 0; i < NT; i++)
        out[(n0 + i) * W_ + j] = x[(n0 + i) * W_ + j] + acc[i] + bj;
}

extern "C" void kernel_launch(void* const* d_in, const int* in_sizes, int n_in,
                              void* d_out, int out_size) {
    const float* x          = (const float*)d_in[0];
    const int*   edge_index = (const int*)d_in[1];
    const int*   edge_attr  = (const int*)d_in[2];
    const float* edge_embed = (const float*)d_in[3];
    const float* emb0       = (const float*)d_in[4];
    const float* emb1       = (const float*)d_in[5];
    const float* emb2       = (const float*)d_in[6];
    const float* emb3       = (const float*)d_in[7];
    const float* init0_e    = (const float*)d_in[8];
    const float* init0      = (const float*)d_in[9];
    const float* W_pre      = (const float*)d_in[10];
    const float* b_pre      = (const float*)d_in[11];
    const float* W_msg0     = (const float*)d_in[12];
    const float* b_msg0     = (const float*)d_in[13];
    const float* W_q        = (const float*)d_in[14];
    const float* b_q        = (const float*)d_in[15];
    const float* W_k        = (const float*)d_in[16];
    const float* b_k        = (const float*)d_in[17];
    const float* W_v        = (const float*)d_in[18];
    const float* b_v        = (const float*)d_in[19];
    const float* W_r0       = (const float*)d_in[20];
    const float* b_r0       = (const float*)d_in[21];
    const float* W_r1       = (const float*)d_in[22];
    const float* b_r1       = (const float*)d_in[23];
    const float* W_r2       = (const float*)d_in[24];
    const float* b_r2       = (const float*)d_in[25];
    const float* W_post     = (const float*)d_in[26];
    const float* b_post     = (const float*)d_in[27];
    float* out = (float*)d_out;

    cudaFuncSetAttribute(k_edge, cudaFuncAttributeMaxDynamicSharedMemorySize, 163840);
    cudaFuncSetAttribute(k_projz, cudaFuncAttributeMaxDynamicSharedMemorySize, 196608);

    k_pre<<<NP / 16, 256>>>(x, W_pre, b_pre);
    k_wfeef<<<1408 + NE / 32, 256>>>(W_r0, W_r1, W_r2, W_q, W_k, W_v, W_msg0,
                                     edge_attr, edge_embed,
                                     emb0, emb1, emb2, emb3, init0_e, init0);
    k_projz<<<NP / 64, 256, 196608>>>(b_q, b_k, b_v, b_msg0, b_r0, b_r1, b_r2, init0);
    k_edge<<<NE / 128, 256, 163840>>>(edge_index, init0);
    k_post<<<NN / 16, 256>>>(x, W_post, b_post, out);
}

// round 7
// speedup vs baseline: 3.7817x; 1.4681x over previous
#include <cuda_runtime.h>
#include <cuda_fp16.h>
#include <math.h>

#define NN 10000
#define NP 10048   // padded nodes (157 * 64)
#define NE 160000
#define W_ 256
#define H_ 512
#define EW_ 128

// Scratch (static device memory — no allocation allowed)
__device__ float g_qn[NN * H_];   // xx@Wq + bq + br0*s_e
__device__ float g_kn[NN * H_];   // xx@Wk + bk + br1*s_e
__device__ float g_vn[NN * H_];   // xx@Wv + bv + br2*s_v (pre-gelu)
__device__ float g_m0[NN * H_];   // gelu(xx@Wm + bm)
__device__ float g_agg[NN * H_];  // scatter-add target
__device__ uint4 g_eefh[NE * 16];        // ee fp16 A-frags (41MB)
__device__ uint2 g_wf2h[8 * 3 * 8 * 8 * 32];   // Wr0..2 fp16 B-frags, chunk-contiguous (384KB)
__device__ uint2 g_wfnh[4 * 64 * 16 * 32];     // Wq/Wk/Wv/Wm fp16 B-frags, stage-contiguous (1MB)
__device__ uint2 g_wfph[32 * 32 * 32];         // W_post fp16 B-frags, stage-contiguous (256KB)
__device__ uint4 g_xxfh[(NP / 16) * 16 * 32];  // LN(pre(x)) fp16 A-frags (~5MB)

__device__ __forceinline__ float gelu_erf(float h) {
    return 0.5f * h * (1.0f + erff(h * 0.70710678118654752f));
}

__device__ __forceinline__ unsigned packh(float a, float b) {
    __half2 h = __floats2half2_rn(a, b);
    return *(unsigned*)&h;
}

__device__ __forceinline__ void mma16(float* d, const uint4& a, const uint2& b) {
    asm volatile(
        "mma.sync.aligned.m16n8k16.row.col.f32.f16.f16.f32 "
        "{%0,%1,%2,%3},{%4,%5,%6,%7},{%8,%9},{%0,%1,%2,%3};"
        : "+f"(d[0]), "+f"(d[1]), "+f"(d[2]), "+f"(d[3])
        : "r"(a.x), "r"(a.y), "r"(a.z), "r"(a.w), "r"(b.x), "r"(b.y));
}

__device__ __forceinline__ void red2(float* p, float x, float y) {
    asm volatile("red.global.add.v2.f32 [%0], {%1,%2};" :: "l"(p), "f"(x), "f"(y) : "memory");
}

// ---- mbarrier + bulk-copy helpers ----
__device__ __forceinline__ unsigned s2u(const void* p) {
    return (unsigned)__cvta_generic_to_shared(p);
}
__device__ __forceinline__ void mbar_init(unsigned mbar, unsigned cnt) {
    asm volatile("mbarrier.init.shared.b64 [%0], %1;" :: "r"(mbar), "r"(cnt) : "memory");
}
__device__ __forceinline__ void mbar_expect(unsigned mbar, unsigned bytes) {
    asm volatile("mbarrier.arrive.expect_tx.shared.b64 _, [%0], %1;"
                 :: "r"(mbar), "r"(bytes) : "memory");
}
__device__ __forceinline__ void bulk_g2s(unsigned dst, const void* src, unsigned bytes,
                                         unsigned mbar) {
    asm volatile("cp.async.bulk.shared::cta.global.mbarrier::complete_tx::bytes "
                 "[%0], [%1], %2, [%3];"
                 :: "r"(dst), "l"(src), "r"(bytes), "r"(mbar) : "memory");
}
__device__ __forceinline__ void mbar_wait(unsigned mbar, int phase) {
    asm volatile(
        "{\n\t.reg .pred P;\n\t"
        "W_%=:\n\t"
        "mbarrier.try_wait.parity.acquire.cta.shared::cta.b64 P, [%0], %1, 0x989680;\n\t"
        "@P bra.uni D_%=;\n\t"
        "bra.uni W_%=;\n\t"
        "D_%=:\n\t}"
        :: "r"(mbar), "r"(phase) : "memory");
}

// ---------------------------------------------------------------------------
// Merged fragment pre-pass:
//  blocks [0,192):    Wr0..2 -> fp16 B-frags, scales folded (g_wf2h)
//  blocks [192,704):  Wq/Wk/Wv/Wm -> fp16 B-frags (g_wfnh)
//  blocks [704,832):  W_post -> fp16 B-frags (g_wfph)
//  blocks [832,5832): ee embedding mix -> fp16 A-frags (g_eefh)
// ---------------------------------------------------------------------------
__global__ void __launch_bounds__(256) k_wfeef(const float* __restrict__ W0,
                                               const float* __restrict__ W1,
                                               const float* __restrict__ W2,
                                               const float* __restrict__ Wq,
                                               const float* __restrict__ Wk,
                                               const float* __restrict__ Wv,
                                               const float* __restrict__ Wm,
                                               const float* __restrict__ Wpost,
                                               const int* __restrict__ edge_attr,
                                               const float* __restrict__ edge_embed,
                                               const float* __restrict__ emb0,
                                               const float* __restrict__ emb1,
                                               const float* __restrict__ emb2,
                                               const float* __restrict__ emb3,
                                               const float* __restrict__ init0_e,
                                               const float* __restrict__ init0) {
    __shared__ float ee_s[32 * EW_];
    __shared__ int s_attr[128];
    int tid = threadIdx.x;
    if (blockIdx.x < 192) {
        int idx = blockIdx.x * 256 + tid;        // 0..49151
        int m = idx / 16384;
        int j = idx & 16383;
        int nt = j >> 8;
        int kt = (j >> 5) & 7;
        int lane = j & 31;
        int tg = lane & 3, gid = lane >> 2;
        const float* W = (m == 0) ? W0 : ((m == 1) ? W1 : W2);
        float sc = expf((m == 2) ? init0[3] : init0[2]);
        int col = nt * 8 + gid;
        int k0 = kt * 16 + tg * 2;
        uint2 o;
        o.x = packh(W[k0 * H_ + col] * sc, W[(k0 + 1) * H_ + col] * sc);
        o.y = packh(W[(k0 + 8) * H_ + col] * sc, W[(k0 + 9) * H_ + col] * sc);
        int chunk = nt >> 3, nt8 = nt & 7;
        g_wf2h[((chunk * 3 + m) * 8 + nt8) * 256 + kt * 32 + lane] = o;
        return;
    }
    if (blockIdx.x < 704) {
        int idx = (blockIdx.x - 192) * 256 + tid;  // 0..131071
        int m = idx >> 15;
        int j = idx & 32767;
        int nt = j >> 9;
        int kt = (j >> 5) & 15;
        int lane = j & 31;
        int tg = lane & 3, gid = lane >> 2;
        const float* W = (m == 0) ? Wq : ((m == 1) ? Wk : ((m == 2) ? Wv : Wm));
        int col = nt * 8 + gid;
        int k0 = kt * 16 + tg * 2;
        uint2 o;
        o.x = packh(W[k0 * H_ + col], W[(k0 + 1) * H_ + col]);
        o.y = packh(W[(k0 + 8) * H_ + col], W[(k0 + 9) * H_ + col]);
        int s = m * 8 + (nt >> 3);
        g_wfnh[((s * 8 + (nt & 7)) * 16 + kt) * 32 + lane] = o;
        return;
    }
    if (blockIdx.x < 832) {
        int idx = (blockIdx.x - 704) * 256 + tid;  // 0..32767
        int nt = idx >> 10;
        int kt = (idx >> 5) & 31;
        int lane = idx & 31;
        int tg = lane & 3, gid = lane >> 2;
        int col = nt * 8 + gid;
        int k0 = kt * 16 + tg * 2;
        uint2 o;
        o.x = packh(Wpost[k0 * W_ + col], Wpost[(k0 + 1) * W_ + col]);
        o.y = packh(Wpost[(k0 + 8) * W_ + col], Wpost[(k0 + 9) * W_ + col]);
        int stage = nt >> 3;
        g_wfph[((stage * 8 + (nt & 7)) * 32 + kt) * 32 + lane] = o;
        return;
    }
    int blk = blockIdx.x - 832;
    int e0 = blk * 32;
    if (tid < 128) s_attr[tid] = edge_attr[e0 * 4 + tid];
    float ew0 = expf(init0_e[0]), ew1 = expf(init0_e[1]);
    float ew2 = expf(init0_e[2]), ew3 = expf(init0_e[3]);
    float rs = rsqrtf(ew0 + ew1 + ew2 + ew3);
    ew0 *= rs; ew1 *= rs; ew2 *= rs; ew3 *= rs;
    __syncthreads();
    for (int idx = tid; idx < 32 * EW_; idx += 256) {
        int e = idx >> 7;
        int c = idx & (EW_ - 1);
        int a0 = s_attr[e * 4 + 0], a1 = s_attr[e * 4 + 1];
        int a2 = s_attr[e * 4 + 2], a3 = s_attr[e * 4 + 3];
        float v = emb0[a0 * EW_ + c] * ew0 + emb1[a1 * EW_ + c] * ew1 +
                  emb2[a2 * EW_ + c] * ew2 + emb3[a3 * EW_ + c] * ew3;
        ee_s[idx] = 0.5f * (v + edge_embed[(e0 + e) * EW_ + c]);
    }
    __syncthreads();
    unsigned* out = (unsigned*)(g_eefh + (size_t)blk * 512);
    for (int idx = tid; idx < 2048; idx += 256) {
        int i = idx & 3;
        int t = (idx >> 2) & 31;
        int kt = (idx >> 7) & 7;
        int let = idx >> 10;
        int er = (t >> 2) + ((i & 1) << 3);
        int kc = kt * 16 + (t & 3) * 2 + ((i >> 1) << 3);
        out[idx] = packh(ee_s[(let * 16 + er) * EW_ + kc],
                         ee_s[(let * 16 + er) * EW_ + kc + 1]);
    }
}

// xx = LayerNorm(x @ W_pre + b_pre), 16 nodes/block, output as fp16 A-frags.
__global__ void __launch_bounds__(256) k_pre(const float* __restrict__ x,
                                             const float* __restrict__ Wp,
                                             const float* __restrict__ bp) {
    const int NT = 16;
    __shared__ float xs[NT * W_];
    __shared__ float ys[NT * W_];
    __shared__ float s_mean[NT], s_rstd[NT];
    int tid = threadIdx.x;
    int n0 = blockIdx.x * NT;
    for (int idx = tid; idx < NT * W_; idx += 256) {
        int row = idx >> 8;
        xs[idx] = (n0 + row < NN) ? x[n0 * W_ + idx] : 0.f;
    }
    __syncthreads();
    float acc[NT];
#pragma unroll
    for (int i = 0; i < NT; i++) acc[i] = 0.f;
    int j = tid;
    for (int k = 0; k < W_; k++) {
        float w = Wp[k * W_ + j];
#pragma unroll
        for (int i = 0; i < NT; i++) acc[i] += xs[i * W_ + k] * w;
    }
    float bj = bp[j];
#pragma unroll
    for (int i = 0; i < NT; i++) ys[i * W_ + j] = acc[i] + bj;
    __syncthreads();
    int wid = tid >> 5, lane = tid & 31;
#pragma unroll
    for (int rr = 0; rr < 2; rr++) {
        int row = wid * 2 + rr;
        float s = 0.f;
#pragma unroll
        for (int m = 0; m < W_ / 32; m++) s += ys[row * W_ + lane + 32 * m];
#pragma unroll
        for (int off = 16; off > 0; off >>= 1) s += __shfl_xor_sync(0xffffffffu, s, off);
        float mean = s * (1.0f / W_);
        float v = 0.f;
#pragma unroll
        for (int m = 0; m < W_ / 32; m++) {
            float d = ys[row * W_ + lane + 32 * m] - mean;
            v += d * d;
        }
#pragma unroll
        for (int off = 16; off > 0; off >>= 1) v += __shfl_xor_sync(0xffffffffu, v, off);
        if (lane == 0) {
            s_mean[row] = mean;
            s_rstd[row] = rsqrtf(v * (1.0f / W_) + 1e-5f);
        }
    }
    __syncthreads();
    unsigned* out = (unsigned*)(g_xxfh + (size_t)blockIdx.x * 512);
    for (int idx = tid; idx < 2048; idx += 256) {
        int i = idx & 3;
        int t = (idx >> 2) & 31;
        int kt = idx >> 7;  // 0..15
        int er = (t >> 2) + ((i & 1) << 3);
        int kc = kt * 16 + (t & 3) * 2 + ((i >> 1) << 3);
        float f0 = (ys[er * W_ + kc] - s_mean[er]) * s_rstd[er];
        float f1 = (ys[er * W_ + kc + 1] - s_mean[er]) * s_rstd[er];
        out[idx] = packh(f0, f1);
    }
}

// ---------------------------------------------------------------------------
// fp16 tensor-core node projections: 64 nodes/block, 32 passes.
// A resident 32KB; B streamed via 2x32KB bulk ring. 2 blocks/SM.
// ---------------------------------------------------------------------------
__global__ void __launch_bounds__(256, 2) k_projz(const float* __restrict__ bq,
                                                  const float* __restrict__ bk,
                                                  const float* __restrict__ bv,
                                                  const float* __restrict__ bm,
                                                  const float* __restrict__ br0,
                                                  const float* __restrict__ br1,
                                                  const float* __restrict__ br2,
                                                  const float* __restrict__ init0) {
    extern __shared__ char dsm[];
    uint4* a_sm = (uint4*)dsm;               // [4mt][16kt][32lane] = 32KB
    uint2* b_sm = (uint2*)(dsm + 32768);     // 2 x 4096 uint2 = 64KB
    __shared__ __align__(8) unsigned long long mbar_s[3];

    int tid = threadIdx.x;
    int lane = tid & 31, wid = tid >> 5;
    int mg = wid >> 2;        // 0..1
    int ng = wid & 3;         // 0..3
    int gid = lane >> 2, tg = lane & 3;
    int blk = blockIdx.x;

    unsigned mbA = s2u(&mbar_s[0]);
    unsigned mb0 = s2u(&mbar_s[1]);
    unsigned mb1 = s2u(&mbar_s[2]);
    if (tid == 0) {
        mbar_init(mbA, 1);
        mbar_init(mb0, 1);
        mbar_init(mb1, 1);
    }
    float s_e = expf(init0[2]);
    float s_v = expf(init0[3]);
    __syncthreads();

    if (tid == 0) {
        mbar_expect(mbA, 32768);
        bulk_g2s(s2u(a_sm), g_xxfh + (size_t)blk * 2048, 32768, mbA);
        mbar_expect(mb0, 32768);
        bulk_g2s(s2u(b_sm), g_wfnh, 32768, mb0);
        mbar_expect(mb1, 32768);
        bulk_g2s(s2u(b_sm + 4096), g_wfnh + 4096, 32768, mb1);
    }

    // zero g_agg slice while copies are in flight
    {
        int r0 = blk * 64;
        float4 z = make_float4(0.f, 0.f, 0.f, 0.f);
        for (int i = tid; i < 64 * (H_ / 4); i += 256) {
            int r = r0 + (i >> 7);
            if (r < NN) *(float4*)(g_agg + (size_t)r * H_ + ((i & 127) << 2)) = z;
        }
    }

    const uint4* aw = a_sm + mg * 1024 + lane;        // mt stride 512
    const uint2* bw = b_sm + (ng * 2) * 512 + lane;   // nt stride 512

    mbar_wait(mbA, 0);
    int ph0 = 0, ph1 = 0;

#pragma unroll 1
    for (int s = 0; s < 32; s++) {
        int buf = s & 1;
        if (buf == 0) { mbar_wait(mb0, ph0); ph0 ^= 1; }
        else          { mbar_wait(mb1, ph1); ph1 ^= 1; }

        float acc[2][2][4];
#pragma unroll
        for (int mt = 0; mt < 2; mt++)
#pragma unroll
            for (int nt = 0; nt < 2; nt++)
#pragma unroll
                for (int c = 0; c < 4; c++) acc[mt][nt][c] = 0.f;

#pragma unroll 4
        for (int kt = 0; kt < 16; kt++) {
            uint4 av0 = aw[kt * 32];
            uint4 av1 = aw[512 + kt * 32];
            uint2 bv0 = bw[buf * 4096 + kt * 32];
            uint2 bv1 = bw[buf * 4096 + 512 + kt * 32];
            mma16(acc[0][0], av0, bv0);
            mma16(acc[0][1], av0, bv1);
            mma16(acc[1][0], av1, bv0);
            mma16(acc[1][1], av1, bv1);
        }
        __syncthreads();
        if (tid == 0 && s + 2 < 32) {
            if (buf == 0) { mbar_expect(mb0, 32768); bulk_g2s(s2u(b_sm), g_wfnh + (size_t)(s + 2) * 4096, 32768, mb0); }
            else          { mbar_expect(mb1, 32768); bulk_g2s(s2u(b_sm + 4096), g_wfnh + (size_t)(s + 2) * 4096, 32768, mb1); }
        }

        int m = s >> 3, cc = s & 7;
        const float* bmain = (m == 0) ? bq : ((m == 1) ? bk : ((m == 2) ? bv : bm));
        const float* badd  = (m == 0) ? br0 : ((m == 1) ? br1 : br2);
        float scale = (m < 2) ? s_e : s_v;
        float* dst = (m == 0) ? g_qn : ((m == 1) ? g_kn : ((m == 2) ? g_vn : g_m0));
        float2 bb[2];
#pragma unroll
        for (int nt = 0; nt < 2; nt++) {
            int col = cc * 64 + ng * 16 + nt * 8 + tg * 2;
            float2 b1 = *(const float2*)(bmain + col);
            if (m < 3) {
                float2 b2 = *(const float2*)(badd + col);
                bb[nt] = make_float2(b1.x + b2.x * scale, b1.y + b2.y * scale);
            } else {
                bb[nt] = b1;
            }
        }
#pragma unroll
        for (int mt = 0; mt < 2; mt++) {
            int r0 = blk * 64 + mg * 32 + mt * 16 + gid;
            int r1 = r0 + 8;
#pragma unroll
            for (int nt = 0; nt < 2; nt++) {
                int col = cc * 64 + ng * 16 + nt * 8 + tg * 2;
                float o00 = acc[mt][nt][0] + bb[nt].x;
                float o01 = acc[mt][nt][1] + bb[nt].y;
                float o10 = acc[mt][nt][2] + bb[nt].x;
                float o11 = acc[mt][nt][3] + bb[nt].y;
                if (m == 3) {
                    o00 = gelu_erf(o00); o01 = gelu_erf(o01);
                    o10 = gelu_erf(o10); o11 = gelu_erf(o11);
                }
                if (r0 < NN) *(float2*)(dst + (size_t)r0 * H_ + col) = make_float2(o00, o01);
                if (r1 < NN) *(float2*)(dst + (size_t)r1 * H_ + col) = make_float2(o10, o11);
            }
        }
    }
}

// ---------------------------------------------------------------------------
// fp16 tensor-core edge kernel: 128 edges/block, 512 threads = 16 warps
// (4 mg x 4 ng). A resident 32KB; B streamed 2x48KB ring (stage = chunk).
// ---------------------------------------------------------------------------
__global__ void __launch_bounds__(512) k_edge(const int* __restrict__ edge_index,
                                              const float* __restrict__ init0) {
    extern __shared__ char dsm[];
    uint4* a_sm = (uint4*)dsm;               // [8mt][8kt][32lane] = 32KB
    uint2* b_sm = (uint2*)(dsm + 32768);     // 2 x 6144 uint2 = 96KB
    __shared__ int s_src[128], s_dst[128];
    __shared__ float p_buf[4][128];
    __shared__ __align__(8) unsigned long long mbar_s[3];

    int tid = threadIdx.x;
    int lane = tid & 31, wid = tid >> 5;
    int mg = wid >> 2;        // 0..3 (32 edges each)
    int ng = wid & 3;         // 0..3 (16 cols)
    int gid = lane >> 2, tg = lane & 3;
    int e0 = blockIdx.x * 128;

    unsigned mbA = s2u(&mbar_s[0]);
    unsigned mb0 = s2u(&mbar_s[1]);
    unsigned mb1 = s2u(&mbar_s[2]);

    if (tid < 128) {
        s_src[tid] = edge_index[e0 + tid];
        s_dst[tid] = edge_index[NE + e0 + tid];
    }
    if (tid == 0) {
        mbar_init(mbA, 1);
        mbar_init(mb0, 1);
        mbar_init(mb1, 1);
    }
    float c0 = init0[0] * 0.125f;
    float c1 = init0[1];
    __syncthreads();

    if (tid == 0) {
        mbar_expect(mbA, 32768);
        bulk_g2s(s2u(a_sm), g_eefh + (size_t)blockIdx.x * 2048, 32768, mbA);
        mbar_expect(mb0, 49152);
        bulk_g2s(s2u(b_sm), g_wf2h, 49152, mb0);
        mbar_expect(mb1, 49152);
        bulk_g2s(s2u(b_sm + 6144), g_wf2h + 6144, 49152, mb1);
    }

    int rd0[2], rd1[2], rs0[2], rs1[2];
#pragma unroll
    for (int mt = 0; mt < 2; mt++) {
        int el = mg * 32 + mt * 16 + gid;
        rd0[mt] = s_dst[el];
        rd1[mt] = s_dst[el + 8];
        rs0[mt] = s_src[el];
        rs1[mt] = s_src[el + 8];
    }

    const uint4* aw = a_sm + mg * 512 + lane;          // mt stride 256
    const uint2* bw = b_sm + (ng * 2) * 256 + lane;    // nt8 stride 256

    mbar_wait(mbA, 0);
    int ph0 = 0, ph1 = 0;

#pragma unroll 1
    for (int chunk = 0; chunk < 8; chunk++) {
        float acc[3][2][2][4];
#pragma unroll
        for (int m = 0; m < 3; m++)
#pragma unroll
            for (int mt = 0; mt < 2; mt++)
#pragma unroll
                for (int nt = 0; nt < 2; nt++)
#pragma unroll
                    for (int c = 0; c < 4; c++) acc[m][mt][nt][c] = 0.f;

        int colbase = chunk * 64 + ng * 16 + tg * 2;
        int bufbase = (chunk & 1) * 6144;

        // prefetch q/k gathers
        float2 qv[2][2][2], kv[2][2][2];
#pragma unroll
        for (int mt = 0; mt < 2; mt++)
#pragma unroll
            for (int nt = 0; nt < 2; nt++) {
                int colg = colbase + nt * 8;
                qv[mt][nt][0] = *(const float2*)(g_qn + (size_t)rd0[mt] * H_ + colg);
                qv[mt][nt][1] = *(const float2*)(g_qn + (size_t)rd1[mt] * H_ + colg);
                kv[mt][nt][0] = *(const float2*)(g_kn + (size_t)rs0[mt] * H_ + colg);
                kv[mt][nt][1] = *(const float2*)(g_kn + (size_t)rs1[mt] * H_ + colg);
            }

        if ((chunk & 1) == 0) { mbar_wait(mb0, ph0); ph0 ^= 1; }
        else                  { mbar_wait(mb1, ph1); ph1 ^= 1; }

#pragma unroll
        for (int kt = 0; kt < 4; kt++) {
            uint4 av0 = aw[kt * 32];
            uint4 av1 = aw[256 + kt * 32];
            uint2 bv[3][2];
#pragma unroll
            for (int m = 0; m < 3; m++)
#pragma unroll
                for (int nt = 0; nt < 2; nt++)
                    bv[m][nt] = bw[bufbase + (m * 8 + nt) * 256 + kt * 32];
#pragma unroll
            for (int m = 0; m < 3; m++)
#pragma unroll
                for (int nt = 0; nt < 2; nt++) {
                    mma16(acc[m][0][nt], av0, bv[m][nt]);
                    mma16(acc[m][1][nt], av1, bv[m][nt]);
                }
        }

        // prefetch v gathers (hide under second mma half)
        float2 vv[2][2][2];
#pragma unroll
        for (int mt = 0; mt < 2; mt++)
#pragma unroll
            for (int nt = 0; nt < 2; nt++) {
                int colg = colbase + nt * 8;
                vv[mt][nt][0] = *(const float2*)(g_vn + (size_t)rs0[mt] * H_ + colg);
                vv[mt][nt][1] = *(const float2*)(g_vn + (size_t)rs1[mt] * H_ + colg);
            }

#pragma unroll
        for (int kt = 4; kt < 8; kt++) {
            uint4 av0 = aw[kt * 32];
            uint4 av1 = aw[256 + kt * 32];
            uint2 bv[3][2];
#pragma unroll
            for (int m = 0; m < 3; m++)
#pragma unroll
                for (int nt = 0; nt < 2; nt++)
                    bv[m][nt] = bw[bufbase + (m * 8 + nt) * 256 + kt * 32];
#pragma unroll
            for (int m = 0; m < 3; m++)
#pragma unroll
                for (int nt = 0; nt < 2; nt++) {
                    mma16(acc[m][0][nt], av0, bv[m][nt]);
                    mma16(acc[m][1][nt], av1, bv[m][nt]);
                }
        }

        // attention partial dots
        float p[2][2];
        p[0][0] = p[0][1] = p[1][0] = p[1][1] = 0.f;
#pragma unroll
        for (int mt = 0; mt < 2; mt++)
#pragma unroll
            for (int nt = 0; nt < 2; nt++) {
                p[mt][0] += (qv[mt][nt][0].x + acc[0][mt][nt][0]) * (kv[mt][nt][0].x + acc[1][mt][nt][0])
                          + (qv[mt][nt][0].y + acc[0][mt][nt][1]) * (kv[mt][nt][0].y + acc[1][mt][nt][1]);
                p[mt][1] += (qv[mt][nt][1].x + acc[0][mt][nt][2]) * (kv[mt][nt][1].x + acc[1][mt][nt][2])
                          + (qv[mt][nt][1].y + acc[0][mt][nt][3]) * (kv[mt][nt][1].y + acc[1][mt][nt][3]);
            }
#pragma unroll
        for (int off = 1; off <= 2; off <<= 1) {
            p[0][0] += __shfl_xor_sync(0xffffffffu, p[0][0], off);
            p[0][1] += __shfl_xor_sync(0xffffffffu, p[0][1], off);
            p[1][0] += __shfl_xor_sync(0xffffffffu, p[1][0], off);
            p[1][1] += __shfl_xor_sync(0xffffffffu, p[1][1], off);
        }
        __syncthreads();   // all warps done with this chunk's B buf + prev p_buf
        if (tg == 0) {
#pragma unroll
            for (int mt = 0; mt < 2; mt++) {
                int el = mg * 32 + mt * 16 + gid;
                p_buf[ng][el] = p[mt][0];
                p_buf[ng][el + 8] = p[mt][1];
            }
        }
        __syncthreads();
        if (tid == 0 && chunk < 6) {
            if ((chunk & 1) == 0) { mbar_expect(mb0, 49152); bulk_g2s(s2u(b_sm), g_wf2h + (size_t)(chunk + 2) * 6144, 49152, mb0); }
            else                  { mbar_expect(mb1, 49152); bulk_g2s(s2u(b_sm + 6144), g_wf2h + (size_t)(chunk + 2) * 6144, 49152, mb1); }
        }

        // V epilogue
#pragma unroll
        for (int mt = 0; mt < 2; mt++) {
            int el = mg * 32 + mt * 16 + gid;
            float sum0 = p_buf[0][el] + p_buf[1][el] + p_buf[2][el] + p_buf[3][el];
            float sum1 = p_buf[0][el + 8] + p_buf[1][el + 8] + p_buf[2][el + 8] + p_buf[3][el + 8];
            float att0 = expf(sum0 * c0 + c1);
            float att1 = expf(sum1 * c0 + c1);
#pragma unroll
            for (int nt = 0; nt < 2; nt++) {
                int colg = colbase + nt * 8;
                float xv0 = gelu_erf(vv[mt][nt][0].x + acc[2][mt][nt][0]) * att0;
                float xv1 = gelu_erf(vv[mt][nt][0].y + acc[2][mt][nt][1]) * att0;
                red2(g_agg + (size_t)rd0[mt] * H_ + colg, xv0, xv1);
                float xv2 = gelu_erf(vv[mt][nt][1].x + acc[2][mt][nt][2]) * att1;
                float xv3 = gelu_erf(vv[mt][nt][1].y + acc[2][mt][nt][3]) * att1;
                red2(g_agg + (size_t)rd1[mt] * H_ + colg, xv2, xv3);
            }
        }
    }
}

// ---------------------------------------------------------------------------
// fp16 tensor-core post kernel: out = x + (m0+agg) @ W_post + b_post.
// 64 nodes/block; A frags built in-kernel (64KB smem); B 2x64KB bulk ring.
// ---------------------------------------------------------------------------
__global__ void __launch_bounds__(256) k_post(const float* __restrict__ x,
                                              const float* __restrict__ bp,
                                              float* __restrict__ out) {
    extern __shared__ char dsm[];
    uint4* a_sm = (uint4*)dsm;               // [4mt][32kt][32lane] = 64KB
    uint2* b_sm = (uint2*)(dsm + 65536);     // 2 x 8192 uint2 = 128KB
    __shared__ __align__(8) unsigned long long mbar_s[2];

    int tid = threadIdx.x;
    int lane = tid & 31, wid = tid >> 5;
    int mg = wid >> 2;        // 0..1
    int ng = wid & 3;         // 0..3
    int gid = lane >> 2, tg = lane & 3;
    int blk = blockIdx.x;

    unsigned mb0 = s2u(&mbar_s[0]);
    unsigned mb1 = s2u(&mbar_s[1]);
    if (tid == 0) {
        mbar_init(mb0, 1);
        mbar_init(mb1, 1);
    }
    __syncthreads();
    if (tid == 0) {
        mbar_expect(mb0, 65536);
        bulk_g2s(s2u(b_sm), g_wfph, 65536, mb0);
        mbar_expect(mb1, 65536);
        bulk_g2s(s2u(b_sm + 8192), g_wfph + 8192, 65536, mb1);
    }

    // build A fragments from m0 + agg
    {
        unsigned* aword = (unsigned*)a_sm;
        for (int widx = tid; widx < 16384; widx += 256) {
            int i = widx & 3;
            int t = (widx >> 2) & 31;
            int kt = (widx >> 7) & 31;
            int mt = widx >> 12;
            int er = (t >> 2) + ((i & 1) << 3);
            int row = blk * 64 + mt * 16 + er;
            int kc = kt * 16 + (t & 3) * 2 + ((i >> 1) << 3);
            float f0 = 0.f, f1 = 0.f;
            if (row < NN) {
                float2 m2 = *(const float2*)(g_m0 + (size_t)row * H_ + kc);
                float2 a2 = *(const float2*)(g_agg + (size_t)row * H_ + kc);
                f0 = m2.x + a2.x;
                f1 = m2.y + a2.y;
            }
            aword[widx] = packh(f0, f1);
        }
    }
    __syncthreads();

    const uint4* aw = a_sm + mg * 2048 + lane;        // mt stride 1024
    const uint2* bw = b_sm + (ng * 2) * 1024 + lane;  // nt stride 1024
    int ph0 = 0, ph1 = 0;

#pragma unroll 1
    for (int s = 0; s < 4; s++) {
        int buf = s & 1;
        if (buf == 0) { mbar_wait(mb0, ph0); ph0 ^= 1; }
        else          { mbar_wait(mb1, ph1); ph1 ^= 1; }

        float acc[2][2][4];
#pragma unroll
        for (int mt = 0; mt < 2; mt++)
#pragma unroll
            for (int nt = 0; nt < 2; nt++)
#pragma unroll
                for (int c = 0; c < 4; c++) acc[mt][nt][c] = 0.f;

#pragma unroll 4
        for (int kt = 0; kt < 32; kt++) {
            uint4 av0 = aw[kt * 32];
            uint4 av1 = aw[1024 + kt * 32];
            uint2 bv0 = bw[buf * 8192 + kt * 32];
            uint2 bv1 = bw[buf * 8192 + 1024 + kt * 32];
            mma16(acc[0][0], av0, bv0);
            mma16(acc[0][1], av0, bv1);
            mma16(acc[1][0], av1, bv0);
            mma16(acc[1][1], av1, bv1);
        }
        __syncthreads();
        if (tid == 0 && s + 2 < 4) {
            if (buf == 0) { mbar_expect(mb0, 65536); bulk_g2s(s2u(b_sm), g_wfph + (size_t)(s + 2) * 8192, 65536, mb0); }
            else          { mbar_expect(mb1, 65536); bulk_g2s(s2u(b_sm + 8192), g_wfph + (size_t)(s + 2) * 8192, 65536, mb1); }
        }

#pragma unroll
        for (int mt = 0; mt < 2; mt++) {
            int r0 = blk * 64 + mg * 32 + mt * 16 + gid;
            int r1 = r0 + 8;
#pragma unroll
            for (int nt = 0; nt < 2; nt++) {
                int col = s * 64 + ng * 16 + nt * 8 + tg * 2;
                float2 bb = *(const float2*)(bp + col);
                if (r0 < NN) {
                    float2 xx0 = *(const float2*)(x + (size_t)r0 * W_ + col);
                    *(float2*)(out + (size_t)r0 * W_ + col) =
                        make_float2(xx0.x + acc[mt][nt][0] + bb.x, xx0.y + acc[mt][nt][1] + bb.y);
                }
                if (r1 < NN) {
                    float2 xx1 = *(const float2*)(x + (size_t)r1 * W_ + col);
                    *(float2*)(out + (size_t)r1 * W_ + col) =
                        make_float2(xx1.x + acc[mt][nt][2] + bb.x, xx1.y + acc[mt][nt][3] + bb.y);
                }
            }
        }
    }
}

extern "C" void kernel_launch(void* const* d_in, const int* in_sizes, int n_in,
                              void* d_out, int out_size) {
    const float* x          = (const float*)d_in[0];
    const int*   edge_index = (const int*)d_in[1];
    const int*   edge_attr  = (const int*)d_in[2];
    const float* edge_embed = (const float*)d_in[3];
    const float* emb0       = (const float*)d_in[4];
    const float* emb1       = (const float*)d_in[5];
    const float* emb2       = (const float*)d_in[6];
    const float* emb3       = (const float*)d_in[7];
    const float* init0_e    = (const float*)d_in[8];
    const float* init0      = (const float*)d_in[9];
    const float* W_pre      = (const float*)d_in[10];
    const float* b_pre      = (const float*)d_in[11];
    const float* W_msg0     = (const float*)d_in[12];
    const float* b_msg0     = (const float*)d_in[13];
    const float* W_q        = (const float*)d_in[14];
    const float* b_q        = (const float*)d_in[15];
    const float* W_k        = (const float*)d_in[16];
    const float* b_k        = (const float*)d_in[17];
    const float* W_v        = (const float*)d_in[18];
    const float* b_v        = (const float*)d_in[19];
    const float* W_r0       = (const float*)d_in[20];
    const float* b_r0       = (const float*)d_in[21];
    const float* W_r1       = (const float*)d_in[22];
    const float* b_r1       = (const float*)d_in[23];
    const float* W_r2       = (const float*)d_in[24];
    const float* b_r2       = (const float*)d_in[25];
    const float* W_post     = (const float*)d_in[26];
    const float* b_post     = (const float*)d_in[27];
    float* out = (float*)d_out;

    cudaFuncSetAttribute(k_edge, cudaFuncAttributeMaxDynamicSharedMemorySize, 131072);
    cudaFuncSetAttribute(k_projz, cudaFuncAttributeMaxDynamicSharedMemorySize, 98304);
    cudaFuncSetAttribute(k_post, cudaFuncAttributeMaxDynamicSharedMemorySize, 196608);

    k_pre<<<NP / 16, 256>>>(x, W_pre, b_pre);
    k_wfeef<<<832 + NE / 32, 256>>>(W_r0, W_r1, W_r2, W_q, W_k, W_v, W_msg0, W_post,
                                    edge_attr, edge_embed,
                                    emb0, emb1, emb2, emb3, init0_e, init0);
    k_projz<<<NP / 64, 256, 98304>>>(b_q, b_k, b_v, b_msg0, b_r0, b_r1, b_r2, init0);
    k_edge<<<NE / 128, 512, 131072>>>(edge_index, init0);
    k_post<<<NP / 64, 256, 196608>>>(x, b_post, out);
}

// round 8
// speedup vs baseline: 4.1079x; 1.0862x over previous
#include <cuda_runtime.h>
#include <cuda_fp16.h>
#include <math.h>

#define NN 10000
#define NP 10048   // padded nodes (157 * 64)
#define NE 160000
#define W_ 256
#define H_ 512
#define EW_ 128

// Scratch (static device memory — no allocation allowed)
__device__ float g_qn[NN * H_];
__device__ float g_kn[NN * H_];
__device__ float g_vn[NN * H_];
__device__ float g_m0[NN * H_];
__device__ float g_agg[NN * H_];
__device__ uint4 g_eefh[NE * 16];              // ee fp16 A-frags
__device__ uint2 g_wf2h[8 * 3 * 8 * 8 * 32];   // Wr0..2 fp16 B-frags (perm cols, scales folded)
__device__ uint2 g_wfnh[4 * 64 * 16 * 32];     // Wq/Wk/Wv/Wm fp16 B-frags (perm cols)
__device__ uint2 g_wfph[32 * 32 * 32];         // W_post fp16 B-frags (perm cols)
__device__ uint4 g_xxfh[(NP / 16) * 16 * 32];  // LN(pre(x)) fp16 A-frags

__device__ __forceinline__ float gelu_erf(float h) {
    return 0.5f * h * (1.0f + erff(h * 0.70710678118654752f));
}

__device__ __forceinline__ unsigned packh(float a, float b) {
    __half2 h = __floats2half2_rn(a, b);
    return *(unsigned*)&h;
}

__device__ __forceinline__ void mma16(float* d, const uint4& a, const uint2& b) {
    asm volatile(
        "mma.sync.aligned.m16n8k16.row.col.f32.f16.f16.f32 "
        "{%0,%1,%2,%3},{%4,%5,%6,%7},{%8,%9},{%0,%1,%2,%3};"
        : "+f"(d[0]), "+f"(d[1]), "+f"(d[2]), "+f"(d[3])
        : "r"(a.x), "r"(a.y), "r"(a.z), "r"(a.w), "r"(b.x), "r"(b.y));
}

__device__ __forceinline__ void red4(float* p, float a, float b, float c, float d) {
    asm volatile("red.global.add.v4.f32 [%0], {%1,%2,%3,%4};"
                 :: "l"(p), "f"(a), "f"(b), "f"(c), "f"(d) : "memory");
}

// ---- mbarrier + bulk-copy helpers ----
__device__ __forceinline__ unsigned s2u(const void* p) {
    return (unsigned)__cvta_generic_to_shared(p);
}
__device__ __forceinline__ void mbar_init(unsigned mbar, unsigned cnt) {
    asm volatile("mbarrier.init.shared.b64 [%0], %1;" :: "r"(mbar), "r"(cnt) : "memory");
}
__device__ __forceinline__ void mbar_expect(unsigned mbar, unsigned bytes) {
    asm volatile("mbarrier.arrive.expect_tx.shared.b64 _, [%0], %1;"
                 :: "r"(mbar), "r"(bytes) : "memory");
}
__device__ __forceinline__ void bulk_g2s(unsigned dst, const void* src, unsigned bytes,
                                         unsigned mbar) {
    asm volatile("cp.async.bulk.shared::cta.global.mbarrier::complete_tx::bytes "
                 "[%0], [%1], %2, [%3];"
                 :: "r"(dst), "l"(src), "r"(bytes), "r"(mbar) : "memory");
}
__device__ __forceinline__ void mbar_wait(unsigned mbar, int phase) {
    asm volatile(
        "{\n\t.reg .pred P;\n\t"
        "W_%=:\n\t"
        "mbarrier.try_wait.parity.acquire.cta.shared::cta.b64 P, [%0], %1, 0x989680;\n\t"
        "@P bra.uni D_%=;\n\t"
        "bra.uni W_%=;\n\t"
        "D_%=:\n\t}"
        :: "r"(mbar), "r"(phase) : "memory");
}

// permuted physical column within a 16-col group: thread tg owns 4 consecutive cols
__device__ __forceinline__ int permcol(int nt, int gid) {
    return (nt >> 1) * 16 + (gid >> 1) * 4 + (nt & 1) * 2 + (gid & 1);
}

// ---------------------------------------------------------------------------
// Merged pre-pass (one launch, independent segments):
//  [0,628):        k_pre  — LayerNorm(x@W_pre+b_pre) -> fp16 A-frags
//  [628,820):      Wr0..2 -> fp16 B-frags (permuted cols, scales folded)
//  [820,1332):     Wq/Wk/Wv/Wm -> fp16 B-frags (permuted cols)
//  [1332,1460):    W_post -> fp16 B-frags (permuted cols)
//  [1460,6460):    ee embedding mix -> fp16 A-frags
// ---------------------------------------------------------------------------
__global__ void __launch_bounds__(256) k_wfeef(const float* __restrict__ x,
                                               const float* __restrict__ Wpre,
                                               const float* __restrict__ bpre,
                                               const float* __restrict__ W0,
                                               const float* __restrict__ W1,
                                               const float* __restrict__ W2,
                                               const float* __restrict__ Wq,
                                               const float* __restrict__ Wk,
                                               const float* __restrict__ Wv,
                                               const float* __restrict__ Wm,
                                               const float* __restrict__ Wpost,
                                               const int* __restrict__ edge_attr,
                                               const float* __restrict__ edge_embed,
                                               const float* __restrict__ emb0,
                                               const float* __restrict__ emb1,
                                               const float* __restrict__ emb2,
                                               const float* __restrict__ emb3,
                                               const float* __restrict__ init0_e,
                                               const float* __restrict__ init0) {
    __shared__ float sbuf[8192];   // 32KB union: pre uses all; eefh uses first 16KB
    __shared__ int s_attr[128];
    __shared__ float s_mean[16], s_rstd[16];
    int tid = threadIdx.x;
    int b = blockIdx.x;

    if (b < 628) {
        // ---- k_pre segment ----
        const int NT = 16;
        float* xs = sbuf;
        float* ys = sbuf + 4096;
        int n0 = b * NT;
        for (int idx = tid; idx < NT * W_; idx += 256) {
            int row = idx >> 8;
            xs[idx] = (n0 + row < NN) ? x[n0 * W_ + idx] : 0.f;
        }
        __syncthreads();
        float acc[NT];
#pragma unroll
        for (int i = 0; i < NT; i++) acc[i] = 0.f;
        int j = tid;
        for (int k = 0; k < W_; k++) {
            float w = Wpre[k * W_ + j];
#pragma unroll
            for (int i = 0; i < NT; i++) acc[i] += xs[i * W_ + k] * w;
        }
        float bj = bpre[j];
#pragma unroll
        for (int i = 0; i < NT; i++) ys[i * W_ + j] = acc[i] + bj;
        __syncthreads();
        int wid = tid >> 5, lane = tid & 31;
#pragma unroll
        for (int rr = 0; rr < 2; rr++) {
            int row = wid * 2 + rr;
            float s = 0.f;
#pragma unroll
            for (int m = 0; m < W_ / 32; m++) s += ys[row * W_ + lane + 32 * m];
#pragma unroll
            for (int off = 16; off > 0; off >>= 1) s += __shfl_xor_sync(0xffffffffu, s, off);
            float mean = s * (1.0f / W_);
            float v = 0.f;
#pragma unroll
            for (int m = 0; m < W_ / 32; m++) {
                float d = ys[row * W_ + lane + 32 * m] - mean;
                v += d * d;
            }
#pragma unroll
            for (int off = 16; off > 0; off >>= 1) v += __shfl_xor_sync(0xffffffffu, v, off);
            if (lane == 0) {
                s_mean[row] = mean;
                s_rstd[row] = rsqrtf(v * (1.0f / W_) + 1e-5f);
            }
        }
        __syncthreads();
        unsigned* out = (unsigned*)(g_xxfh + (size_t)b * 512);
        for (int idx = tid; idx < 2048; idx += 256) {
            int i = idx & 3;
            int t = (idx >> 2) & 31;
            int kt = idx >> 7;
            int er = (t >> 2) + ((i & 1) << 3);
            int kc = kt * 16 + (t & 3) * 2 + ((i >> 1) << 3);
            float f0 = (ys[er * W_ + kc] - s_mean[er]) * s_rstd[er];
            float f1 = (ys[er * W_ + kc + 1] - s_mean[er]) * s_rstd[er];
            out[idx] = packh(f0, f1);
        }
        return;
    }
    b -= 628;
    if (b < 192) {
        int idx = b * 256 + tid;        // 0..49151
        int m = idx / 16384;
        int j = idx & 16383;
        int nt = j >> 8;
        int kt = (j >> 5) & 7;
        int lane = j & 31;
        int tg = lane & 3, gid = lane >> 2;
        const float* W = (m == 0) ? W0 : ((m == 1) ? W1 : W2);
        float sc = expf((m == 2) ? init0[3] : init0[2]);
        int col = permcol(nt, gid);
        int k0 = kt * 16 + tg * 2;
        uint2 o;
        o.x = packh(W[k0 * H_ + col] * sc, W[(k0 + 1) * H_ + col] * sc);
        o.y = packh(W[(k0 + 8) * H_ + col] * sc, W[(k0 + 9) * H_ + col] * sc);
        int chunk = nt >> 3, nt8 = nt & 7;
        g_wf2h[((chunk * 3 + m) * 8 + nt8) * 256 + kt * 32 + lane] = o;
        return;
    }
    b -= 192;
    if (b < 512) {
        int idx = b * 256 + tid;  // 0..131071
        int m = idx >> 15;
        int j = idx & 32767;
        int nt = j >> 9;
        int kt = (j >> 5) & 15;
        int lane = j & 31;
        int tg = lane & 3, gid = lane >> 2;
        const float* W = (m == 0) ? Wq : ((m == 1) ? Wk : ((m == 2) ? Wv : Wm));
        int col = permcol(nt, gid);
        int k0 = kt * 16 + tg * 2;
        uint2 o;
        o.x = packh(W[k0 * H_ + col], W[(k0 + 1) * H_ + col]);
        o.y = packh(W[(k0 + 8) * H_ + col], W[(k0 + 9) * H_ + col]);
        int s = m * 8 + (nt >> 3);
        g_wfnh[((s * 8 + (nt & 7)) * 16 + kt) * 32 + lane] = o;
        return;
    }
    b -= 512;
    if (b < 128) {
        int idx = b * 256 + tid;  // 0..32767
        int nt = idx >> 10;
        int kt = (idx >> 5) & 31;
        int lane = idx & 31;
        int tg = lane & 3, gid = lane >> 2;
        int col = permcol(nt, gid);
        int k0 = kt * 16 + tg * 2;
        uint2 o;
        o.x = packh(Wpost[k0 * W_ + col], Wpost[(k0 + 1) * W_ + col]);
        o.y = packh(Wpost[(k0 + 8) * W_ + col], Wpost[(k0 + 9) * W_ + col]);
        int stage = nt >> 3;
        g_wfph[((stage * 8 + (nt & 7)) * 32 + kt) * 32 + lane] = o;
        return;
    }
    b -= 128;
    // ---- ee embedding mix -> A-frags ----
    float* ee_s = sbuf;
    int e0 = b * 32;
    if (tid < 128) s_attr[tid] = edge_attr[e0 * 4 + tid];
    float ew0 = expf(init0_e[0]), ew1 = expf(init0_e[1]);
    float ew2 = expf(init0_e[2]), ew3 = expf(init0_e[3]);
    float rs = rsqrtf(ew0 + ew1 + ew2 + ew3);
    ew0 *= rs; ew1 *= rs; ew2 *= rs; ew3 *= rs;
    __syncthreads();
    for (int idx = tid; idx < 32 * EW_; idx += 256) {
        int e = idx >> 7;
        int c = idx & (EW_ - 1);
        int a0 = s_attr[e * 4 + 0], a1 = s_attr[e * 4 + 1];
        int a2 = s_attr[e * 4 + 2], a3 = s_attr[e * 4 + 3];
        float v = emb0[a0 * EW_ + c] * ew0 + emb1[a1 * EW_ + c] * ew1 +
                  emb2[a2 * EW_ + c] * ew2 + emb3[a3 * EW_ + c] * ew3;
        ee_s[idx] = 0.5f * (v + edge_embed[(e0 + e) * EW_ + c]);
    }
    __syncthreads();
    unsigned* out = (unsigned*)(g_eefh + (size_t)b * 512);
    for (int idx = tid; idx < 2048; idx += 256) {
        int i = idx & 3;
        int t = (idx >> 2) & 31;
        int kt = (idx >> 7) & 7;
        int let = idx >> 10;
        int er = (t >> 2) + ((i & 1) << 3);
        int kc = kt * 16 + (t & 3) * 2 + ((i >> 1) << 3);
        out[idx] = packh(ee_s[(let * 16 + er) * EW_ + kc],
                         ee_s[(let * 16 + er) * EW_ + kc + 1]);
    }
}

// ---------------------------------------------------------------------------
// fp16 node projections: 64 nodes/block, 32 passes, float4 epilogue stores.
// ---------------------------------------------------------------------------
__global__ void __launch_bounds__(256, 2) k_projz(const float* __restrict__ bq,
                                                  const float* __restrict__ bk,
                                                  const float* __restrict__ bv,
                                                  const float* __restrict__ bm,
                                                  const float* __restrict__ br0,
                                                  const float* __restrict__ br1,
                                                  const float* __restrict__ br2,
                                                  const float* __restrict__ init0) {
    extern __shared__ char dsm[];
    uint4* a_sm = (uint4*)dsm;               // 32KB
    uint2* b_sm = (uint2*)(dsm + 32768);     // 2 x 32KB
    __shared__ __align__(8) unsigned long long mbar_s[3];

    int tid = threadIdx.x;
    int lane = tid & 31, wid = tid >> 5;
    int mg = wid >> 2;
    int ng = wid & 3;
    int gid = lane >> 2, tg = lane & 3;
    int blk = blockIdx.x;

    unsigned mbA = s2u(&mbar_s[0]);
    unsigned mb0 = s2u(&mbar_s[1]);
    unsigned mb1 = s2u(&mbar_s[2]);
    if (tid == 0) {
        mbar_init(mbA, 1);
        mbar_init(mb0, 1);
        mbar_init(mb1, 1);
    }
    float s_e = expf(init0[2]);
    float s_v = expf(init0[3]);
    __syncthreads();

    if (tid == 0) {
        mbar_expect(mbA, 32768);
        bulk_g2s(s2u(a_sm), g_xxfh + (size_t)blk * 2048, 32768, mbA);
        mbar_expect(mb0, 32768);
        bulk_g2s(s2u(b_sm), g_wfnh, 32768, mb0);
        mbar_expect(mb1, 32768);
        bulk_g2s(s2u(b_sm + 4096), g_wfnh + 4096, 32768, mb1);
    }

    // zero g_agg slice while copies are in flight
    {
        int r0 = blk * 64;
        float4 z = make_float4(0.f, 0.f, 0.f, 0.f);
        for (int i = tid; i < 64 * (H_ / 4); i += 256) {
            int r = r0 + (i >> 7);
            if (r < NN) *(float4*)(g_agg + (size_t)r * H_ + ((i & 127) << 2)) = z;
        }
    }

    const uint4* aw = a_sm + mg * 1024 + lane;
    const uint2* bw = b_sm + (ng * 2) * 512 + lane;

    mbar_wait(mbA, 0);
    int ph0 = 0, ph1 = 0;

#pragma unroll 1
    for (int s = 0; s < 32; s++) {
        int buf = s & 1;
        if (buf == 0) { mbar_wait(mb0, ph0); ph0 ^= 1; }
        else          { mbar_wait(mb1, ph1); ph1 ^= 1; }

        float acc[2][2][4];
#pragma unroll
        for (int mt = 0; mt < 2; mt++)
#pragma unroll
            for (int nt = 0; nt < 2; nt++)
#pragma unroll
                for (int c = 0; c < 4; c++) acc[mt][nt][c] = 0.f;

#pragma unroll 4
        for (int kt = 0; kt < 16; kt++) {
            uint4 av0 = aw[kt * 32];
            uint4 av1 = aw[512 + kt * 32];
            uint2 bv0 = bw[buf * 4096 + kt * 32];
            uint2 bv1 = bw[buf * 4096 + 512 + kt * 32];
            mma16(acc[0][0], av0, bv0);
            mma16(acc[0][1], av0, bv1);
            mma16(acc[1][0], av1, bv0);
            mma16(acc[1][1], av1, bv1);
        }
        __syncthreads();
        if (tid == 0 && s + 2 < 32) {
            if (buf == 0) { mbar_expect(mb0, 32768); bulk_g2s(s2u(b_sm), g_wfnh + (size_t)(s + 2) * 4096, 32768, mb0); }
            else          { mbar_expect(mb1, 32768); bulk_g2s(s2u(b_sm + 4096), g_wfnh + (size_t)(s + 2) * 4096, 32768, mb1); }
        }

        int m = s >> 3, cc = s & 7;
        const float* bmain = (m == 0) ? bq : ((m == 1) ? bk : ((m == 2) ? bv : bm));
        const float* badd  = (m == 0) ? br0 : ((m == 1) ? br1 : br2);
        float scale = (m < 2) ? s_e : s_v;
        float* dst = (m == 0) ? g_qn : ((m == 1) ? g_kn : ((m == 2) ? g_vn : g_m0));
        int col = cc * 64 + ng * 16 + tg * 4;
        float4 bb = *(const float4*)(bmain + col);
        if (m < 3) {
            float4 b2 = *(const float4*)(badd + col);
            bb = make_float4(bb.x + b2.x * scale, bb.y + b2.y * scale,
                             bb.z + b2.z * scale, bb.w + b2.w * scale);
        }
#pragma unroll
        for (int mt = 0; mt < 2; mt++) {
            int r0 = blk * 64 + mg * 32 + mt * 16 + gid;
            int r1 = r0 + 8;
            float4 o0 = make_float4(acc[mt][0][0] + bb.x, acc[mt][0][1] + bb.y,
                                    acc[mt][1][0] + bb.z, acc[mt][1][1] + bb.w);
            float4 o1 = make_float4(acc[mt][0][2] + bb.x, acc[mt][0][3] + bb.y,
                                    acc[mt][1][2] + bb.z, acc[mt][1][3] + bb.w);
            if (m == 3) {
                o0 = make_float4(gelu_erf(o0.x), gelu_erf(o0.y), gelu_erf(o0.z), gelu_erf(o0.w));
                o1 = make_float4(gelu_erf(o1.x), gelu_erf(o1.y), gelu_erf(o1.z), gelu_erf(o1.w));
            }
            if (r0 < NN) *(float4*)(dst + (size_t)r0 * H_ + col) = o0;
            if (r1 < NN) *(float4*)(dst + (size_t)r1 * H_ + col) = o1;
        }
    }
}

// ---------------------------------------------------------------------------
// fp16 edge kernel: 128 edges/block, 512 threads (4 mg x 4 ng).
// Permuted cols -> float4 gathers + red.v4 scatters.
// ---------------------------------------------------------------------------
__global__ void __launch_bounds__(512) k_edge(const int* __restrict__ edge_index,
                                              const float* __restrict__ init0) {
    extern __shared__ char dsm[];
    uint4* a_sm = (uint4*)dsm;               // 32KB
    uint2* b_sm = (uint2*)(dsm + 32768);     // 2 x 48KB
    __shared__ int s_src[128], s_dst[128];
    __shared__ float p_buf[4][128];
    __shared__ __align__(8) unsigned long long mbar_s[3];

    int tid = threadIdx.x;
    int lane = tid & 31, wid = tid >> 5;
    int mg = wid >> 2;
    int ng = wid & 3;
    int gid = lane >> 2, tg = lane & 3;
    int e0 = blockIdx.x * 128;

    unsigned mbA = s2u(&mbar_s[0]);
    unsigned mb0 = s2u(&mbar_s[1]);
    unsigned mb1 = s2u(&mbar_s[2]);

    if (tid < 128) {
        s_src[tid] = edge_index[e0 + tid];
        s_dst[tid] = edge_index[NE + e0 + tid];
    }
    if (tid == 0) {
        mbar_init(mbA, 1);
        mbar_init(mb0, 1);
        mbar_init(mb1, 1);
    }
    float c0 = init0[0] * 0.125f;
    float c1 = init0[1];
    __syncthreads();

    if (tid == 0) {
        mbar_expect(mbA, 32768);
        bulk_g2s(s2u(a_sm), g_eefh + (size_t)blockIdx.x * 2048, 32768, mbA);
        mbar_expect(mb0, 49152);
        bulk_g2s(s2u(b_sm), g_wf2h, 49152, mb0);
        mbar_expect(mb1, 49152);
        bulk_g2s(s2u(b_sm + 6144), g_wf2h + 6144, 49152, mb1);
    }

    int rd0[2], rd1[2], rs0[2], rs1[2];
#pragma unroll
    for (int mt = 0; mt < 2; mt++) {
        int el = mg * 32 + mt * 16 + gid;
        rd0[mt] = s_dst[el];
        rd1[mt] = s_dst[el + 8];
        rs0[mt] = s_src[el];
        rs1[mt] = s_src[el + 8];
    }

    const uint4* aw = a_sm + mg * 512 + lane;
    const uint2* bw = b_sm + (ng * 2) * 256 + lane;

    mbar_wait(mbA, 0);
    int ph0 = 0, ph1 = 0;

#pragma unroll 1
    for (int chunk = 0; chunk < 8; chunk++) {
        float acc[3][2][2][4];
#pragma unroll
        for (int m = 0; m < 3; m++)
#pragma unroll
            for (int mt = 0; mt < 2; mt++)
#pragma unroll
                for (int nt = 0; nt < 2; nt++)
#pragma unroll
                    for (int c = 0; c < 4; c++) acc[m][mt][nt][c] = 0.f;

        int colbase = chunk * 64 + ng * 16 + tg * 4;
        int bufbase = (chunk & 1) * 6144;

        // prefetch q/k gathers (float4, thread owns 4 consecutive cols)
        float4 qv[2][2], kv[2][2];
#pragma unroll
        for (int mt = 0; mt < 2; mt++) {
            qv[mt][0] = *(const float4*)(g_qn + (size_t)rd0[mt] * H_ + colbase);
            qv[mt][1] = *(const float4*)(g_qn + (size_t)rd1[mt] * H_ + colbase);
            kv[mt][0] = *(const float4*)(g_kn + (size_t)rs0[mt] * H_ + colbase);
            kv[mt][1] = *(const float4*)(g_kn + (size_t)rs1[mt] * H_ + colbase);
        }

        if ((chunk & 1) == 0) { mbar_wait(mb0, ph0); ph0 ^= 1; }
        else                  { mbar_wait(mb1, ph1); ph1 ^= 1; }

#pragma unroll
        for (int kt = 0; kt < 4; kt++) {
            uint4 av0 = aw[kt * 32];
            uint4 av1 = aw[256 + kt * 32];
            uint2 bv[3][2];
#pragma unroll
            for (int m = 0; m < 3; m++)
#pragma unroll
                for (int nt = 0; nt < 2; nt++)
                    bv[m][nt] = bw[bufbase + (m * 8 + nt) * 256 + kt * 32];
#pragma unroll
            for (int m = 0; m < 3; m++)
#pragma unroll
                for (int nt = 0; nt < 2; nt++) {
                    mma16(acc[m][0][nt], av0, bv[m][nt]);
                    mma16(acc[m][1][nt], av1, bv[m][nt]);
                }
        }

        // prefetch v gathers
        float4 vv[2][2];
#pragma unroll
        for (int mt = 0; mt < 2; mt++) {
            vv[mt][0] = *(const float4*)(g_vn + (size_t)rs0[mt] * H_ + colbase);
            vv[mt][1] = *(const float4*)(g_vn + (size_t)rs1[mt] * H_ + colbase);
        }

#pragma unroll
        for (int kt = 4; kt < 8; kt++) {
            uint4 av0 = aw[kt * 32];
            uint4 av1 = aw[256 + kt * 32];
            uint2 bv[3][2];
#pragma unroll
            for (int m = 0; m < 3; m++)
#pragma unroll
                for (int nt = 0; nt < 2; nt++)
                    bv[m][nt] = bw[bufbase + (m * 8 + nt) * 256 + kt * 32];
#pragma unroll
            for (int m = 0; m < 3; m++)
#pragma unroll
                for (int nt = 0; nt < 2; nt++) {
                    mma16(acc[m][0][nt], av0, bv[m][nt]);
                    mma16(acc[m][1][nt], av1, bv[m][nt]);
                }
        }

        // attention partial dots — thread cols map: {nt0c0,nt0c1,nt1c0,nt1c1} = x,y,z,w (row gid);
        // {nt0c2,nt0c3,nt1c2,nt1c3} (row gid+8)
        float p[2][2];
        p[0][0] = p[0][1] = p[1][0] = p[1][1] = 0.f;
#pragma unroll
        for (int mt = 0; mt < 2; mt++) {
            p[mt][0] = (qv[mt][0].x + acc[0][mt][0][0]) * (kv[mt][0].x + acc[1][mt][0][0])
                     + (qv[mt][0].y + acc[0][mt][0][1]) * (kv[mt][0].y + acc[1][mt][0][1])
                     + (qv[mt][0].z + acc[0][mt][1][0]) * (kv[mt][0].z + acc[1][mt][1][0])
                     + (qv[mt][0].w + acc[0][mt][1][1]) * (kv[mt][0].w + acc[1][mt][1][1]);
            p[mt][1] = (qv[mt][1].x + acc[0][mt][0][2]) * (kv[mt][1].x + acc[1][mt][0][2])
                     + (qv[mt][1].y + acc[0][mt][0][3]) * (kv[mt][1].y + acc[1][mt][0][3])
                     + (qv[mt][1].z + acc[0][mt][1][2]) * (kv[mt][1].z + acc[1][mt][1][2])
                     + (qv[mt][1].w + acc[0][mt][1][3]) * (kv[mt][1].w + acc[1][mt][1][3]);
        }
#pragma unroll
        for (int off = 1; off <= 2; off <<= 1) {
            p[0][0] += __shfl_xor_sync(0xffffffffu, p[0][0], off);
            p[0][1] += __shfl_xor_sync(0xffffffffu, p[0][1], off);
            p[1][0] += __shfl_xor_sync(0xffffffffu, p[1][0], off);
            p[1][1] += __shfl_xor_sync(0xffffffffu, p[1][1], off);
        }
        __syncthreads();
        if (tg == 0) {
#pragma unroll
            for (int mt = 0; mt < 2; mt++) {
                int el = mg * 32 + mt * 16 + gid;
                p_buf[ng][el] = p[mt][0];
                p_buf[ng][el + 8] = p[mt][1];
            }
        }
        __syncthreads();
        if (tid == 0 && chunk < 6) {
            if ((chunk & 1) == 0) { mbar_expect(mb0, 49152); bulk_g2s(s2u(b_sm), g_wf2h + (size_t)(chunk + 2) * 6144, 49152, mb0); }
            else                  { mbar_expect(mb1, 49152); bulk_g2s(s2u(b_sm + 6144), g_wf2h + (size_t)(chunk + 2) * 6144, 49152, mb1); }
        }

        // V epilogue: gelu + att scale + red.v4 scatter (1 per edge-row)
#pragma unroll
        for (int mt = 0; mt < 2; mt++) {
            int el = mg * 32 + mt * 16 + gid;
            float sum0 = p_buf[0][el] + p_buf[1][el] + p_buf[2][el] + p_buf[3][el];
            float sum1 = p_buf[0][el + 8] + p_buf[1][el + 8] + p_buf[2][el + 8] + p_buf[3][el + 8];
            float att0 = expf(sum0 * c0 + c1);
            float att1 = expf(sum1 * c0 + c1);
            red4(g_agg + (size_t)rd0[mt] * H_ + colbase,
                 gelu_erf(vv[mt][0].x + acc[2][mt][0][0]) * att0,
                 gelu_erf(vv[mt][0].y + acc[2][mt][0][1]) * att0,
                 gelu_erf(vv[mt][0].z + acc[2][mt][1][0]) * att0,
                 gelu_erf(vv[mt][0].w + acc[2][mt][1][1]) * att0);
            red4(g_agg + (size_t)rd1[mt] * H_ + colbase,
                 gelu_erf(vv[mt][1].x + acc[2][mt][0][2]) * att1,
                 gelu_erf(vv[mt][1].y + acc[2][mt][0][3]) * att1,
                 gelu_erf(vv[mt][1].z + acc[2][mt][1][2]) * att1,
                 gelu_erf(vv[mt][1].w + acc[2][mt][1][3]) * att1);
        }
    }
}

// ---------------------------------------------------------------------------
// fp16 post kernel: out = x + (m0+agg) @ W_post + b_post. float4 epilogue.
// ---------------------------------------------------------------------------
__global__ void __launch_bounds__(256) k_post(const float* __restrict__ x,
                                              const float* __restrict__ bp,
                                              float* __restrict__ out) {
    extern __shared__ char dsm[];
    uint4* a_sm = (uint4*)dsm;               // 64KB
    uint2* b_sm = (uint2*)(dsm + 65536);     // 2 x 64KB
    __shared__ __align__(8) unsigned long long mbar_s[2];

    int tid = threadIdx.x;
    int lane = tid & 31, wid = tid >> 5;
    int mg = wid >> 2;
    int ng = wid & 3;
    int gid = lane >> 2, tg = lane & 3;
    int blk = blockIdx.x;

    unsigned mb0 = s2u(&mbar_s[0]);
    unsigned mb1 = s2u(&mbar_s[1]);
    if (tid == 0) {
        mbar_init(mb0, 1);
        mbar_init(mb1, 1);
    }
    __syncthreads();
    if (tid == 0) {
        mbar_expect(mb0, 65536);
        bulk_g2s(s2u(b_sm), g_wfph, 65536, mb0);
        mbar_expect(mb1, 65536);
        bulk_g2s(s2u(b_sm + 8192), g_wfph + 8192, 65536, mb1);
    }

    // build A fragments from m0 + agg
    {
        unsigned* aword = (unsigned*)a_sm;
        for (int widx = tid; widx < 16384; widx += 256) {
            int i = widx & 3;
            int t = (widx >> 2) & 31;
            int kt = (widx >> 7) & 31;
            int mt = widx >> 12;
            int er = (t >> 2) + ((i & 1) << 3);
            int row = blk * 64 + mt * 16 + er;
            int kc = kt * 16 + (t & 3) * 2 + ((i >> 1) << 3);
            float f0 = 0.f, f1 = 0.f;
            if (row < NN) {
                float2 m2 = *(const float2*)(g_m0 + (size_t)row * H_ + kc);
                float2 a2 = *(const float2*)(g_agg + (size_t)row * H_ + kc);
                f0 = m2.x + a2.x;
                f1 = m2.y + a2.y;
            }
            aword[widx] = packh(f0, f1);
        }
    }
    __syncthreads();

    const uint4* aw = a_sm + mg * 2048 + lane;
    const uint2* bw = b_sm + (ng * 2) * 1024 + lane;
    int ph0 = 0, ph1 = 0;

#pragma unroll 1
    for (int s = 0; s < 4; s++) {
        int buf = s & 1;
        if (buf == 0) { mbar_wait(mb0, ph0); ph0 ^= 1; }
        else          { mbar_wait(mb1, ph1); ph1 ^= 1; }

        float acc[2][2][4];
#pragma unroll
        for (int mt = 0; mt < 2; mt++)
#pragma unroll
            for (int nt = 0; nt < 2; nt++)
#pragma unroll
                for (int c = 0; c < 4; c++) acc[mt][nt][c] = 0.f;

#pragma unroll 4
        for (int kt = 0; kt < 32; kt++) {
            uint4 av0 = aw[kt * 32];
            uint4 av1 = aw[1024 + kt * 32];
            uint2 bv0 = bw[buf * 8192 + kt * 32];
            uint2 bv1 = bw[buf * 8192 + 1024 + kt * 32];
            mma16(acc[0][0], av0, bv0);
            mma16(acc[0][1], av0, bv1);
            mma16(acc[1][0], av1, bv0);
            mma16(acc[1][1], av1, bv1);
        }
        __syncthreads();
        if (tid == 0 && s + 2 < 4) {
            if (buf == 0) { mbar_expect(mb0, 65536); bulk_g2s(s2u(b_sm), g_wfph + (size_t)(s + 2) * 8192, 65536, mb0); }
            else          { mbar_expect(mb1, 65536); bulk_g2s(s2u(b_sm + 8192), g_wfph + (size_t)(s + 2) * 8192, 65536, mb1); }
        }

        int col = s * 64 + ng * 16 + tg * 4;
        float4 bb = *(const float4*)(bp + col);
#pragma unroll
        for (int mt = 0; mt < 2; mt++) {
            int r0 = blk * 64 + mg * 32 + mt * 16 + gid;
            int r1 = r0 + 8;
            if (r0 < NN) {
                float4 xx0 = *(const float4*)(x + (size_t)r0 * W_ + col);
                *(float4*)(out + (size_t)r0 * W_ + col) =
                    make_float4(xx0.x + acc[mt][0][0] + bb.x, xx0.y + acc[mt][0][1] + bb.y,
                                xx0.z + acc[mt][1][0] + bb.z, xx0.w + acc[mt][1][1] + bb.w);
            }
            if (r1 < NN) {
                float4 xx1 = *(const float4*)(x + (size_t)r1 * W_ + col);
                *(float4*)(out + (size_t)r1 * W_ + col) =
                    make_float4(xx1.x + acc[mt][0][2] + bb.x, xx1.y + acc[mt][0][3] + bb.y,
                                xx1.z + acc[mt][1][2] + bb.z, xx1.w + acc[mt][1][3] + bb.w);
            }
        }
    }
}

extern "C" void kernel_launch(void* const* d_in, const int* in_sizes, int n_in,
                              void* d_out, int out_size) {
    const float* x          = (const float*)d_in[0];
    const int*   edge_index = (const int*)d_in[1];
    const int*   edge_attr  = (const int*)d_in[2];
    const float* edge_embed = (const float*)d_in[3];
    const float* emb0       = (const float*)d_in[4];
    const float* emb1       = (const float*)d_in[5];
    const float* emb2       = (const float*)d_in[6];
    const float* emb3       = (const float*)d_in[7];
    const float* init0_e    = (const float*)d_in[8];
    const float* init0      = (const float*)d_in[9];
    const float* W_pre      = (const float*)d_in[10];
    const float* b_pre      = (const float*)d_in[11];
    const float* W_msg0     = (const float*)d_in[12];
    const float* b_msg0     = (const float*)d_in[13];
    const float* W_q        = (const float*)d_in[14];
    const float* b_q        = (const float*)d_in[15];
    const float* W_k        = (const float*)d_in[16];
    const float* b_k        = (const float*)d_in[17];
    const float* W_v        = (const float*)d_in[18];
    const float* b_v        = (const float*)d_in[19];
    const float* W_r0       = (const float*)d_in[20];
    const float* b_r0       = (const float*)d_in[21];
    const float* W_r1       = (const float*)d_in[22];
    const float* b_r1       = (const float*)d_in[23];
    const float* W_r2       = (const float*)d_in[24];
    const float* b_r2       = (const float*)d_in[25];
    const float* W_post     = (const float*)d_in[26];
    const float* b_post     = (const float*)d_in[27];
    float* out = (float*)d_out;

    cudaFuncSetAttribute(k_edge, cudaFuncAttributeMaxDynamicSharedMemorySize, 131072);
    cudaFuncSetAttribute(k_projz, cudaFuncAttributeMaxDynamicSharedMemorySize, 98304);
    cudaFuncSetAttribute(k_post, cudaFuncAttributeMaxDynamicSharedMemorySize, 196608);

    k_wfeef<<<628 + 832 + NE / 32, 256>>>(x, W_pre, b_pre,
                                          W_r0, W_r1, W_r2, W_q, W_k, W_v, W_msg0, W_post,
                                          edge_attr, edge_embed,
                                          emb0, emb1, emb2, emb3, init0_e, init0);
    k_projz<<<NP / 64, 256, 98304>>>(b_q, b_k, b_v, b_msg0, b_r0, b_r1, b_r2, init0);
    k_edge<<<NE / 128, 512, 131072>>>(edge_index, init0);
    k_post<<<NP / 64, 256, 196608>>>(x, b_post, out);
}

// round 10
// speedup vs baseline: 4.2887x; 1.0440x over previous
#include <cuda_runtime.h>
#include <cuda_fp16.h>
#include <math.h>

#define NN 10000
#define NP 10048   // padded nodes (157 * 64)
#define NE 160000
#define W_ 256
#define H_ 512
#define EW_ 128

// Scratch (static device memory — no allocation allowed)
__device__ float g_qn[NN * H_];
__device__ float g_kn[NN * H_];
__device__ float g_vn[NN * H_];
__device__ float g_m0[NN * H_];
__device__ float g_agg[NN * H_];
__device__ uint4 g_eefh[NE * 16];              // ee fp16 A-frags
__device__ uint2 g_wf2h[8 * 3 * 8 * 8 * 32];   // Wr0..2 fp16 B-frags (perm cols, scales folded)
__device__ uint2 g_wfnh[4 * 64 * 16 * 32];     // Wq/Wk/Wv/Wm fp16 B-frags (perm cols)
__device__ uint2 g_wfph[32 * 32 * 32];         // W_post fp16 B-frags (perm cols)
__device__ uint4 g_xxfh[(NP / 16) * 512];      // LN(pre(x)) fp16 A-frags
__device__ uint4 g_xf[(NP / 16) * 512];        // raw x fp16 A-frags
__device__ uint2 g_wfpre[32 * 16 * 32];        // W_pre fp16 B-frags (natural cols, 128KB)

__device__ __forceinline__ float gelu_erf(float h) {
    return 0.5f * h * (1.0f + erff(h * 0.70710678118654752f));
}

__device__ __forceinline__ unsigned packh(float a, float b) {
    __half2 h = __floats2half2_rn(a, b);
    return *(unsigned*)&h;
}

__device__ __forceinline__ void mma16(float* d, const uint4& a, const uint2& b) {
    asm volatile(
        "mma.sync.aligned.m16n8k16.row.col.f32.f16.f16.f32 "
        "{%0,%1,%2,%3},{%4,%5,%6,%7},{%8,%9},{%0,%1,%2,%3};"
        : "+f"(d[0]), "+f"(d[1]), "+f"(d[2]), "+f"(d[3])
        : "r"(a.x), "r"(a.y), "r"(a.z), "r"(a.w), "r"(b.x), "r"(b.y));
}

__device__ __forceinline__ void red4(float* p, float a, float b, float c, float d) {
    asm volatile("red.global.add.v4.f32 [%0], {%1,%2,%3,%4};"
                 :: "l"(p), "f"(a), "f"(b), "f"(c), "f"(d) : "memory");
}

// ---- mbarrier + bulk-copy helpers ----
__device__ __forceinline__ unsigned s2u(const void* p) {
    return (unsigned)__cvta_generic_to_shared(p);
}
__device__ __forceinline__ void mbar_init(unsigned mbar, unsigned cnt) {
    asm volatile("mbarrier.init.shared.b64 [%0], %1;" :: "r"(mbar), "r"(cnt) : "memory");
}
__device__ __forceinline__ void mbar_expect(unsigned mbar, unsigned bytes) {
    asm volatile("mbarrier.arrive.expect_tx.shared.b64 _, [%0], %1;"
                 :: "r"(mbar), "r"(bytes) : "memory");
}
__device__ __forceinline__ void bulk_g2s(unsigned dst, const void* src, unsigned bytes,
                                         unsigned mbar) {
    asm volatile("cp.async.bulk.shared::cta.global.mbarrier::complete_tx::bytes "
                 "[%0], [%1], %2, [%3];"
                 :: "r"(dst), "l"(src), "r"(bytes), "r"(mbar) : "memory");
}
__device__ __forceinline__ void mbar_wait(unsigned mbar, int phase) {
    asm volatile(
        "{\n\t.reg .pred P;\n\t"
        "W_%=:\n\t"
        "mbarrier.try_wait.parity.acquire.cta.shared::cta.b64 P, [%0], %1, 0x989680;\n\t"
        "@P bra.uni D_%=;\n\t"
        "bra.uni W_%=;\n\t"
        "D_%=:\n\t}"
        :: "r"(mbar), "r"(phase) : "memory");
}

// permuted physical column within a 16-col group
__device__ __forceinline__ int permcol(int nt, int gid) {
    return (nt >> 1) * 16 + (gid >> 1) * 4 + (nt & 1) * 2 + (gid & 1);
}

// ---------------------------------------------------------------------------
// Merged pre-pass:
//  [0,628):        x -> fp16 A-frags (g_xf)
//  [628,692):      W_pre -> fp16 B-frags, natural cols (g_wfpre)
//  [692,884):      Wr0..2 -> fp16 B-frags (perm, scales folded)
//  [884,1396):     Wq/Wk/Wv/Wm -> fp16 B-frags (perm)
//  [1396,1524):    W_post -> fp16 B-frags (perm)
//  [1524,6524):    ee embedding mix -> fp16 A-frags
// ---------------------------------------------------------------------------
__global__ void __launch_bounds__(256) k_wfeef(const float* __restrict__ x,
                                               const float* __restrict__ Wpre,
                                               const float* __restrict__ W0,
                                               const float* __restrict__ W1,
                                               const float* __restrict__ W2,
                                               const float* __restrict__ Wq,
                                               const float* __restrict__ Wk,
                                               const float* __restrict__ Wv,
                                               const float* __restrict__ Wm,
                                               const float* __restrict__ Wpost,
                                               const int* __restrict__ edge_attr,
                                               const float* __restrict__ edge_embed,
                                               const float* __restrict__ emb0,
                                               const float* __restrict__ emb1,
                                               const float* __restrict__ emb2,
                                               const float* __restrict__ emb3,
                                               const float* __restrict__ init0_e,
                                               const float* __restrict__ init0) {
    __shared__ float sbuf[4096];   // 16KB
    __shared__ int s_attr[128];
    int tid = threadIdx.x;
    int b = blockIdx.x;

    if (b < 628) {
        // x tile -> A-frags
        int n0 = b * 16;
        for (int idx = tid; idx < 4096; idx += 256) {
            int row = idx >> 8;
            sbuf[idx] = (n0 + row < NN) ? x[n0 * W_ + idx] : 0.f;
        }
        __syncthreads();
        unsigned* out = (unsigned*)(g_xf + (size_t)b * 512);
        for (int idx = tid; idx < 2048; idx += 256) {
            int i = idx & 3;
            int t = (idx >> 2) & 31;
            int kt = idx >> 7;
            int er = (t >> 2) + ((i & 1) << 3);
            int kc = kt * 16 + (t & 3) * 2 + ((i >> 1) << 3);
            out[idx] = packh(sbuf[er * W_ + kc], sbuf[er * W_ + kc + 1]);
        }
        return;
    }
    b -= 628;
    if (b < 64) {
        // W_pre -> B-frags natural (g_wfpre), 16384 uint2 total
        int idx = b * 256 + tid;
        int nt = idx >> 9;          // 0..31
        int kt = (idx >> 5) & 15;
        int lane = idx & 31;
        int tg = lane & 3, gid = lane >> 2;
        int col = nt * 8 + gid;
        int k0 = kt * 16 + tg * 2;
        uint2 o;
        o.x = packh(Wpre[k0 * W_ + col], Wpre[(k0 + 1) * W_ + col]);
        o.y = packh(Wpre[(k0 + 8) * W_ + col], Wpre[(k0 + 9) * W_ + col]);
        g_wfpre[(nt * 16 + kt) * 32 + lane] = o;
        return;
    }
    b -= 64;
    if (b < 192) {
        int idx = b * 256 + tid;        // 0..49151
        int m = idx / 16384;
        int j = idx & 16383;
        int nt = j >> 8;
        int kt = (j >> 5) & 7;
        int lane = j & 31;
        int tg = lane & 3, gid = lane >> 2;
        const float* W = (m == 0) ? W0 : ((m == 1) ? W1 : W2);
        float sc = expf((m == 2) ? init0[3] : init0[2]);
        int col = permcol(nt, gid);
        int k0 = kt * 16 + tg * 2;
        uint2 o;
        o.x = packh(W[k0 * H_ + col] * sc, W[(k0 + 1) * H_ + col] * sc);
        o.y = packh(W[(k0 + 8) * H_ + col] * sc, W[(k0 + 9) * H_ + col] * sc);
        int chunk = nt >> 3, nt8 = nt & 7;
        g_wf2h[((chunk * 3 + m) * 8 + nt8) * 256 + kt * 32 + lane] = o;
        return;
    }
    b -= 192;
    if (b < 512) {
        int idx = b * 256 + tid;  // 0..131071
        int m = idx >> 15;
        int j = idx & 32767;
        int nt = j >> 9;
        int kt = (j >> 5) & 15;
        int lane = j & 31;
        int tg = lane & 3, gid = lane >> 2;
        const float* W = (m == 0) ? Wq : ((m == 1) ? Wk : ((m == 2) ? Wv : Wm));
        int col = permcol(nt, gid);
        int k0 = kt * 16 + tg * 2;
        uint2 o;
        o.x = packh(W[k0 * H_ + col], W[(k0 + 1) * H_ + col]);
        o.y = packh(W[(k0 + 8) * H_ + col], W[(k0 + 9) * H_ + col]);
        int s = m * 8 + (nt >> 3);
        g_wfnh[((s * 8 + (nt & 7)) * 16 + kt) * 32 + lane] = o;
        return;
    }
    b -= 512;
    if (b < 128) {
        int idx = b * 256 + tid;  // 0..32767
        int nt = idx >> 10;
        int kt = (idx >> 5) & 31;
        int lane = idx & 31;
        int tg = lane & 3, gid = lane >> 2;
        int col = permcol(nt, gid);
        int k0 = kt * 16 + tg * 2;
        uint2 o;
        o.x = packh(Wpost[k0 * W_ + col], Wpost[(k0 + 1) * W_ + col]);
        o.y = packh(Wpost[(k0 + 8) * W_ + col], Wpost[(k0 + 9) * W_ + col]);
        int stage = nt >> 3;
        g_wfph[((stage * 8 + (nt & 7)) * 32 + kt) * 32 + lane] = o;
        return;
    }
    b -= 128;
    // ---- ee embedding mix -> A-frags ----
    float* ee_s = sbuf;
    int e0 = b * 32;
    if (tid < 128) s_attr[tid] = edge_attr[e0 * 4 + tid];
    float ew0 = expf(init0_e[0]), ew1 = expf(init0_e[1]);
    float ew2 = expf(init0_e[2]), ew3 = expf(init0_e[3]);
    float rs = rsqrtf(ew0 + ew1 + ew2 + ew3);
    ew0 *= rs; ew1 *= rs; ew2 *= rs; ew3 *= rs;
    __syncthreads();
    for (int idx = tid; idx < 32 * EW_; idx += 256) {
        int e = idx >> 7;
        int c = idx & (EW_ - 1);
        int a0 = s_attr[e * 4 + 0], a1 = s_attr[e * 4 + 1];
        int a2 = s_attr[e * 4 + 2], a3 = s_attr[e * 4 + 3];
        float v = emb0[a0 * EW_ + c] * ew0 + emb1[a1 * EW_ + c] * ew1 +
                  emb2[a2 * EW_ + c] * ew2 + emb3[a3 * EW_ + c] * ew3;
        ee_s[idx] = 0.5f * (v + edge_embed[(e0 + e) * EW_ + c]);
    }
    __syncthreads();
    unsigned* out = (unsigned*)(g_eefh + (size_t)b * 512);
    for (int idx = tid; idx < 2048; idx += 256) {
        int i = idx & 3;
        int t = (idx >> 2) & 31;
        int kt = (idx >> 7) & 7;
        int let = idx >> 10;
        int er = (t >> 2) + ((i & 1) << 3);
        int kc = kt * 16 + (t & 3) * 2 + ((i >> 1) << 3);
        out[idx] = packh(ee_s[(let * 16 + er) * EW_ + kc],
                         ee_s[(let * 16 + er) * EW_ + kc + 1]);
    }
}

// ---------------------------------------------------------------------------
// Tensorized pre: xx = LN(x@W_pre + b_pre), 64 nodes/block, fp16 mma,
// LN in smem, output packed to g_xxfh A-frags. B (W_pre, 128KB) resident.
// ---------------------------------------------------------------------------
__global__ void __launch_bounds__(256, 1) k_preT(const float* __restrict__ bpre) {
    extern __shared__ char dsm[];
    uint4* a_sm = (uint4*)dsm;               // [4mt][16kt][32lane] = 32KB
    uint2* b_sm = (uint2*)(dsm + 32768);     // 128KB (aliased by ys after mma)
    float* ys = (float*)(dsm + 32768);       // [64][256] = 64KB
    __shared__ float s_mean[64], s_rstd[64];
    __shared__ __align__(8) unsigned long long mbar_s[2];

    int tid = threadIdx.x;
    int lane = tid & 31, wid = tid >> 5;
    int mg = wid >> 2;        // 0..1
    int ng = wid & 3;         // 0..3 (64 cols each)
    int gid = lane >> 2, tg = lane & 3;
    int blk = blockIdx.x;

    unsigned mbA = s2u(&mbar_s[0]);
    unsigned mbB = s2u(&mbar_s[1]);
    if (tid == 0) {
        mbar_init(mbA, 1);
        mbar_init(mbB, 1);
    }
    __syncthreads();
    if (tid == 0) {
        mbar_expect(mbA, 32768);
        bulk_g2s(s2u(a_sm), g_xf + (size_t)blk * 2048, 32768, mbA);
        mbar_expect(mbB, 131072);
        bulk_g2s(s2u(b_sm), g_wfpre, 65536, mbB);
        bulk_g2s(s2u(b_sm + 8192), g_wfpre + 8192, 65536, mbB);  // FIX: +8192 uint2 = +64KB
    }

    float acc[2][8][4];
#pragma unroll
    for (int mt = 0; mt < 2; mt++)
#pragma unroll
        for (int nt = 0; nt < 8; nt++)
#pragma unroll
            for (int c = 0; c < 4; c++) acc[mt][nt][c] = 0.f;

    const uint4* aw = a_sm + mg * 1024 + lane;
    const uint2* bw = b_sm + ng * 8 * 512 + lane;

    mbar_wait(mbA, 0);
    mbar_wait(mbB, 0);

#pragma unroll 4
    for (int kt = 0; kt < 16; kt++) {
        uint4 av0 = aw[kt * 32];
        uint4 av1 = aw[512 + kt * 32];
#pragma unroll
        for (int nt = 0; nt < 8; nt++) {
            uint2 bv = bw[nt * 512 + kt * 32];
            mma16(acc[0][nt], av0, bv);
            mma16(acc[1][nt], av1, bv);
        }
    }
    __syncthreads();  // done reading b_sm; safe to alias ys

    // write biased results to ys
#pragma unroll
    for (int mt = 0; mt < 2; mt++) {
        int r0 = (mg * 2 + mt) * 16 + gid;
        int r1 = r0 + 8;
#pragma unroll
        for (int nt = 0; nt < 8; nt++) {
            int c = ng * 64 + nt * 8 + tg * 2;
            float2 bb = *(const float2*)(bpre + c);
            ys[r0 * W_ + c] = acc[mt][nt][0] + bb.x;
            ys[r0 * W_ + c + 1] = acc[mt][nt][1] + bb.y;
            ys[r1 * W_ + c] = acc[mt][nt][2] + bb.x;
            ys[r1 * W_ + c + 1] = acc[mt][nt][3] + bb.y;
        }
    }
    __syncthreads();

    // LN stats: 8 warps x 8 rows
#pragma unroll
    for (int rr = 0; rr < 8; rr++) {
        int row = wid * 8 + rr;
        float s = 0.f;
#pragma unroll
        for (int m = 0; m < W_ / 32; m++) s += ys[row * W_ + lane + 32 * m];
#pragma unroll
        for (int off = 16; off > 0; off >>= 1) s += __shfl_xor_sync(0xffffffffu, s, off);
        float mean = s * (1.0f / W_);
        float v = 0.f;
#pragma unroll
        for (int m = 0; m < W_ / 32; m++) {
            float d = ys[row * W_ + lane + 32 * m] - mean;
            v += d * d;
        }
#pragma unroll
        for (int off = 16; off > 0; off >>= 1) v += __shfl_xor_sync(0xffffffffu, v, off);
        if (lane == 0) {
            s_mean[row] = mean;
            s_rstd[row] = rsqrtf(v * (1.0f / W_) + 1e-5f);
        }
    }
    __syncthreads();

    // pack normalized rows into A-frags (4 tiles of 16 nodes)
    unsigned* out = (unsigned*)(g_xxfh + (size_t)blk * 2048);
    for (int idx = tid; idx < 8192; idx += 256) {
        int w = idx & 2047;
        int tile = idx >> 11;
        int i = w & 3;
        int t = (w >> 2) & 31;
        int kt = w >> 7;
        int er = (t >> 2) + ((i & 1) << 3);
        int row = tile * 16 + er;
        int kc = kt * 16 + (t & 3) * 2 + ((i >> 1) << 3);
        float mean = s_mean[row], rstd = s_rstd[row];
        out[idx] = packh((ys[row * W_ + kc] - mean) * rstd,
                         (ys[row * W_ + kc + 1] - mean) * rstd);
    }
}

// ---------------------------------------------------------------------------
// fp16 node projections: 64 nodes/block, 32 passes, float4 epilogue stores.
// ---------------------------------------------------------------------------
__global__ void __launch_bounds__(256, 2) k_projz(const float* __restrict__ bq,
                                                  const float* __restrict__ bk,
                                                  const float* __restrict__ bv,
                                                  const float* __restrict__ bm,
                                                  const float* __restrict__ br0,
                                                  const float* __restrict__ br1,
                                                  const float* __restrict__ br2,
                                                  const float* __restrict__ init0) {
    extern __shared__ char dsm[];
    uint4* a_sm = (uint4*)dsm;               // 32KB
    uint2* b_sm = (uint2*)(dsm + 32768);     // 2 x 32KB
    __shared__ __align__(8) unsigned long long mbar_s[3];

    int tid = threadIdx.x;
    int lane = tid & 31, wid = tid >> 5;
    int mg = wid >> 2;
    int ng = wid & 3;
    int gid = lane >> 2, tg = lane & 3;
    int blk = blockIdx.x;

    unsigned mbA = s2u(&mbar_s[0]);
    unsigned mb0 = s2u(&mbar_s[1]);
    unsigned mb1 = s2u(&mbar_s[2]);
    if (tid == 0) {
        mbar_init(mbA, 1);
        mbar_init(mb0, 1);
        mbar_init(mb1, 1);
    }
    float s_e = expf(init0[2]);
    float s_v = expf(init0[3]);
    __syncthreads();

    if (tid == 0) {
        mbar_expect(mbA, 32768);
        bulk_g2s(s2u(a_sm), g_xxfh + (size_t)blk * 2048, 32768, mbA);
        mbar_expect(mb0, 32768);
        bulk_g2s(s2u(b_sm), g_wfnh, 32768, mb0);
        mbar_expect(mb1, 32768);
        bulk_g2s(s2u(b_sm + 4096), g_wfnh + 4096, 32768, mb1);
    }

    // zero g_agg slice while copies are in flight
    {
        int r0 = blk * 64;
        float4 z = make_float4(0.f, 0.f, 0.f, 0.f);
        for (int i = tid; i < 64 * (H_ / 4); i += 256) {
            int r = r0 + (i >> 7);
            if (r < NN) *(float4*)(g_agg + (size_t)r * H_ + ((i & 127) << 2)) = z;
        }
    }

    const uint4* aw = a_sm + mg * 1024 + lane;
    const uint2* bw = b_sm + (ng * 2) * 512 + lane;

    mbar_wait(mbA, 0);
    int ph0 = 0, ph1 = 0;

#pragma unroll 1
    for (int s = 0; s < 32; s++) {
        int buf = s & 1;
        if (buf == 0) { mbar_wait(mb0, ph0); ph0 ^= 1; }
        else          { mbar_wait(mb1, ph1); ph1 ^= 1; }

        float acc[2][2][4];
#pragma unroll
        for (int mt = 0; mt < 2; mt++)
#pragma unroll
            for (int nt = 0; nt < 2; nt++)
#pragma unroll
                for (int c = 0; c < 4; c++) acc[mt][nt][c] = 0.f;

#pragma unroll 4
        for (int kt = 0; kt < 16; kt++) {
            uint4 av0 = aw[kt * 32];
            uint4 av1 = aw[512 + kt * 32];
            uint2 bv0 = bw[buf * 4096 + kt * 32];
            uint2 bv1 = bw[buf * 4096 + 512 + kt * 32];
            mma16(acc[0][0], av0, bv0);
            mma16(acc[0][1], av0, bv1);
            mma16(acc[1][0], av1, bv0);
            mma16(acc[1][1], av1, bv1);
        }
        __syncthreads();
        if (tid == 0 && s + 2 < 32) {
            if (buf == 0) { mbar_expect(mb0, 32768); bulk_g2s(s2u(b_sm), g_wfnh + (size_t)(s + 2) * 4096, 32768, mb0); }
            else          { mbar_expect(mb1, 32768); bulk_g2s(s2u(b_sm + 4096), g_wfnh + (size_t)(s + 2) * 4096, 32768, mb1); }
        }

        int m = s >> 3, cc = s & 7;
        const float* bmain = (m == 0) ? bq : ((m == 1) ? bk : ((m == 2) ? bv : bm));
        const float* badd  = (m == 0) ? br0 : ((m == 1) ? br1 : br2);
        float scale = (m < 2) ? s_e : s_v;
        float* dst = (m == 0) ? g_qn : ((m == 1) ? g_kn : ((m == 2) ? g_vn : g_m0));
        int col = cc * 64 + ng * 16 + tg * 4;
        float4 bb = *(const float4*)(bmain + col);
        if (m < 3) {
            float4 b2 = *(const float4*)(badd + col);
            bb = make_float4(bb.x + b2.x * scale, bb.y + b2.y * scale,
                             bb.z + b2.z * scale, bb.w + b2.w * scale);
        }
#pragma unroll
        for (int mt = 0; mt < 2; mt++) {
            int r0 = blk * 64 + mg * 32 + mt * 16 + gid;
            int r1 = r0 + 8;
            float4 o0 = make_float4(acc[mt][0][0] + bb.x, acc[mt][0][1] + bb.y,
                                    acc[mt][1][0] + bb.z, acc[mt][1][1] + bb.w);
            float4 o1 = make_float4(acc[mt][0][2] + bb.x, acc[mt][0][3] + bb.y,
                                    acc[mt][1][2] + bb.z, acc[mt][1][3] + bb.w);
            if (m == 3) {
                o0 = make_float4(gelu_erf(o0.x), gelu_erf(o0.y), gelu_erf(o0.z), gelu_erf(o0.w));
                o1 = make_float4(gelu_erf(o1.x), gelu_erf(o1.y), gelu_erf(o1.z), gelu_erf(o1.w));
            }
            if (r0 < NN) *(float4*)(dst + (size_t)r0 * H_ + col) = o0;
            if (r1 < NN) *(float4*)(dst + (size_t)r1 * H_ + col) = o1;
        }
    }
}

// ---------------------------------------------------------------------------
// fp16 edge kernel: 128 edges/block, 512 threads (4 mg x 4 ng).
// One __syncthreads per chunk (p_buf double-buffered over chunks).
// ---------------------------------------------------------------------------
__global__ void __launch_bounds__(512) k_edge(const int* __restrict__ edge_index,
                                              const float* __restrict__ init0) {
    extern __shared__ char dsm[];
    uint4* a_sm = (uint4*)dsm;               // 32KB
    uint2* b_sm = (uint2*)(dsm + 32768);     // 2 x 48KB
    __shared__ int s_src[128], s_dst[128];
    __shared__ float p_buf[2][4][128];
    __shared__ __align__(8) unsigned long long mbar_s[3];

    int tid = threadIdx.x;
    int lane = tid & 31, wid = tid >> 5;
    int mg = wid >> 2;
    int ng = wid & 3;
    int gid = lane >> 2, tg = lane & 3;
    int e0 = blockIdx.x * 128;

    unsigned mbA = s2u(&mbar_s[0]);
    unsigned mb0 = s2u(&mbar_s[1]);
    unsigned mb1 = s2u(&mbar_s[2]);

    if (tid < 128) {
        s_src[tid] = edge_index[e0 + tid];
        s_dst[tid] = edge_index[NE + e0 + tid];
    }
    if (tid == 0) {
        mbar_init(mbA, 1);
        mbar_init(mb0, 1);
        mbar_init(mb1, 1);
    }
    float c0 = init0[0] * 0.125f;
    float c1 = init0[1];
    __syncthreads();

    if (tid == 0) {
        mbar_expect(mbA, 32768);
        bulk_g2s(s2u(a_sm), g_eefh + (size_t)blockIdx.x * 2048, 32768, mbA);
        mbar_expect(mb0, 49152);
        bulk_g2s(s2u(b_sm), g_wf2h, 49152, mb0);
        mbar_expect(mb1, 49152);
        bulk_g2s(s2u(b_sm + 6144), g_wf2h + 6144, 49152, mb1);
    }

    int rd0[2], rd1[2], rs0[2], rs1[2];
#pragma unroll
    for (int mt = 0; mt < 2; mt++) {
        int el = mg * 32 + mt * 16 + gid;
        rd0[mt] = s_dst[el];
        rd1[mt] = s_dst[el + 8];
        rs0[mt] = s_src[el];
        rs1[mt] = s_src[el + 8];
    }

    const uint4* aw = a_sm + mg * 512 + lane;
    const uint2* bw = b_sm + (ng * 2) * 256 + lane;

    mbar_wait(mbA, 0);
    int ph0 = 0, ph1 = 0;

#pragma unroll 1
    for (int chunk = 0; chunk < 8; chunk++) {
        float acc[3][2][2][4];
#pragma unroll
        for (int m = 0; m < 3; m++)
#pragma unroll
            for (int mt = 0; mt < 2; mt++)
#pragma unroll
                for (int nt = 0; nt < 2; nt++)
#pragma unroll
                    for (int c = 0; c < 4; c++) acc[m][mt][nt][c] = 0.f;

        int colbase = chunk * 64 + ng * 16 + tg * 4;
        int bufbase = (chunk & 1) * 6144;
        int pb = chunk & 1;

        float4 qv[2][2], kv[2][2];
#pragma unroll
        for (int mt = 0; mt < 2; mt++) {
            qv[mt][0] = *(const float4*)(g_qn + (size_t)rd0[mt] * H_ + colbase);
            qv[mt][1] = *(const float4*)(g_qn + (size_t)rd1[mt] * H_ + colbase);
            kv[mt][0] = *(const float4*)(g_kn + (size_t)rs0[mt] * H_ + colbase);
            kv[mt][1] = *(const float4*)(g_kn + (size_t)rs1[mt] * H_ + colbase);
        }

        if ((chunk & 1) == 0) { mbar_wait(mb0, ph0); ph0 ^= 1; }
        else                  { mbar_wait(mb1, ph1); ph1 ^= 1; }

#pragma unroll
        for (int kt = 0; kt < 4; kt++) {
            uint4 av0 = aw[kt * 32];
            uint4 av1 = aw[256 + kt * 32];
            uint2 bv[3][2];
#pragma unroll
            for (int m = 0; m < 3; m++)
#pragma unroll
                for (int nt = 0; nt < 2; nt++)
                    bv[m][nt] = bw[bufbase + (m * 8 + nt) * 256 + kt * 32];
#pragma unroll
            for (int m = 0; m < 3; m++)
#pragma unroll
                for (int nt = 0; nt < 2; nt++) {
                    mma16(acc[m][0][nt], av0, bv[m][nt]);
                    mma16(acc[m][1][nt], av1, bv[m][nt]);
                }
        }

        float4 vv[2][2];
#pragma unroll
        for (int mt = 0; mt < 2; mt++) {
            vv[mt][0] = *(const float4*)(g_vn + (size_t)rs0[mt] * H_ + colbase);
            vv[mt][1] = *(const float4*)(g_vn + (size_t)rs1[mt] * H_ + colbase);
        }

#pragma unroll
        for (int kt = 4; kt < 8; kt++) {
            uint4 av0 = aw[kt * 32];
            uint4 av1 = aw[256 + kt * 32];
            uint2 bv[3][2];
#pragma unroll
            for (int m = 0; m < 3; m++)
#pragma unroll
                for (int nt = 0; nt < 2; nt++)
                    bv[m][nt] = bw[bufbase + (m * 8 + nt) * 256 + kt * 32];
#pragma unroll
            for (int m = 0; m < 3; m++)
#pragma unroll
                for (int nt = 0; nt < 2; nt++) {
                    mma16(acc[m][0][nt], av0, bv[m][nt]);
                    mma16(acc[m][1][nt], av1, bv[m][nt]);
                }
        }

        float p[2][2];
#pragma unroll
        for (int mt = 0; mt < 2; mt++) {
            p[mt][0] = (qv[mt][0].x + acc[0][mt][0][0]) * (kv[mt][0].x + acc[1][mt][0][0])
                     + (qv[mt][0].y + acc[0][mt][0][1]) * (kv[mt][0].y + acc[1][mt][0][1])
                     + (qv[mt][0].z + acc[0][mt][1][0]) * (kv[mt][0].z + acc[1][mt][1][0])
                     + (qv[mt][0].w + acc[0][mt][1][1]) * (kv[mt][0].w + acc[1][mt][1][1]);
            p[mt][1] = (qv[mt][1].x + acc[0][mt][0][2]) * (kv[mt][1].x + acc[1][mt][0][2])
                     + (qv[mt][1].y + acc[0][mt][0][3]) * (kv[mt][1].y + acc[1][mt][0][3])
                     + (qv[mt][1].z + acc[0][mt][1][2]) * (kv[mt][1].z + acc[1][mt][1][2])
                     + (qv[mt][1].w + acc[0][mt][1][3]) * (kv[mt][1].w + acc[1][mt][1][3]);
        }
#pragma unroll
        for (int off = 1; off <= 2; off <<= 1) {
            p[0][0] += __shfl_xor_sync(0xffffffffu, p[0][0], off);
            p[0][1] += __shfl_xor_sync(0xffffffffu, p[0][1], off);
            p[1][0] += __shfl_xor_sync(0xffffffffu, p[1][0], off);
            p[1][1] += __shfl_xor_sync(0xffffffffu, p[1][1], off);
        }
        if (tg == 0) {
#pragma unroll
            for (int mt = 0; mt < 2; mt++) {
                int el = mg * 32 + mt * 16 + gid;
                p_buf[pb][ng][el] = p[mt][0];
                p_buf[pb][ng][el + 8] = p[mt][1];
            }
        }
        __syncthreads();   // pbuf write->read; also all warps done with B buf
        if (tid == 0 && chunk < 6) {
            if ((chunk & 1) == 0) { mbar_expect(mb0, 49152); bulk_g2s(s2u(b_sm), g_wf2h + (size_t)(chunk + 2) * 6144, 49152, mb0); }
            else                  { mbar_expect(mb1, 49152); bulk_g2s(s2u(b_sm + 6144), g_wf2h + (size_t)(chunk + 2) * 6144, 49152, mb1); }
        }

#pragma unroll
        for (int mt = 0; mt < 2; mt++) {
            int el = mg * 32 + mt * 16 + gid;
            float sum0 = p_buf[pb][0][el] + p_buf[pb][1][el] + p_buf[pb][2][el] + p_buf[pb][3][el];
            float sum1 = p_buf[pb][0][el + 8] + p_buf[pb][1][el + 8] + p_buf[pb][2][el + 8] + p_buf[pb][3][el + 8];
            float att0 = expf(sum0 * c0 + c1);
            float att1 = expf(sum1 * c0 + c1);
            red4(g_agg + (size_t)rd0[mt] * H_ + colbase,
                 gelu_erf(vv[mt][0].x + acc[2][mt][0][0]) * att0,
                 gelu_erf(vv[mt][0].y + acc[2][mt][0][1]) * att0,
                 gelu_erf(vv[mt][0].z + acc[2][mt][1][0]) * att0,
                 gelu_erf(vv[mt][0].w + acc[2][mt][1][1]) * att0);
            red4(g_agg + (size_t)rd1[mt] * H_ + colbase,
                 gelu_erf(vv[mt][1].x + acc[2][mt][0][2]) * att1,
                 gelu_erf(vv[mt][1].y + acc[2][mt][0][3]) * att1,
                 gelu_erf(vv[mt][1].z + acc[2][mt][1][2]) * att1,
                 gelu_erf(vv[mt][1].w + acc[2][mt][1][3]) * att1);
        }
    }
}

// ---------------------------------------------------------------------------
// fp16 post kernel: out = x + (m0+agg) @ W_post + b_post. float4 A-build.
// ---------------------------------------------------------------------------
__global__ void __launch_bounds__(256) k_post(const float* __restrict__ x,
                                              const float* __restrict__ bp,
                                              float* __restrict__ out) {
    extern __shared__ char dsm[];
    uint4* a_sm = (uint4*)dsm;               // 64KB
    uint2* b_sm = (uint2*)(dsm + 65536);     // 2 x 64KB
    __shared__ __align__(8) unsigned long long mbar_s[2];

    int tid = threadIdx.x;
    int lane = tid & 31, wid = tid >> 5;
    int mg = wid >> 2;
    int ng = wid & 3;
    int gid = lane >> 2, tg = lane & 3;
    int blk = blockIdx.x;

    unsigned mb0 = s2u(&mbar_s[0]);
    unsigned mb1 = s2u(&mbar_s[1]);
    if (tid == 0) {
        mbar_init(mb0, 1);
        mbar_init(mb1, 1);
    }
    __syncthreads();
    if (tid == 0) {
        mbar_expect(mb0, 65536);
        bulk_g2s(s2u(b_sm), g_wfph, 65536, mb0);
        mbar_expect(mb1, 65536);
        bulk_g2s(s2u(b_sm + 8192), g_wfph + 8192, 65536, mb1);
    }

    // build A fragments from m0 + agg (float4 coalesced)
    {
        unsigned* aword = (unsigned*)a_sm;
        for (int idx = tid; idx < 8192; idx += 256) {
            int rl = idx >> 7;            // local row 0..63
            int c4 = (idx & 127) << 2;    // col 0..508 step 4
            int row = blk * 64 + rl;
            float4 f = make_float4(0.f, 0.f, 0.f, 0.f);
            if (row < NN) {
                float4 m4 = *(const float4*)(g_m0 + (size_t)row * H_ + c4);
                float4 a4 = *(const float4*)(g_agg + (size_t)row * H_ + c4);
                f = make_float4(m4.x + a4.x, m4.y + a4.y, m4.z + a4.z, m4.w + a4.w);
            }
            int mt = rl >> 4;
            int er = rl & 15;
            int kt = c4 >> 4;
            int i = (er >> 3) | (((c4 >> 3) & 1) << 1);
            int tb = (er & 7) * 4 + ((c4 >> 1) & 3);
            int base = ((mt * 32 + kt) * 32 + tb) * 4 + i;
            aword[base] = packh(f.x, f.y);
            aword[base + 4] = packh(f.z, f.w);
        }
    }
    __syncthreads();

    const uint4* aw = a_sm + mg * 2048 + lane;
    const uint2* bw = b_sm + (ng * 2) * 1024 + lane;
    int ph0 = 0, ph1 = 0;

#pragma unroll 1
    for (int s = 0; s < 4; s++) {
        int buf = s & 1;
        if (buf == 0) { mbar_wait(mb0, ph0); ph0 ^= 1; }
        else          { mbar_wait(mb1, ph1); ph1 ^= 1; }

        float acc[2][2][4];
#pragma unroll
        for (int mt = 0; mt < 2; mt++)
#pragma unroll
            for (int nt = 0; nt < 2; nt++)
#pragma unroll
                for (int c = 0; c < 4; c++) acc[mt][nt][c] = 0.f;

#pragma unroll 4
        for (int kt = 0; kt < 32; kt++) {
            uint4 av0 = aw[kt * 32];
            uint4 av1 = aw[1024 + kt * 32];
            uint2 bv0 = bw[buf * 8192 + kt * 32];
            uint2 bv1 = bw[buf * 8192 + 1024 + kt * 32];
            mma16(acc[0][0], av0, bv0);
            mma16(acc[0][1], av0, bv1);
            mma16(acc[1][0], av1, bv0);
            mma16(acc[1][1], av1, bv1);
        }
        __syncthreads();
        if (tid == 0 && s + 2 < 4) {
            if (buf == 0) { mbar_expect(mb0, 65536); bulk_g2s(s2u(b_sm), g_wfph + (size_t)(s + 2) * 8192, 65536, mb0); }
            else          { mbar_expect(mb1, 65536); bulk_g2s(s2u(b_sm + 8192), g_wfph + (size_t)(s + 2) * 8192, 65536, mb1); }
        }

        int col = s * 64 + ng * 16 + tg * 4;
        float4 bb = *(const float4*)(bp + col);
#pragma unroll
        for (int mt = 0; mt < 2; mt++) {
            int r0 = blk * 64 + mg * 32 + mt * 16 + gid;
            int r1 = r0 + 8;
            if (r0 < NN) {
                float4 xx0 = *(const float4*)(x + (size_t)r0 * W_ + col);
                *(float4*)(out + (size_t)r0 * W_ + col) =
                    make_float4(xx0.x + acc[mt][0][0] + bb.x, xx0.y + acc[mt][0][1] + bb.y,
                                xx0.z + acc[mt][1][0] + bb.z, xx0.w + acc[mt][1][1] + bb.w);
            }
            if (r1 < NN) {
                float4 xx1 = *(const float4*)(x + (size_t)r1 * W_ + col);
                *(float4*)(out + (size_t)r1 * W_ + col) =
                    make_float4(xx1.x + acc[mt][0][2] + bb.x, xx1.y + acc[mt][0][3] + bb.y,
                                xx1.z + acc[mt][1][2] + bb.z, xx1.w + acc[mt][1][3] + bb.w);
            }
        }
    }
}

extern "C" void kernel_launch(void* const* d_in, const int* in_sizes, int n_in,
                              void* d_out, int out_size) {
    const float* x          = (const float*)d_in[0];
    const int*   edge_index = (const int*)d_in[1];
    const int*   edge_attr  = (const int*)d_in[2];
    const float* edge_embed = (const float*)d_in[3];
    const float* emb0       = (const float*)d_in[4];
    const float* emb1       = (const float*)d_in[5];
    const float* emb2       = (const float*)d_in[6];
    const float* emb3       = (const float*)d_in[7];
    const float* init0_e    = (const float*)d_in[8];
    const float* init0      = (const float*)d_in[9];
    const float* W_pre      = (const float*)d_in[10];
    const float* b_pre      = (const float*)d_in[11];
    const float* W_msg0     = (const float*)d_in[12];
    const float* b_msg0     = (const float*)d_in[13];
    const float* W_q        = (const float*)d_in[14];
    const float* b_q        = (const float*)d_in[15];
    const float* W_k        = (const float*)d_in[16];
    const float* b_k        = (const float*)d_in[17];
    const float* W_v        = (const float*)d_in[18];
    const float* b_v        = (const float*)d_in[19];
    const float* W_r0       = (const float*)d_in[20];
    const float* b_r0       = (const float*)d_in[21];
    const float* W_r1       = (const float*)d_in[22];
    const float* b_r1       = (const float*)d_in[23];
    const float* W_r2       = (const float*)d_in[24];
    const float* b_r2       = (const float*)d_in[25];
    const float* W_post     = (const float*)d_in[26];
    const float* b_post     = (const float*)d_in[27];
    float* out = (float*)d_out;

    cudaFuncSetAttribute(k_edge, cudaFuncAttributeMaxDynamicSharedMemorySize, 131072);
    cudaFuncSetAttribute(k_projz, cudaFuncAttributeMaxDynamicSharedMemorySize, 98304);
    cudaFuncSetAttribute(k_post, cudaFuncAttributeMaxDynamicSharedMemorySize, 196608);
    cudaFuncSetAttribute(k_preT, cudaFuncAttributeMaxDynamicSharedMemorySize, 163840);

    k_wfeef<<<1524 + NE / 32, 256>>>(x, W_pre,
                                     W_r0, W_r1, W_r2, W_q, W_k, W_v, W_msg0, W_post,
                                     edge_attr, edge_embed,
                                     emb0, emb1, emb2, emb3, init0_e, init0);
    k_preT<<<NP / 64, 256, 163840>>>(b_pre);
    k_projz<<<NP / 64, 256, 98304>>>(b_q, b_k, b_v, b_msg0, b_r0, b_r1, b_r2, init0);
    k_edge<<<NE / 128, 512, 131072>>>(edge_index, init0);
    k_post<<<NP / 64, 256, 196608>>>(x, b_post, out);
}

// round 11
// speedup vs baseline: 4.3770x; 1.0206x over previous
#include <cuda_runtime.h>
#include <cuda_fp16.h>
#include <math.h>

#define NN 10000
#define NP 10048   // padded nodes (157 * 64)
#define NE 160000
#define W_ 256
#define H_ 512
#define EW_ 128

// Scratch (static device memory — no allocation allowed)
__device__ float g_qn[NN * H_];
__device__ float g_kn[NN * H_];
__device__ float g_vn[NN * H_];
__device__ float g_m0[NN * H_];
__device__ float g_agg[NN * H_];
__device__ uint4 g_eefh[NE * 16];              // ee fp16 A-frags
__device__ uint2 g_wf2h[8 * 3 * 8 * 8 * 32];   // Wr0..2 fp16 B-frags (perm cols, scales folded)
__device__ uint2 g_wfnh[4 * 64 * 16 * 32];     // Wq/Wk/Wv/Wm fp16 B-frags (perm cols)
__device__ uint2 g_wfph[32 * 32 * 32];         // W_post fp16 B-frags (perm cols)
__device__ uint4 g_xxfh[(NP / 16) * 512];      // LN(pre(x)) fp16 A-frags
__device__ uint4 g_xf[(NP / 16) * 512];        // raw x fp16 A-frags
__device__ uint2 g_wfpre[32 * 16 * 32];        // W_pre fp16 B-frags (natural cols, 128KB)

// Fast branch-free erf-gelu (Abramowitz-Stegun 7.1.25, |err| <= 2.5e-5 abs)
__device__ __forceinline__ float gelu_fast(float h) {
    float s = h * 0.70710678118654752f;
    float a = fabsf(s);
    float t = __fdividef(1.0f, fmaf(0.47047f, a, 1.0f));
    float p = t * fmaf(t, fmaf(t, 0.7478556f, -0.0958798f), 0.3480242f);
    float e = __expf(-s * s);
    float erfa = fmaf(-p, e, 1.0f);
    float er = copysignf(erfa, s);
    return 0.5f * h * (1.0f + er);
}

__device__ __forceinline__ unsigned packh(float a, float b) {
    __half2 h = __floats2half2_rn(a, b);
    return *(unsigned*)&h;
}

__device__ __forceinline__ void mma16(float* d, const uint4& a, const uint2& b) {
    asm volatile(
        "mma.sync.aligned.m16n8k16.row.col.f32.f16.f16.f32 "
        "{%0,%1,%2,%3},{%4,%5,%6,%7},{%8,%9},{%0,%1,%2,%3};"
        : "+f"(d[0]), "+f"(d[1]), "+f"(d[2]), "+f"(d[3])
        : "r"(a.x), "r"(a.y), "r"(a.z), "r"(a.w), "r"(b.x), "r"(b.y));
}

__device__ __forceinline__ void red4(float* p, float a, float b, float c, float d) {
    asm volatile("red.global.add.v4.f32 [%0], {%1,%2,%3,%4};"
                 :: "l"(p), "f"(a), "f"(b), "f"(c), "f"(d) : "memory");
}

// ---- mbarrier + bulk-copy helpers ----
__device__ __forceinline__ unsigned s2u(const void* p) {
    return (unsigned)__cvta_generic_to_shared(p);
}
__device__ __forceinline__ void mbar_init(unsigned mbar, unsigned cnt) {
    asm volatile("mbarrier.init.shared.b64 [%0], %1;" :: "r"(mbar), "r"(cnt) : "memory");
}
__device__ __forceinline__ void mbar_expect(unsigned mbar, unsigned bytes) {
    asm volatile("mbarrier.arrive.expect_tx.shared.b64 _, [%0], %1;"
                 :: "r"(mbar), "r"(bytes) : "memory");
}
__device__ __forceinline__ void bulk_g2s(unsigned dst, const void* src, unsigned bytes,
                                         unsigned mbar) {
    asm volatile("cp.async.bulk.shared::cta.global.mbarrier::complete_tx::bytes "
                 "[%0], [%1], %2, [%3];"
                 :: "r"(dst), "l"(src), "r"(bytes), "r"(mbar) : "memory");
}
__device__ __forceinline__ void mbar_wait(unsigned mbar, int phase) {
    asm volatile(
        "{\n\t.reg .pred P;\n\t"
        "W_%=:\n\t"
        "mbarrier.try_wait.parity.acquire.cta.shared::cta.b64 P, [%0], %1, 0x989680;\n\t"
        "@P bra.uni D_%=;\n\t"
        "bra.uni W_%=;\n\t"
        "D_%=:\n\t}"
        :: "r"(mbar), "r"(phase) : "memory");
}

// permuted physical column within a 16-col group
__device__ __forceinline__ int permcol(int nt, int gid) {
    return (nt >> 1) * 16 + (gid >> 1) * 4 + (nt & 1) * 2 + (gid & 1);
}

// ---------------------------------------------------------------------------
// Merged pre-pass:
//  [0,628):        x -> fp16 A-frags (g_xf)
//  [628,692):      W_pre -> fp16 B-frags, natural cols (g_wfpre)
//  [692,884):      Wr0..2 -> fp16 B-frags (perm, scales folded)
//  [884,1396):     Wq/Wk/Wv/Wm -> fp16 B-frags (perm)
//  [1396,1524):    W_post -> fp16 B-frags (perm)
//  [1524,6524):    ee embedding mix -> fp16 A-frags
// ---------------------------------------------------------------------------
__global__ void __launch_bounds__(256) k_wfeef(const float* __restrict__ x,
                                               const float* __restrict__ Wpre,
                                               const float* __restrict__ W0,
                                               const float* __restrict__ W1,
                                               const float* __restrict__ W2,
                                               const float* __restrict__ Wq,
                                               const float* __restrict__ Wk,
                                               const float* __restrict__ Wv,
                                               const float* __restrict__ Wm,
                                               const float* __restrict__ Wpost,
                                               const int* __restrict__ edge_attr,
                                               const float* __restrict__ edge_embed,
                                               const float* __restrict__ emb0,
                                               const float* __restrict__ emb1,
                                               const float* __restrict__ emb2,
                                               const float* __restrict__ emb3,
                                               const float* __restrict__ init0_e,
                                               const float* __restrict__ init0) {
    __shared__ float sbuf[4096];   // 16KB
    __shared__ int s_attr[128];
    int tid = threadIdx.x;
    int b = blockIdx.x;

    if (b < 628) {
        // x tile -> A-frags
        int n0 = b * 16;
        for (int idx = tid; idx < 4096; idx += 256) {
            int row = idx >> 8;
            sbuf[idx] = (n0 + row < NN) ? x[n0 * W_ + idx] : 0.f;
        }
        __syncthreads();
        unsigned* out = (unsigned*)(g_xf + (size_t)b * 512);
        for (int idx = tid; idx < 2048; idx += 256) {
            int i = idx & 3;
            int t = (idx >> 2) & 31;
            int kt = idx >> 7;
            int er = (t >> 2) + ((i & 1) << 3);
            int kc = kt * 16 + (t & 3) * 2 + ((i >> 1) << 3);
            out[idx] = packh(sbuf[er * W_ + kc], sbuf[er * W_ + kc + 1]);
        }
        return;
    }
    b -= 628;
    if (b < 64) {
        // W_pre -> B-frags natural (g_wfpre), 16384 uint2 total
        int idx = b * 256 + tid;
        int nt = idx >> 9;          // 0..31
        int kt = (idx >> 5) & 15;
        int lane = idx & 31;
        int tg = lane & 3, gid = lane >> 2;
        int col = nt * 8 + gid;
        int k0 = kt * 16 + tg * 2;
        uint2 o;
        o.x = packh(Wpre[k0 * W_ + col], Wpre[(k0 + 1) * W_ + col]);
        o.y = packh(Wpre[(k0 + 8) * W_ + col], Wpre[(k0 + 9) * W_ + col]);
        g_wfpre[(nt * 16 + kt) * 32 + lane] = o;
        return;
    }
    b -= 64;
    if (b < 192) {
        int idx = b * 256 + tid;        // 0..49151
        int m = idx / 16384;
        int j = idx & 16383;
        int nt = j >> 8;
        int kt = (j >> 5) & 7;
        int lane = j & 31;
        int tg = lane & 3, gid = lane >> 2;
        const float* W = (m == 0) ? W0 : ((m == 1) ? W1 : W2);
        float sc = __expf((m == 2) ? init0[3] : init0[2]);
        int col = permcol(nt, gid);
        int k0 = kt * 16 + tg * 2;
        uint2 o;
        o.x = packh(W[k0 * H_ + col] * sc, W[(k0 + 1) * H_ + col] * sc);
        o.y = packh(W[(k0 + 8) * H_ + col] * sc, W[(k0 + 9) * H_ + col] * sc);
        int chunk = nt >> 3, nt8 = nt & 7;
        g_wf2h[((chunk * 3 + m) * 8 + nt8) * 256 + kt * 32 + lane] = o;
        return;
    }
    b -= 192;
    if (b < 512) {
        int idx = b * 256 + tid;  // 0..131071
        int m = idx >> 15;
        int j = idx & 32767;
        int nt = j >> 9;
        int kt = (j >> 5) & 15;
        int lane = j & 31;
        int tg = lane & 3, gid = lane >> 2;
        const float* W = (m == 0) ? Wq : ((m == 1) ? Wk : ((m == 2) ? Wv : Wm));
        int col = permcol(nt, gid);
        int k0 = kt * 16 + tg * 2;
        uint2 o;
        o.x = packh(W[k0 * H_ + col], W[(k0 + 1) * H_ + col]);
        o.y = packh(W[(k0 + 8) * H_ + col], W[(k0 + 9) * H_ + col]);
        int s = m * 8 + (nt >> 3);
        g_wfnh[((s * 8 + (nt & 7)) * 16 + kt) * 32 + lane] = o;
        return;
    }
    b -= 512;
    if (b < 128) {
        int idx = b * 256 + tid;  // 0..32767
        int nt = idx >> 10;
        int kt = (idx >> 5) & 31;
        int lane = idx & 31;
        int tg = lane & 3, gid = lane >> 2;
        int col = permcol(nt, gid);
        int k0 = kt * 16 + tg * 2;
        uint2 o;
        o.x = packh(Wpost[k0 * W_ + col], Wpost[(k0 + 1) * W_ + col]);
        o.y = packh(Wpost[(k0 + 8) * W_ + col], Wpost[(k0 + 9) * W_ + col]);
        int stage = nt >> 3;
        g_wfph[((stage * 8 + (nt & 7)) * 32 + kt) * 32 + lane] = o;
        return;
    }
    b -= 128;
    // ---- ee embedding mix -> A-frags ----
    float* ee_s = sbuf;
    int e0 = b * 32;
    if (tid < 128) s_attr[tid] = edge_attr[e0 * 4 + tid];
    float ew0 = __expf(init0_e[0]), ew1 = __expf(init0_e[1]);
    float ew2 = __expf(init0_e[2]), ew3 = __expf(init0_e[3]);
    float rs = rsqrtf(ew0 + ew1 + ew2 + ew3);
    ew0 *= rs; ew1 *= rs; ew2 *= rs; ew3 *= rs;
    __syncthreads();
    for (int idx = tid; idx < 32 * EW_; idx += 256) {
        int e = idx >> 7;
        int c = idx & (EW_ - 1);
        int a0 = s_attr[e * 4 + 0], a1 = s_attr[e * 4 + 1];
        int a2 = s_attr[e * 4 + 2], a3 = s_attr[e * 4 + 3];
        float v = emb0[a0 * EW_ + c] * ew0 + emb1[a1 * EW_ + c] * ew1 +
                  emb2[a2 * EW_ + c] * ew2 + emb3[a3 * EW_ + c] * ew3;
        ee_s[idx] = 0.5f * (v + edge_embed[(e0 + e) * EW_ + c]);
    }
    __syncthreads();
    unsigned* out = (unsigned*)(g_eefh + (size_t)b * 512);
    for (int idx = tid; idx < 2048; idx += 256) {
        int i = idx & 3;
        int t = (idx >> 2) & 31;
        int kt = (idx >> 7) & 7;
        int let = idx >> 10;
        int er = (t >> 2) + ((i & 1) << 3);
        int kc = kt * 16 + (t & 3) * 2 + ((i >> 1) << 3);
        out[idx] = packh(ee_s[(let * 16 + er) * EW_ + kc],
                         ee_s[(let * 16 + er) * EW_ + kc + 1]);
    }
}

// ---------------------------------------------------------------------------
// Tensorized pre: xx = LN(x@W_pre + b_pre), 64 nodes/block, fp16 mma,
// LN in smem, output packed to g_xxfh A-frags. B (W_pre, 128KB) resident.
// ---------------------------------------------------------------------------
__global__ void __launch_bounds__(256, 1) k_preT(const float* __restrict__ bpre) {
    extern __shared__ char dsm[];
    uint4* a_sm = (uint4*)dsm;               // [4mt][16kt][32lane] = 32KB
    uint2* b_sm = (uint2*)(dsm + 32768);     // 128KB (aliased by ys after mma)
    float* ys = (float*)(dsm + 32768);       // [64][256] = 64KB
    __shared__ float s_mean[64], s_rstd[64];
    __shared__ __align__(8) unsigned long long mbar_s[2];

    int tid = threadIdx.x;
    int lane = tid & 31, wid = tid >> 5;
    int mg = wid >> 2;        // 0..1
    int ng = wid & 3;         // 0..3 (64 cols each)
    int gid = lane >> 2, tg = lane & 3;
    int blk = blockIdx.x;

    unsigned mbA = s2u(&mbar_s[0]);
    unsigned mbB = s2u(&mbar_s[1]);
    if (tid == 0) {
        mbar_init(mbA, 1);
        mbar_init(mbB, 1);
    }
    __syncthreads();
    if (tid == 0) {
        mbar_expect(mbA, 32768);
        bulk_g2s(s2u(a_sm), g_xf + (size_t)blk * 2048, 32768, mbA);
        mbar_expect(mbB, 131072);
        bulk_g2s(s2u(b_sm), g_wfpre, 65536, mbB);
        bulk_g2s(s2u(b_sm + 8192), g_wfpre + 8192, 65536, mbB);
    }

    float acc[2][8][4];
#pragma unroll
    for (int mt = 0; mt < 2; mt++)
#pragma unroll
        for (int nt = 0; nt < 8; nt++)
#pragma unroll
            for (int c = 0; c < 4; c++) acc[mt][nt][c] = 0.f;

    const uint4* aw = a_sm + mg * 1024 + lane;
    const uint2* bw = b_sm + ng * 8 * 512 + lane;

    mbar_wait(mbA, 0);
    mbar_wait(mbB, 0);

#pragma unroll 4
    for (int kt = 0; kt < 16; kt++) {
        uint4 av0 = aw[kt * 32];
        uint4 av1 = aw[512 + kt * 32];
#pragma unroll
        for (int nt = 0; nt < 8; nt++) {
            uint2 bv = bw[nt * 512 + kt * 32];
            mma16(acc[0][nt], av0, bv);
            mma16(acc[1][nt], av1, bv);
        }
    }
    __syncthreads();  // done reading b_sm; safe to alias ys

    // write biased results to ys
#pragma unroll
    for (int mt = 0; mt < 2; mt++) {
        int r0 = (mg * 2 + mt) * 16 + gid;
        int r1 = r0 + 8;
#pragma unroll
        for (int nt = 0; nt < 8; nt++) {
            int c = ng * 64 + nt * 8 + tg * 2;
            float2 bb = *(const float2*)(bpre + c);
            ys[r0 * W_ + c] = acc[mt][nt][0] + bb.x;
            ys[r0 * W_ + c + 1] = acc[mt][nt][1] + bb.y;
            ys[r1 * W_ + c] = acc[mt][nt][2] + bb.x;
            ys[r1 * W_ + c + 1] = acc[mt][nt][3] + bb.y;
        }
    }
    __syncthreads();

    // LN stats: 8 warps x 8 rows
#pragma unroll
    for (int rr = 0; rr < 8; rr++) {
        int row = wid * 8 + rr;
        float s = 0.f;
#pragma unroll
        for (int m = 0; m < W_ / 32; m++) s += ys[row * W_ + lane + 32 * m];
#pragma unroll
        for (int off = 16; off > 0; off >>= 1) s += __shfl_xor_sync(0xffffffffu, s, off);
        float mean = s * (1.0f / W_);
        float v = 0.f;
#pragma unroll
        for (int m = 0; m < W_ / 32; m++) {
            float d = ys[row * W_ + lane + 32 * m] - mean;
            v += d * d;
        }
#pragma unroll
        for (int off = 16; off > 0; off >>= 1) v += __shfl_xor_sync(0xffffffffu, v, off);
        if (lane == 0) {
            s_mean[row] = mean;
            s_rstd[row] = rsqrtf(v * (1.0f / W_) + 1e-5f);
        }
    }
    __syncthreads();

    // pack normalized rows into A-frags (4 tiles of 16 nodes)
    unsigned* out = (unsigned*)(g_xxfh + (size_t)blk * 2048);
    for (int idx = tid; idx < 8192; idx += 256) {
        int w = idx & 2047;
        int tile = idx >> 11;
        int i = w & 3;
        int t = (w >> 2) & 31;
        int kt = w >> 7;
        int er = (t >> 2) + ((i & 1) << 3);
        int row = tile * 16 + er;
        int kc = kt * 16 + (t & 3) * 2 + ((i >> 1) << 3);
        float mean = s_mean[row], rstd = s_rstd[row];
        out[idx] = packh((ys[row * W_ + kc] - mean) * rstd,
                         (ys[row * W_ + kc + 1] - mean) * rstd);
    }
}

// ---------------------------------------------------------------------------
// fp16 node projections: 64 nodes/block, 32 passes, float4 epilogue stores.
// ---------------------------------------------------------------------------
__global__ void __launch_bounds__(256, 2) k_projz(const float* __restrict__ bq,
                                                  const float* __restrict__ bk,
                                                  const float* __restrict__ bv,
                                                  const float* __restrict__ bm,
                                                  const float* __restrict__ br0,
                                                  const float* __restrict__ br1,
                                                  const float* __restrict__ br2,
                                                  const float* __restrict__ init0) {
    extern __shared__ char dsm[];
    uint4* a_sm = (uint4*)dsm;               // 32KB
    uint2* b_sm = (uint2*)(dsm + 32768);     // 2 x 32KB
    __shared__ __align__(8) unsigned long long mbar_s[3];

    int tid = threadIdx.x;
    int lane = tid & 31, wid = tid >> 5;
    int mg = wid >> 2;
    int ng = wid & 3;
    int gid = lane >> 2, tg = lane & 3;
    int blk = blockIdx.x;

    unsigned mbA = s2u(&mbar_s[0]);
    unsigned mb0 = s2u(&mbar_s[1]);
    unsigned mb1 = s2u(&mbar_s[2]);
    if (tid == 0) {
        mbar_init(mbA, 1);
        mbar_init(mb0, 1);
        mbar_init(mb1, 1);
    }
    float s_e = __expf(init0[2]);
    float s_v = __expf(init0[3]);
    __syncthreads();

    if (tid == 0) {
        mbar_expect(mbA, 32768);
        bulk_g2s(s2u(a_sm), g_xxfh + (size_t)blk * 2048, 32768, mbA);
        mbar_expect(mb0, 32768);
        bulk_g2s(s2u(b_sm), g_wfnh, 32768, mb0);
        mbar_expect(mb1, 32768);
        bulk_g2s(s2u(b_sm + 4096), g_wfnh + 4096, 32768, mb1);
    }

    // zero g_agg slice while copies are in flight
    {
        int r0 = blk * 64;
        float4 z = make_float4(0.f, 0.f, 0.f, 0.f);
        for (int i = tid; i < 64 * (H_ / 4); i += 256) {
            int r = r0 + (i >> 7);
            if (r < NN) *(float4*)(g_agg + (size_t)r * H_ + ((i & 127) << 2)) = z;
        }
    }

    const uint4* aw = a_sm + mg * 1024 + lane;
    const uint2* bw = b_sm + (ng * 2) * 512 + lane;

    mbar_wait(mbA, 0);
    int ph0 = 0, ph1 = 0;

#pragma unroll 1
    for (int s = 0; s < 32; s++) {
        int buf = s & 1;
        if (buf == 0) { mbar_wait(mb0, ph0); ph0 ^= 1; }
        else          { mbar_wait(mb1, ph1); ph1 ^= 1; }

        float acc[2][2][4];
#pragma unroll
        for (int mt = 0; mt < 2; mt++)
#pragma unroll
            for (int nt = 0; nt < 2; nt++)
#pragma unroll
                for (int c = 0; c < 4; c++) acc[mt][nt][c] = 0.f;

#pragma unroll 4
        for (int kt = 0; kt < 16; kt++) {
            uint4 av0 = aw[kt * 32];
            uint4 av1 = aw[512 + kt * 32];
            uint2 bv0 = bw[buf * 4096 + kt * 32];
            uint2 bv1 = bw[buf * 4096 + 512 + kt * 32];
            mma16(acc[0][0], av0, bv0);
            mma16(acc[0][1], av0, bv1);
            mma16(acc[1][0], av1, bv0);
            mma16(acc[1][1], av1, bv1);
        }
        __syncthreads();
        if (tid == 0 && s + 2 < 32) {
            if (buf == 0) { mbar_expect(mb0, 32768); bulk_g2s(s2u(b_sm), g_wfnh + (size_t)(s + 2) * 4096, 32768, mb0); }
            else          { mbar_expect(mb1, 32768); bulk_g2s(s2u(b_sm + 4096), g_wfnh + (size_t)(s + 2) * 4096, 32768, mb1); }
        }

        int m = s >> 3, cc = s & 7;
        const float* bmain = (m == 0) ? bq : ((m == 1) ? bk : ((m == 2) ? bv : bm));
        const float* badd  = (m == 0) ? br0 : ((m == 1) ? br1 : br2);
        float scale = (m < 2) ? s_e : s_v;
        float* dst = (m == 0) ? g_qn : ((m == 1) ? g_kn : ((m == 2) ? g_vn : g_m0));
        int col = cc * 64 + ng * 16 + tg * 4;
        float4 bb = *(const float4*)(bmain + col);
        if (m < 3) {
            float4 b2 = *(const float4*)(badd + col);
            bb = make_float4(bb.x + b2.x * scale, bb.y + b2.y * scale,
                             bb.z + b2.z * scale, bb.w + b2.w * scale);
        }
#pragma unroll
        for (int mt = 0; mt < 2; mt++) {
            int r0 = blk * 64 + mg * 32 + mt * 16 + gid;
            int r1 = r0 + 8;
            float4 o0 = make_float4(acc[mt][0][0] + bb.x, acc[mt][0][1] + bb.y,
                                    acc[mt][1][0] + bb.z, acc[mt][1][1] + bb.w);
            float4 o1 = make_float4(acc[mt][0][2] + bb.x, acc[mt][0][3] + bb.y,
                                    acc[mt][1][2] + bb.z, acc[mt][1][3] + bb.w);
            if (m == 3) {
                o0 = make_float4(gelu_fast(o0.x), gelu_fast(o0.y), gelu_fast(o0.z), gelu_fast(o0.w));
                o1 = make_float4(gelu_fast(o1.x), gelu_fast(o1.y), gelu_fast(o1.z), gelu_fast(o1.w));
            }
            if (r0 < NN) *(float4*)(dst + (size_t)r0 * H_ + col) = o0;
            if (r1 < NN) *(float4*)(dst + (size_t)r1 * H_ + col) = o1;
        }
    }
}

// ---------------------------------------------------------------------------
// fp16 edge kernel: 128 edges/block, 512 threads (4 mg x 4 ng).
// One __syncthreads per chunk (p_buf double-buffered over chunks).
// Epilogue uses fast erf-gelu + __expf.
// ---------------------------------------------------------------------------
__global__ void __launch_bounds__(512) k_edge(const int* __restrict__ edge_index,
                                              const float* __restrict__ init0) {
    extern __shared__ char dsm[];
    uint4* a_sm = (uint4*)dsm;               // 32KB
    uint2* b_sm = (uint2*)(dsm + 32768);     // 2 x 48KB
    __shared__ int s_src[128], s_dst[128];
    __shared__ float p_buf[2][4][128];
    __shared__ __align__(8) unsigned long long mbar_s[3];

    int tid = threadIdx.x;
    int lane = tid & 31, wid = tid >> 5;
    int mg = wid >> 2;
    int ng = wid & 3;
    int gid = lane >> 2, tg = lane & 3;
    int e0 = blockIdx.x * 128;

    unsigned mbA = s2u(&mbar_s[0]);
    unsigned mb0 = s2u(&mbar_s[1]);
    unsigned mb1 = s2u(&mbar_s[2]);

    if (tid < 128) {
        s_src[tid] = edge_index[e0 + tid];
        s_dst[tid] = edge_index[NE + e0 + tid];
    }
    if (tid == 0) {
        mbar_init(mbA, 1);
        mbar_init(mb0, 1);
        mbar_init(mb1, 1);
    }
    float c0 = init0[0] * 0.125f;
    float c1 = init0[1];
    __syncthreads();

    if (tid == 0) {
        mbar_expect(mbA, 32768);
        bulk_g2s(s2u(a_sm), g_eefh + (size_t)blockIdx.x * 2048, 32768, mbA);
        mbar_expect(mb0, 49152);
        bulk_g2s(s2u(b_sm), g_wf2h, 49152, mb0);
        mbar_expect(mb1, 49152);
        bulk_g2s(s2u(b_sm + 6144), g_wf2h + 6144, 49152, mb1);
    }

    int rd0[2], rd1[2], rs0[2], rs1[2];
#pragma unroll
    for (int mt = 0; mt < 2; mt++) {
        int el = mg * 32 + mt * 16 + gid;
        rd0[mt] = s_dst[el];
        rd1[mt] = s_dst[el + 8];
        rs0[mt] = s_src[el];
        rs1[mt] = s_src[el + 8];
    }

    const uint4* aw = a_sm + mg * 512 + lane;
    const uint2* bw = b_sm + (ng * 2) * 256 + lane;

    mbar_wait(mbA, 0);
    int ph0 = 0, ph1 = 0;

#pragma unroll 1
    for (int chunk = 0; chunk < 8; chunk++) {
        float acc[3][2][2][4];
#pragma unroll
        for (int m = 0; m < 3; m++)
#pragma unroll
            for (int mt = 0; mt < 2; mt++)
#pragma unroll
                for (int nt = 0; nt < 2; nt++)
#pragma unroll
                    for (int c = 0; c < 4; c++) acc[m][mt][nt][c] = 0.f;

        int colbase = chunk * 64 + ng * 16 + tg * 4;
        int bufbase = (chunk & 1) * 6144;
        int pb = chunk & 1;

        float4 qv[2][2], kv[2][2];
#pragma unroll
        for (int mt = 0; mt < 2; mt++) {
            qv[mt][0] = *(const float4*)(g_qn + (size_t)rd0[mt] * H_ + colbase);
            qv[mt][1] = *(const float4*)(g_qn + (size_t)rd1[mt] * H_ + colbase);
            kv[mt][0] = *(const float4*)(g_kn + (size_t)rs0[mt] * H_ + colbase);
            kv[mt][1] = *(const float4*)(g_kn + (size_t)rs1[mt] * H_ + colbase);
        }

        if ((chunk & 1) == 0) { mbar_wait(mb0, ph0); ph0 ^= 1; }
        else                  { mbar_wait(mb1, ph1); ph1 ^= 1; }

#pragma unroll
        for (int kt = 0; kt < 4; kt++) {
            uint4 av0 = aw[kt * 32];
            uint4 av1 = aw[256 + kt * 32];
            uint2 bv[3][2];
#pragma unroll
            for (int m = 0; m < 3; m++)
#pragma unroll
                for (int nt = 0; nt < 2; nt++)
                    bv[m][nt] = bw[bufbase + (m * 8 + nt) * 256 + kt * 32];
#pragma unroll
            for (int m = 0; m < 3; m++)
#pragma unroll
                for (int nt = 0; nt < 2; nt++) {
                    mma16(acc[m][0][nt], av0, bv[m][nt]);
                    mma16(acc[m][1][nt], av1, bv[m][nt]);
                }
        }

        float4 vv[2][2];
#pragma unroll
        for (int mt = 0; mt < 2; mt++) {
            vv[mt][0] = *(const float4*)(g_vn + (size_t)rs0[mt] * H_ + colbase);
            vv[mt][1] = *(const float4*)(g_vn + (size_t)rs1[mt] * H_ + colbase);
        }

#pragma unroll
        for (int kt = 4; kt < 8; kt++) {
            uint4 av0 = aw[kt * 32];
            uint4 av1 = aw[256 + kt * 32];
            uint2 bv[3][2];
#pragma unroll
            for (int m = 0; m < 3; m++)
#pragma unroll
                for (int nt = 0; nt < 2; nt++)
                    bv[m][nt] = bw[bufbase + (m * 8 + nt) * 256 + kt * 32];
#pragma unroll
            for (int m = 0; m < 3; m++)
#pragma unroll
                for (int nt = 0; nt < 2; nt++) {
                    mma16(acc[m][0][nt], av0, bv[m][nt]);
                    mma16(acc[m][1][nt], av1, bv[m][nt]);
                }
        }

        float p[2][2];
#pragma unroll
        for (int mt = 0; mt < 2; mt++) {
            p[mt][0] = (qv[mt][0].x + acc[0][mt][0][0]) * (kv[mt][0].x + acc[1][mt][0][0])
                     + (qv[mt][0].y + acc[0][mt][0][1]) * (kv[mt][0].y + acc[1][mt][0][1])
                     + (qv[mt][0].z + acc[0][mt][1][0]) * (kv[mt][0].z + acc[1][mt][1][0])
                     + (qv[mt][0].w + acc[0][mt][1][1]) * (kv[mt][0].w + acc[1][mt][1][1]);
            p[mt][1] = (qv[mt][1].x + acc[0][mt][0][2]) * (kv[mt][1].x + acc[1][mt][0][2])
                     + (qv[mt][1].y + acc[0][mt][0][3]) * (kv[mt][1].y + acc[1][mt][0][3])
                     + (qv[mt][1].z + acc[0][mt][1][2]) * (kv[mt][1].z + acc[1][mt][1][2])
                     + (qv[mt][1].w + acc[0][mt][1][3]) * (kv[mt][1].w + acc[1][mt][1][3]);
        }
#pragma unroll
        for (int off = 1; off <= 2; off <<= 1) {
            p[0][0] += __shfl_xor_sync(0xffffffffu, p[0][0], off);
            p[0][1] += __shfl_xor_sync(0xffffffffu, p[0][1], off);
            p[1][0] += __shfl_xor_sync(0xffffffffu, p[1][0], off);
            p[1][1] += __shfl_xor_sync(0xffffffffu, p[1][1], off);
        }
        if (tg == 0) {
#pragma unroll
            for (int mt = 0; mt < 2; mt++) {
                int el = mg * 32 + mt * 16 + gid;
                p_buf[pb][ng][el] = p[mt][0];
                p_buf[pb][ng][el + 8] = p[mt][1];
            }
        }
        __syncthreads();   // pbuf write->read; also all warps done with B buf
        if (tid == 0 && chunk < 6) {
            if ((chunk & 1) == 0) { mbar_expect(mb0, 49152); bulk_g2s(s2u(b_sm), g_wf2h + (size_t)(chunk + 2) * 6144, 49152, mb0); }
            else                  { mbar_expect(mb1, 49152); bulk_g2s(s2u(b_sm + 6144), g_wf2h + (size_t)(chunk + 2) * 6144, 49152, mb1); }
        }

#pragma unroll
        for (int mt = 0; mt < 2; mt++) {
            int el = mg * 32 + mt * 16 + gid;
            float sum0 = p_buf[pb][0][el] + p_buf[pb][1][el] + p_buf[pb][2][el] + p_buf[pb][3][el];
            float sum1 = p_buf[pb][0][el + 8] + p_buf[pb][1][el + 8] + p_buf[pb][2][el + 8] + p_buf[pb][3][el + 8];
            float att0 = __expf(sum0 * c0 + c1);
            float att1 = __expf(sum1 * c0 + c1);
            red4(g_agg + (size_t)rd0[mt] * H_ + colbase,
                 gelu_fast(vv[mt][0].x + acc[2][mt][0][0]) * att0,
                 gelu_fast(vv[mt][0].y + acc[2][mt][0][1]) * att0,
                 gelu_fast(vv[mt][0].z + acc[2][mt][1][0]) * att0,
                 gelu_fast(vv[mt][0].w + acc[2][mt][1][1]) * att0);
            red4(g_agg + (size_t)rd1[mt] * H_ + colbase,
                 gelu_fast(vv[mt][1].x + acc[2][mt][0][2]) * att1,
                 gelu_fast(vv[mt][1].y + acc[2][mt][0][3]) * att1,
                 gelu_fast(vv[mt][1].z + acc[2][mt][1][2]) * att1,
                 gelu_fast(vv[mt][1].w + acc[2][mt][1][3]) * att1);
        }
    }
}

// ---------------------------------------------------------------------------
// fp16 post kernel: out = x + (m0+agg) @ W_post + b_post. float4 A-build.
// ---------------------------------------------------------------------------
__global__ void __launch_bounds__(256) k_post(const float* __restrict__ x,
                                              const float* __restrict__ bp,
                                              float* __restrict__ out) {
    extern __shared__ char dsm[];
    uint4* a_sm = (uint4*)dsm;               // 64KB
    uint2* b_sm = (uint2*)(dsm + 65536);     // 2 x 64KB
    __shared__ __align__(8) unsigned long long mbar_s[2];

    int tid = threadIdx.x;
    int lane = tid & 31, wid = tid >> 5;
    int mg = wid >> 2;
    int ng = wid & 3;
    int gid = lane >> 2, tg = lane & 3;
    int blk = blockIdx.x;

    unsigned mb0 = s2u(&mbar_s[0]);
    unsigned mb1 = s2u(&mbar_s[1]);
    if (tid == 0) {
        mbar_init(mb0, 1);
        mbar_init(mb1, 1);
    }
    __syncthreads();
    if (tid == 0) {
        mbar_expect(mb0, 65536);
        bulk_g2s(s2u(b_sm), g_wfph, 65536, mb0);
        mbar_expect(mb1, 65536);
        bulk_g2s(s2u(b_sm + 8192), g_wfph + 8192, 65536, mb1);
    }

    // build A fragments from m0 + agg (float4 coalesced)
    {
        unsigned* aword = (unsigned*)a_sm;
        for (int idx = tid; idx < 8192; idx += 256) {
            int rl = idx >> 7;            // local row 0..63
            int c4 = (idx & 127) << 2;    // col 0..508 step 4
            int row = blk * 64 + rl;
            float4 f = make_float4(0.f, 0.f, 0.f, 0.f);
            if (row < NN) {
                float4 m4 = *(const float4*)(g_m0 + (size_t)row * H_ + c4);
                float4 a4 = *(const float4*)(g_agg + (size_t)row * H_ + c4);
                f = make_float4(m4.x + a4.x, m4.y + a4.y, m4.z + a4.z, m4.w + a4.w);
            }
            int mt = rl >> 4;
            int er = rl & 15;
            int kt = c4 >> 4;
            int i = (er >> 3) | (((c4 >> 3) & 1) << 1);
            int tb = (er & 7) * 4 + ((c4 >> 1) & 3);
            int base = ((mt * 32 + kt) * 32 + tb) * 4 + i;
            aword[base] = packh(f.x, f.y);
            aword[base + 4] = packh(f.z, f.w);
        }
    }
    __syncthreads();

    const uint4* aw = a_sm + mg * 2048 + lane;
    const uint2* bw = b_sm + (ng * 2) * 1024 + lane;
    int ph0 = 0, ph1 = 0;

#pragma unroll 1
    for (int s = 0; s < 4; s++) {
        int buf = s & 1;
        if (buf == 0) { mbar_wait(mb0, ph0); ph0 ^= 1; }
        else          { mbar_wait(mb1, ph1); ph1 ^= 1; }

        float acc[2][2][4];
#pragma unroll
        for (int mt = 0; mt < 2; mt++)
#pragma unroll
            for (int nt = 0; nt < 2; nt++)
#pragma unroll
                for (int c = 0; c < 4; c++) acc[mt][nt][c] = 0.f;

#pragma unroll 4
        for (int kt = 0; kt < 32; kt++) {
            uint4 av0 = aw[kt * 32];
            uint4 av1 = aw[1024 + kt * 32];
            uint2 bv0 = bw[buf * 8192 + kt * 32];
            uint2 bv1 = bw[buf * 8192 + 1024 + kt * 32];
            mma16(acc[0][0], av0, bv0);
            mma16(acc[0][1], av0, bv1);
            mma16(acc[1][0], av1, bv0);
            mma16(acc[1][1], av1, bv1);
        }
        __syncthreads();
        if (tid == 0 && s + 2 < 4) {
            if (buf == 0) { mbar_expect(mb0, 65536); bulk_g2s(s2u(b_sm), g_wfph + (size_t)(s + 2) * 8192, 65536, mb0); }
            else          { mbar_expect(mb1, 65536); bulk_g2s(s2u(b_sm + 8192), g_wfph + (size_t)(s + 2) * 8192, 65536, mb1); }
        }

        int col = s * 64 + ng * 16 + tg * 4;
        float4 bb = *(const float4*)(bp + col);
#pragma unroll
        for (int mt = 0; mt < 2; mt++) {
            int r0 = blk * 64 + mg * 32 + mt * 16 + gid;
            int r1 = r0 + 8;
            if (r0 < NN) {
                float4 xx0 = *(const float4*)(x + (size_t)r0 * W_ + col);
                *(float4*)(out + (size_t)r0 * W_ + col) =
                    make_float4(xx0.x + acc[mt][0][0] + bb.x, xx0.y + acc[mt][0][1] + bb.y,
                                xx0.z + acc[mt][1][0] + bb.z, xx0.w + acc[mt][1][1] + bb.w);
            }
            if (r1 < NN) {
                float4 xx1 = *(const float4*)(x + (size_t)r1 * W_ + col);
                *(float4*)(out + (size_t)r1 * W_ + col) =
                    make_float4(xx1.x + acc[mt][0][2] + bb.x, xx1.y + acc[mt][0][3] + bb.y,
                                xx1.z + acc[mt][1][2] + bb.z, xx1.w + acc[mt][1][3] + bb.w);
            }
        }
    }
}

extern "C" void kernel_launch(void* const* d_in, const int* in_sizes, int n_in,
                              void* d_out, int out_size) {
    const float* x          = (const float*)d_in[0];
    const int*   edge_index = (const int*)d_in[1];
    const int*   edge_attr  = (const int*)d_in[2];
    const float* edge_embed = (const float*)d_in[3];
    const float* emb0       = (const float*)d_in[4];
    const float* emb1       = (const float*)d_in[5];
    const float* emb2       = (const float*)d_in[6];
    const float* emb3       = (const float*)d_in[7];
    const float* init0_e    = (const float*)d_in[8];
    const float* init0      = (const float*)d_in[9];
    const float* W_pre      = (const float*)d_in[10];
    const float* b_pre      = (const float*)d_in[11];
    const float* W_msg0     = (const float*)d_in[12];
    const float* b_msg0     = (const float*)d_in[13];
    const float* W_q        = (const float*)d_in[14];
    const float* b_q        = (const float*)d_in[15];
    const float* W_k        = (const float*)d_in[16];
    const float* b_k        = (const float*)d_in[17];
    const float* W_v        = (const float*)d_in[18];
    const float* b_v        = (const float*)d_in[19];
    const float* W_r0       = (const float*)d_in[20];
    const float* b_r0       = (const float*)d_in[21];
    const float* W_r1       = (const float*)d_in[22];
    const float* b_r1       = (const float*)d_in[23];
    const float* W_r2       = (const float*)d_in[24];
    const float* b_r2       = (const float*)d_in[25];
    const float* W_post     = (const float*)d_in[26];
    const float* b_post     = (const float*)d_in[27];
    float* out = (float*)d_out;

    cudaFuncSetAttribute(k_edge, cudaFuncAttributeMaxDynamicSharedMemorySize, 131072);
    cudaFuncSetAttribute(k_projz, cudaFuncAttributeMaxDynamicSharedMemorySize, 98304);
    cudaFuncSetAttribute(k_post, cudaFuncAttributeMaxDynamicSharedMemorySize, 196608);
    cudaFuncSetAttribute(k_preT, cudaFuncAttributeMaxDynamicSharedMemorySize, 163840);

    k_wfeef<<<1524 + NE / 32, 256>>>(x, W_pre,
                                     W_r0, W_r1, W_r2, W_q, W_k, W_v, W_msg0, W_post,
                                     edge_attr, edge_embed,
                                     emb0, emb1, emb2, emb3, init0_e, init0);
    k_preT<<<NP / 64, 256, 163840>>>(b_pre);
    k_projz<<<NP / 64, 256, 98304>>>(b_q, b_k, b_v, b_msg0, b_r0, b_r1, b_r2, init0);
    k_edge<<<NE / 128, 512, 131072>>>(edge_index, init0);
    k_post<<<NP / 64, 256, 196608>>>(x, b_post, out);
}